// round 2
// baseline (speedup 1.0000x reference)
#include <cuda_runtime.h>
#include <cstdint>

#define S_LEN   2048
#define D_MODEL 1024
#define N_HEADS 16
#define D_HEAD  64
#define D_FF    4096

// ---------------- scratch (no allocation allowed) ----------------
__device__ float g_Q[N_HEADS * S_LEN * D_HEAD];
__device__ float g_K[N_HEADS * S_LEN * D_HEAD];
__device__ float g_V[N_HEADS * S_LEN * D_HEAD];
__device__ float g_Z[S_LEN * D_MODEL];
__device__ float g_ATT[S_LEN * D_MODEL];
__device__ float g_HID[S_LEN * D_FF];
__device__ float g_DUMMY[S_LEN * D_MODEL];

// =================================================================
// Generic 128x128 tiled SGEMM, BK=16, 256 threads, 8x8 microtile.
// BMODE 0: B is per-head [H][K][64], column n -> (h=n/64, e=n%64)  (QKV)
// BMODE 1: B is [N][K] row-major (C = A @ B^T)                      (WO/FF)
// OUTHEAD: write C[n/64][m][n%64] (per-head layout) instead of C[m][n]
// =================================================================
template<int BMODE, bool BIAS, bool RELU, bool RESID, bool OUTHEAD>
__global__ __launch_bounds__(256) void gemm_kernel(
    const float* __restrict__ A, const float* __restrict__ B,
    const float* __restrict__ bias, const float* __restrict__ resid,
    float* __restrict__ C, int M, int N, int K)
{
    __shared__ float As[16 * 132];
    __shared__ float Bs[16 * 132];

    const int t  = threadIdx.x;
    const int ty = t >> 4;
    const int tx = t & 15;
    const int m0 = blockIdx.y * 128;
    const int n0 = blockIdx.x * 128;

    float acc[8][8];
#pragma unroll
    for (int i = 0; i < 8; i++)
#pragma unroll
        for (int j = 0; j < 8; j++) acc[i][j] = 0.0f;

    const int amm = t >> 1;
    const int akq = (t & 1) * 8;

    for (int k0 = 0; k0 < K; k0 += 16) {
        // ---- load A tile (transposed into As[kk][m]) ----
        {
            const float* ap = A + (size_t)(m0 + amm) * K + k0 + akq;
            float4 v0 = *(const float4*)ap;
            float4 v1 = *(const float4*)(ap + 4);
            As[(akq + 0) * 132 + amm] = v0.x;
            As[(akq + 1) * 132 + amm] = v0.y;
            As[(akq + 2) * 132 + amm] = v0.z;
            As[(akq + 3) * 132 + amm] = v0.w;
            As[(akq + 4) * 132 + amm] = v1.x;
            As[(akq + 5) * 132 + amm] = v1.y;
            As[(akq + 6) * 132 + amm] = v1.z;
            As[(akq + 7) * 132 + amm] = v1.w;
        }
        // ---- load B tile into Bs[kk][n] ----
        if (BMODE == 1) {
            const int bn  = t >> 1;
            const int bkq = (t & 1) * 8;
            const float* bp = B + (size_t)(n0 + bn) * K + k0 + bkq;
            float4 v0 = *(const float4*)bp;
            float4 v1 = *(const float4*)(bp + 4);
            Bs[(bkq + 0) * 132 + bn] = v0.x;
            Bs[(bkq + 1) * 132 + bn] = v0.y;
            Bs[(bkq + 2) * 132 + bn] = v0.z;
            Bs[(bkq + 3) * 132 + bn] = v0.w;
            Bs[(bkq + 4) * 132 + bn] = v1.x;
            Bs[(bkq + 5) * 132 + bn] = v1.y;
            Bs[(bkq + 6) * 132 + bn] = v1.z;
            Bs[(bkq + 7) * 132 + bn] = v1.w;
        } else {
            const int kk = t >> 4;          // 0..15
            const int nn = (t & 15) * 8;    // 0..120
            const int ng = n0 + nn;
            const int h  = ng >> 6;
            const int e  = ng & 63;
            const float* bp = B + ((size_t)h * K + (k0 + kk)) * 64 + e;
            float4 v0 = *(const float4*)bp;
            float4 v1 = *(const float4*)(bp + 4);
            *(float4*)&Bs[kk * 132 + nn]     = v0;
            *(float4*)&Bs[kk * 132 + nn + 4] = v1;
        }
        __syncthreads();

#pragma unroll
        for (int kk = 0; kk < 16; kk++) {
            float4 a0 = *(const float4*)&As[kk * 132 + ty * 8];
            float4 a1 = *(const float4*)&As[kk * 132 + ty * 8 + 4];
            float4 b0 = *(const float4*)&Bs[kk * 132 + tx * 8];
            float4 b1 = *(const float4*)&Bs[kk * 132 + tx * 8 + 4];
            float a[8] = {a0.x, a0.y, a0.z, a0.w, a1.x, a1.y, a1.z, a1.w};
            float b[8] = {b0.x, b0.y, b0.z, b0.w, b1.x, b1.y, b1.z, b1.w};
#pragma unroll
            for (int i = 0; i < 8; i++)
#pragma unroll
                for (int j = 0; j < 8; j++)
                    acc[i][j] = fmaf(a[i], b[j], acc[i][j]);
        }
        __syncthreads();
    }

    // ---- epilogue ----
    float4 bi0 = make_float4(0.f, 0.f, 0.f, 0.f);
    float4 bi1 = make_float4(0.f, 0.f, 0.f, 0.f);
    if (BIAS) {
        bi0 = *(const float4*)&bias[n0 + tx * 8];
        bi1 = *(const float4*)&bias[n0 + tx * 8 + 4];
    }
#pragma unroll
    for (int i = 0; i < 8; i++) {
        const int m = m0 + ty * 8 + i;
        float4 v0 = make_float4(acc[i][0], acc[i][1], acc[i][2], acc[i][3]);
        float4 v1 = make_float4(acc[i][4], acc[i][5], acc[i][6], acc[i][7]);
        if (BIAS) {
            v0.x += bi0.x; v0.y += bi0.y; v0.z += bi0.z; v0.w += bi0.w;
            v1.x += bi1.x; v1.y += bi1.y; v1.z += bi1.z; v1.w += bi1.w;
        }
        if (RELU) {
            v0.x = fmaxf(v0.x, 0.f); v0.y = fmaxf(v0.y, 0.f);
            v0.z = fmaxf(v0.z, 0.f); v0.w = fmaxf(v0.w, 0.f);
            v1.x = fmaxf(v1.x, 0.f); v1.y = fmaxf(v1.y, 0.f);
            v1.z = fmaxf(v1.z, 0.f); v1.w = fmaxf(v1.w, 0.f);
        }
        if (RESID) {
            float4 r0 = *(const float4*)&resid[(size_t)m * N + n0 + tx * 8];
            float4 r1 = *(const float4*)&resid[(size_t)m * N + n0 + tx * 8 + 4];
            v0.x += r0.x; v0.y += r0.y; v0.z += r0.z; v0.w += r0.w;
            v1.x += r1.x; v1.y += r1.y; v1.z += r1.z; v1.w += r1.w;
        }
        if (OUTHEAD) {
            const int n = n0 + tx * 8;
            const int h = n >> 6;
            const int e = n & 63;
            *(float4*)&C[((size_t)h * M + m) * 64 + e]     = v0;
            *(float4*)&C[((size_t)h * M + m) * 64 + e + 4] = v1;
        } else {
            *(float4*)&C[(size_t)m * N + n0 + tx * 8]     = v0;
            *(float4*)&C[(size_t)m * N + n0 + tx * 8 + 4] = v1;
        }
    }
}

// =================================================================
// Attention: one block = (head, 64-query tile). 256 threads, 4x4 microtiles.
// Pass 1: exact online (m, l) over causal row.  Pass 2: write normalized SA
// and accumulate z = SA @ V.  Upper-triangle tiles of SA explicitly zeroed.
// =================================================================
__device__ __forceinline__ float rmax16(float v) {
#pragma unroll
    for (int o = 8; o > 0; o >>= 1) v = fmaxf(v, __shfl_xor_sync(0xffffffffu, v, o));
    return v;
}
__device__ __forceinline__ float rsum16(float v) {
#pragma unroll
    for (int o = 8; o > 0; o >>= 1) v += __shfl_xor_sync(0xffffffffu, v, o);
    return v;
}

#define SMP 68  // padded row stride (floats); 68*4 bytes keeps float4 alignment

__global__ __launch_bounds__(256) void attn_kernel(
    const float* __restrict__ Q, const float* __restrict__ K,
    const float* __restrict__ V, float* __restrict__ SA, float* __restrict__ Z)
{
    extern __shared__ float sm[];
    float* Qs  = sm;                // [64][SMP]  Qs[d][r]  (d-major)
    float* KVs = sm + 64 * SMP;     // [64][SMP]  K: [d][c], V: [c][v]
    float* Ps  = sm + 2 * 64 * SMP; // [64][SMP]  Ps[c][r]

    const int t  = threadIdx.x;
    const int ty = t >> 4;
    const int tx = t & 15;
    const int qt = blockIdx.x;      // query tile (0..31)
    const int h  = blockIdx.y;
    const int q0 = qt * 64;

    const float slope = exp2f(-0.5f * (float)(h + 1));
    const float* Qh = Q + (size_t)h * S_LEN * D_HEAD;
    const float* Kh = K + (size_t)h * S_LEN * D_HEAD;
    const float* Vh = V + (size_t)h * S_LEN * D_HEAD;

    // load Q tile transposed: Qs[d][r]
    for (int idx = t; idx < 64 * 64; idx += 256) {
        int r = idx >> 6, d = idx & 63;
        Qs[d * SMP + r] = Qh[(size_t)(q0 + r) * 64 + d];
    }
    __syncthreads();

    float m_r[4], l_r[4];
#pragma unroll
    for (int i = 0; i < 4; i++) { m_r[i] = -1e30f; l_r[i] = 0.0f; }

    // ---------------- pass 1: exact row max / sum ----------------
    for (int kt = 0; kt <= qt; kt++) {
        const int k0 = kt * 64;
        for (int idx = t; idx < 64 * 64; idx += 256) {
            int c = idx >> 6, d = idx & 63;
            KVs[d * SMP + c] = Kh[(size_t)(k0 + c) * 64 + d];
        }
        __syncthreads();

        float s[4][4];
#pragma unroll
        for (int i = 0; i < 4; i++)
#pragma unroll
            for (int j = 0; j < 4; j++) s[i][j] = 0.0f;
#pragma unroll 8
        for (int d = 0; d < 64; d++) {
            float4 a = *(const float4*)&Qs[d * SMP + ty * 4];
            float4 b = *(const float4*)&KVs[d * SMP + tx * 4];
            float av[4] = {a.x, a.y, a.z, a.w};
            float bv[4] = {b.x, b.y, b.z, b.w};
#pragma unroll
            for (int i = 0; i < 4; i++)
#pragma unroll
                for (int j = 0; j < 4; j++)
                    s[i][j] = fmaf(av[i], bv[j], s[i][j]);
        }
#pragma unroll
        for (int i = 0; i < 4; i++) {
            const int gi = q0 + ty * 4 + i;
#pragma unroll
            for (int j = 0; j < 4; j++) {
                const int gj = k0 + tx * 4 + j;
                s[i][j] = (gj <= gi) ? s[i][j] * 0.125f - (float)(gi - gj) * slope
                                     : -1e30f;
            }
            float tm = fmaxf(fmaxf(s[i][0], s[i][1]), fmaxf(s[i][2], s[i][3]));
            tm = rmax16(tm);
            float mn = fmaxf(m_r[i], tm);
            float p = __expf(s[i][0] - mn) + __expf(s[i][1] - mn)
                    + __expf(s[i][2] - mn) + __expf(s[i][3] - mn);
            p = rsum16(p);
            l_r[i] = l_r[i] * __expf(m_r[i] - mn) + p;
            m_r[i] = mn;
        }
        __syncthreads();
    }

    float linv[4];
#pragma unroll
    for (int i = 0; i < 4; i++) linv[i] = 1.0f / l_r[i];

    // ---------------- pass 2: write SA, accumulate z ----------------
    float zacc[4][4];
#pragma unroll
    for (int i = 0; i < 4; i++)
#pragma unroll
        for (int j = 0; j < 4; j++) zacc[i][j] = 0.0f;

    for (int kt = 0; kt <= qt; kt++) {
        const int k0 = kt * 64;
        for (int idx = t; idx < 64 * 64; idx += 256) {
            int c = idx >> 6, d = idx & 63;
            KVs[d * SMP + c] = Kh[(size_t)(k0 + c) * 64 + d];
        }
        __syncthreads();

        float s[4][4];
#pragma unroll
        for (int i = 0; i < 4; i++)
#pragma unroll
            for (int j = 0; j < 4; j++) s[i][j] = 0.0f;
#pragma unroll 8
        for (int d = 0; d < 64; d++) {
            float4 a = *(const float4*)&Qs[d * SMP + ty * 4];
            float4 b = *(const float4*)&KVs[d * SMP + tx * 4];
            float av[4] = {a.x, a.y, a.z, a.w};
            float bv[4] = {b.x, b.y, b.z, b.w};
#pragma unroll
            for (int i = 0; i < 4; i++)
#pragma unroll
                for (int j = 0; j < 4; j++)
                    s[i][j] = fmaf(av[i], bv[j], s[i][j]);
        }
        float P[4][4];
#pragma unroll
        for (int i = 0; i < 4; i++) {
            const int gi = q0 + ty * 4 + i;
#pragma unroll
            for (int j = 0; j < 4; j++) {
                const int gj = k0 + tx * 4 + j;
                P[i][j] = (gj <= gi)
                    ? __expf(s[i][j] * 0.125f - (float)(gi - gj) * slope - m_r[i]) * linv[i]
                    : 0.0f;
            }
        }
        if (SA) {
#pragma unroll
            for (int i = 0; i < 4; i++) {
                float4 w = make_float4(P[i][0], P[i][1], P[i][2], P[i][3]);
                *(float4*)&SA[((size_t)h * S_LEN + (q0 + ty * 4 + i)) * S_LEN + k0 + tx * 4] = w;
            }
        }
        __syncthreads();  // done reading K from KVs

        // load V (natural) and stage P transposed
        for (int idx = t; idx < 64 * 64; idx += 256) {
            int c = idx >> 6, v = idx & 63;
            KVs[c * SMP + v] = Vh[(size_t)(k0 + c) * 64 + v];
        }
#pragma unroll
        for (int j = 0; j < 4; j++) {
            float4 w = make_float4(P[0][j], P[1][j], P[2][j], P[3][j]);
            *(float4*)&Ps[(tx * 4 + j) * SMP + ty * 4] = w;
        }
        __syncthreads();

#pragma unroll 8
        for (int c = 0; c < 64; c++) {
            float4 a = *(const float4*)&Ps[c * SMP + ty * 4];
            float4 b = *(const float4*)&KVs[c * SMP + tx * 4];
            float av[4] = {a.x, a.y, a.z, a.w};
            float bv[4] = {b.x, b.y, b.z, b.w};
#pragma unroll
            for (int i = 0; i < 4; i++)
#pragma unroll
                for (int j = 0; j < 4; j++)
                    zacc[i][j] = fmaf(av[i], bv[j], zacc[i][j]);
        }
        __syncthreads();
    }

    // zero-fill strictly-upper tiles of SA
    if (SA) {
        const float4 z4 = make_float4(0.f, 0.f, 0.f, 0.f);
        for (int kt = qt + 1; kt < S_LEN / 64; kt++) {
            const int k0 = kt * 64;
#pragma unroll
            for (int i = 0; i < 4; i++)
                *(float4*)&SA[((size_t)h * S_LEN + (q0 + ty * 4 + i)) * S_LEN + k0 + tx * 4] = z4;
        }
    }

    // write z directly into concat layout Z[s][h*64 + v]
#pragma unroll
    for (int i = 0; i < 4; i++) {
        float4 w = make_float4(zacc[i][0], zacc[i][1], zacc[i][2], zacc[i][3]);
        *(float4*)&Z[(size_t)(q0 + ty * 4 + i) * D_MODEL + h * D_HEAD + tx * 4] = w;
    }
}

// =================================================================
extern "C" void kernel_launch(void* const* d_in, const int* in_sizes, int n_in,
                              void* d_out, int out_size)
{
    const float* X   = (const float*)d_in[0];
    const float* WQ  = (const float*)d_in[1];
    const float* WK  = (const float*)d_in[2];
    const float* WV  = (const float*)d_in[3];
    const float* WOw = (const float*)d_in[4];
    const float* WOb = (const float*)d_in[5];
    const float* F1w = (const float*)d_in[6];
    const float* F1b = (const float*)d_in[7];
    const float* F2w = (const float*)d_in[8];
    const float* F2b = (const float*)d_in[9];

    float *Qp, *Kp, *Vp, *Zp, *Ap, *Hp, *Dp;
    cudaGetSymbolAddress((void**)&Qp, g_Q);
    cudaGetSymbolAddress((void**)&Kp, g_K);
    cudaGetSymbolAddress((void**)&Vp, g_V);
    cudaGetSymbolAddress((void**)&Zp, g_Z);
    cudaGetSymbolAddress((void**)&Ap, g_ATT);
    cudaGetSymbolAddress((void**)&Hp, g_HID);
    cudaGetSymbolAddress((void**)&Dp, g_DUMMY);

    const size_t SA_EL = (size_t)N_HEADS * S_LEN * S_LEN;
    const size_t OV_EL = (size_t)S_LEN * D_MODEL;
    float* out = (float*)d_out;
    float* sa;
    float* ov;
    if ((size_t)out_size >= SA_EL + OV_EL)      { sa = out;     ov = out + SA_EL; }
    else if ((size_t)out_size >= SA_EL)         { sa = out;     ov = Dp; }
    else                                        { sa = nullptr; ov = out; }

    const int attn_smem = 3 * 64 * SMP * 4;
    cudaFuncSetAttribute(attn_kernel, cudaFuncAttributeMaxDynamicSharedMemorySize, attn_smem);

    dim3 blk(256);

    // QKV projections (per-head weight layout)
    gemm_kernel<0, false, false, false, true><<<dim3(8, 16), blk>>>(X, WQ, nullptr, nullptr, Qp, S_LEN, D_MODEL, D_MODEL);
    gemm_kernel<0, false, false, false, true><<<dim3(8, 16), blk>>>(X, WK, nullptr, nullptr, Kp, S_LEN, D_MODEL, D_MODEL);
    gemm_kernel<0, false, false, false, true><<<dim3(8, 16), blk>>>(X, WV, nullptr, nullptr, Vp, S_LEN, D_MODEL, D_MODEL);

    // attention (writes SA + z)
    attn_kernel<<<dim3(S_LEN / 64, N_HEADS), blk, attn_smem>>>(Qp, Kp, Vp, sa, Zp);

    // attouts = X + z @ WO^T + WO_b
    gemm_kernel<1, true, false, true, false><<<dim3(8, 16), blk>>>(Zp, WOw, WOb, X, Ap, S_LEN, D_MODEL, D_MODEL);
    // hidden = relu(attouts @ FF1^T + b1)
    gemm_kernel<1, true, true, false, false><<<dim3(32, 16), blk>>>(Ap, F1w, F1b, nullptr, Hp, S_LEN, D_FF, D_MODEL);
    // out = attouts + hidden @ FF2^T + b2
    gemm_kernel<1, true, false, true, false><<<dim3(8, 16), blk>>>(Hp, F2w, F2b, Ap, ov, S_LEN, D_MODEL, D_FF);
}

// round 3
// speedup vs baseline: 1.5914x; 1.5914x over previous
#include <cuda_runtime.h>
#include <cstdint>

#define S_LEN   2048
#define D_MODEL 1024
#define N_HEADS 16
#define D_HEAD  64
#define D_FF    4096

// ---------------- scratch (no allocation allowed) ----------------
__device__ float g_Q[N_HEADS * S_LEN * D_HEAD];
__device__ float g_K[N_HEADS * S_LEN * D_HEAD];
__device__ float g_V[N_HEADS * S_LEN * D_HEAD];
__device__ float g_Z[S_LEN * D_MODEL];
__device__ float g_ATT[S_LEN * D_MODEL];
__device__ float g_HID[S_LEN * D_FF];
__device__ float g_DUMMY[S_LEN * D_MODEL];

// =================================================================
// tf32 tensor-core GEMM: 128x128 tile, BK=32, 256 threads (8 warps),
// warp grid 4(M) x 2(N), warp tile 32x64, mma.sync m16n8k8 tf32.
// BMODE 0: B is per-head [H][K][64], col n -> (h=n/64, e=n%64)   (QKV)
// BMODE 1: B is [N][K] row-major (C = A @ B^T)                    (WO/FF)
// OUTHEAD: write C[n/64][m][n%64] per-head layout.
// SPLIT:   2-term tf32 split (hi+lo) for near-fp32 accuracy (Q,K).
// =================================================================
__device__ __forceinline__ float to_tf32(float x) {
    float r;
    asm("cvt.rna.tf32.f32 %0, %1;" : "=f"(r) : "f"(x));
    return r;
}

__device__ __forceinline__ void mma8(float* c,
    uint32_t a0, uint32_t a1, uint32_t a2, uint32_t a3,
    uint32_t b0, uint32_t b1)
{
    asm volatile(
        "mma.sync.aligned.m16n8k8.row.col.f32.tf32.tf32.f32 "
        "{%0,%1,%2,%3},{%4,%5,%6,%7},{%8,%9},{%0,%1,%2,%3};"
        : "+f"(c[0]), "+f"(c[1]), "+f"(c[2]), "+f"(c[3])
        : "r"(a0), "r"(a1), "r"(a2), "r"(a3), "r"(b0), "r"(b1));
}

#define GP 136          // padded row stride (floats): 136 % 32 == 8 -> conflict-free frags
#define GTILE (32 * GP) // one 32xk buffer

template<int BMODE, bool BIAS, bool RELU, bool RESID, bool OUTHEAD, bool SPLIT>
__global__ __launch_bounds__(256) void gemm_tc(
    const float* __restrict__ A, const float* __restrict__ B,
    const float* __restrict__ bias, const float* __restrict__ resid,
    float* __restrict__ C, int M, int N, int K)
{
    extern __shared__ float sm[];
    float* Ahi = sm;
    float* Alo = SPLIT ? (sm + GTILE) : sm;
    float* Bhi = sm + (SPLIT ? 2 : 1) * GTILE;
    float* Blo = SPLIT ? (Bhi + GTILE) : Bhi;

    const int t    = threadIdx.x;
    const int lane = t & 31;
    const int w    = t >> 5;
    const int grp  = lane >> 2;      // 0..7
    const int qd   = lane & 3;       // 0..3
    const int wm   = (w & 3) * 32;   // warp M offset
    const int wn   = (w >> 2) * 64;  // warp N offset
    const int m0   = blockIdx.y * 128;
    const int n0   = blockIdx.x * 128;

    float acc[2][8][4];
#pragma unroll
    for (int i = 0; i < 2; i++)
#pragma unroll
        for (int j = 0; j < 8; j++)
#pragma unroll
            for (int k = 0; k < 4; k++) acc[i][j][k] = 0.0f;

    // loader mappings
    const int am  = t >> 1;          // A: row 0..127
    const int akq = (t & 1) * 16;    // A: k chunk
    const int bn1 = t >> 1;          // B mode1: row (n)
    const int bk1 = (t & 1) * 16;
    const int bk0 = t >> 3;          // B mode0: k 0..31
    const int bn0 = (t & 7) * 16;    // B mode0: n chunk

    for (int k0 = 0; k0 < K; k0 += 32) {
        // ---- A tile: load [m][k] chunk, store transposed As[k][m] ----
        {
            const float* ap = A + (size_t)(m0 + am) * K + k0 + akq;
            float v[16];
            *(float4*)&v[0]  = *(const float4*)(ap);
            *(float4*)&v[4]  = *(const float4*)(ap + 4);
            *(float4*)&v[8]  = *(const float4*)(ap + 8);
            *(float4*)&v[12] = *(const float4*)(ap + 12);
#pragma unroll
            for (int j = 0; j < 16; j++) {
                float hi = to_tf32(v[j]);
                Ahi[(akq + j) * GP + am] = hi;
                if (SPLIT) Alo[(akq + j) * GP + am] = to_tf32(v[j] - hi);
            }
        }
        // ---- B tile -> Bs[k][n] ----
        if (BMODE == 1) {
            const float* bp = B + (size_t)(n0 + bn1) * K + k0 + bk1;
            float v[16];
            *(float4*)&v[0]  = *(const float4*)(bp);
            *(float4*)&v[4]  = *(const float4*)(bp + 4);
            *(float4*)&v[8]  = *(const float4*)(bp + 8);
            *(float4*)&v[12] = *(const float4*)(bp + 12);
#pragma unroll
            for (int j = 0; j < 16; j++) {
                float hi = to_tf32(v[j]);
                Bhi[(bk1 + j) * GP + bn1] = hi;
                if (SPLIT) Blo[(bk1 + j) * GP + bn1] = to_tf32(v[j] - hi);
            }
        } else {
            const int ng = n0 + bn0;
            const int h  = ng >> 6;
            const int e  = ng & 63;
            const float* bp = B + ((size_t)h * K + (k0 + bk0)) * 64 + e;
            float v[16];
            *(float4*)&v[0]  = *(const float4*)(bp);
            *(float4*)&v[4]  = *(const float4*)(bp + 4);
            *(float4*)&v[8]  = *(const float4*)(bp + 8);
            *(float4*)&v[12] = *(const float4*)(bp + 12);
#pragma unroll
            for (int j = 0; j < 16; j++) {
                float hi = to_tf32(v[j]);
                Bhi[bk0 * GP + bn0 + j] = hi;
                if (SPLIT) Blo[bk0 * GP + bn0 + j] = to_tf32(v[j] - hi);
            }
        }
        __syncthreads();

#pragma unroll
        for (int ks = 0; ks < 32; ks += 8) {
            // A fragments for 2 m-tiles
            uint32_t afh[2][4], afl[2][4];
#pragma unroll
            for (int mt = 0; mt < 2; mt++) {
                const int mb = wm + mt * 16;
                afh[mt][0] = __float_as_uint(Ahi[(ks + qd)     * GP + mb + grp]);
                afh[mt][1] = __float_as_uint(Ahi[(ks + qd)     * GP + mb + grp + 8]);
                afh[mt][2] = __float_as_uint(Ahi[(ks + qd + 4) * GP + mb + grp]);
                afh[mt][3] = __float_as_uint(Ahi[(ks + qd + 4) * GP + mb + grp + 8]);
                if (SPLIT) {
                    afl[mt][0] = __float_as_uint(Alo[(ks + qd)     * GP + mb + grp]);
                    afl[mt][1] = __float_as_uint(Alo[(ks + qd)     * GP + mb + grp + 8]);
                    afl[mt][2] = __float_as_uint(Alo[(ks + qd + 4) * GP + mb + grp]);
                    afl[mt][3] = __float_as_uint(Alo[(ks + qd + 4) * GP + mb + grp + 8]);
                }
            }
#pragma unroll
            for (int nt = 0; nt < 8; nt++) {
                const int nb = wn + nt * 8;
                uint32_t bh0 = __float_as_uint(Bhi[(ks + qd)     * GP + nb + grp]);
                uint32_t bh1 = __float_as_uint(Bhi[(ks + qd + 4) * GP + nb + grp]);
#pragma unroll
                for (int mt = 0; mt < 2; mt++)
                    mma8(acc[mt][nt], afh[mt][0], afh[mt][1], afh[mt][2], afh[mt][3], bh0, bh1);
                if (SPLIT) {
                    uint32_t bl0 = __float_as_uint(Blo[(ks + qd)     * GP + nb + grp]);
                    uint32_t bl1 = __float_as_uint(Blo[(ks + qd + 4) * GP + nb + grp]);
#pragma unroll
                    for (int mt = 0; mt < 2; mt++) {
                        mma8(acc[mt][nt], afh[mt][0], afh[mt][1], afh[mt][2], afh[mt][3], bl0, bl1);
                        mma8(acc[mt][nt], afl[mt][0], afl[mt][1], afl[mt][2], afl[mt][3], bh0, bh1);
                    }
                }
            }
        }
        __syncthreads();
    }

    // ---- epilogue: each thread owns rows {grp, grp+8} cols {2qd, 2qd+1} per tile ----
#pragma unroll
    for (int mt = 0; mt < 2; mt++) {
#pragma unroll
        for (int nt = 0; nt < 8; nt++) {
            const int n  = n0 + wn + nt * 8 + 2 * qd;
            float2 v0 = make_float2(acc[mt][nt][0], acc[mt][nt][1]);
            float2 v1 = make_float2(acc[mt][nt][2], acc[mt][nt][3]);
            if (BIAS) {
                float2 bb = *(const float2*)&bias[n];
                v0.x += bb.x; v0.y += bb.y;
                v1.x += bb.x; v1.y += bb.y;
            }
            if (RELU) {
                v0.x = fmaxf(v0.x, 0.f); v0.y = fmaxf(v0.y, 0.f);
                v1.x = fmaxf(v1.x, 0.f); v1.y = fmaxf(v1.y, 0.f);
            }
            const int mA = m0 + wm + mt * 16 + grp;
            const int mB = mA + 8;
            if (RESID) {
                float2 r0 = *(const float2*)&resid[(size_t)mA * N + n];
                float2 r1 = *(const float2*)&resid[(size_t)mB * N + n];
                v0.x += r0.x; v0.y += r0.y;
                v1.x += r1.x; v1.y += r1.y;
            }
            if (OUTHEAD) {
                const int h = n >> 6;
                const int e = n & 63;
                *(float2*)&C[((size_t)h * M + mA) * 64 + e] = v0;
                *(float2*)&C[((size_t)h * M + mB) * 64 + e] = v1;
            } else {
                *(float2*)&C[(size_t)mA * N + n] = v0;
                *(float2*)&C[(size_t)mB * N + n] = v1;
            }
        }
    }
}

// =================================================================
// Attention: one block = (head, 64-query tile). 256 threads, 4x4 microtiles.
// =================================================================
__device__ __forceinline__ float rmax16(float v) {
#pragma unroll
    for (int o = 8; o > 0; o >>= 1) v = fmaxf(v, __shfl_xor_sync(0xffffffffu, v, o));
    return v;
}
__device__ __forceinline__ float rsum16(float v) {
#pragma unroll
    for (int o = 8; o > 0; o >>= 1) v += __shfl_xor_sync(0xffffffffu, v, o);
    return v;
}

#define SMP 68

__global__ __launch_bounds__(256) void attn_kernel(
    const float* __restrict__ Q, const float* __restrict__ K,
    const float* __restrict__ V, float* __restrict__ SA, float* __restrict__ Z)
{
    extern __shared__ float sm[];
    float* Qs  = sm;
    float* KVs = sm + 64 * SMP;
    float* Ps  = sm + 2 * 64 * SMP;

    const int t  = threadIdx.x;
    const int ty = t >> 4;
    const int tx = t & 15;
    const int qt = blockIdx.x;
    const int h  = blockIdx.y;
    const int q0 = qt * 64;

    const float slope = exp2f(-0.5f * (float)(h + 1));
    const float* Qh = Q + (size_t)h * S_LEN * D_HEAD;
    const float* Kh = K + (size_t)h * S_LEN * D_HEAD;
    const float* Vh = V + (size_t)h * S_LEN * D_HEAD;

    for (int idx = t; idx < 64 * 64; idx += 256) {
        int r = idx >> 6, d = idx & 63;
        Qs[d * SMP + r] = Qh[(size_t)(q0 + r) * 64 + d];
    }
    __syncthreads();

    float m_r[4], l_r[4];
#pragma unroll
    for (int i = 0; i < 4; i++) { m_r[i] = -1e30f; l_r[i] = 0.0f; }

    for (int kt = 0; kt <= qt; kt++) {
        const int k0 = kt * 64;
        for (int idx = t; idx < 64 * 64; idx += 256) {
            int c = idx >> 6, d = idx & 63;
            KVs[d * SMP + c] = Kh[(size_t)(k0 + c) * 64 + d];
        }
        __syncthreads();

        float s[4][4];
#pragma unroll
        for (int i = 0; i < 4; i++)
#pragma unroll
            for (int j = 0; j < 4; j++) s[i][j] = 0.0f;
#pragma unroll 8
        for (int d = 0; d < 64; d++) {
            float4 a = *(const float4*)&Qs[d * SMP + ty * 4];
            float4 b = *(const float4*)&KVs[d * SMP + tx * 4];
            float av[4] = {a.x, a.y, a.z, a.w};
            float bv[4] = {b.x, b.y, b.z, b.w};
#pragma unroll
            for (int i = 0; i < 4; i++)
#pragma unroll
                for (int j = 0; j < 4; j++)
                    s[i][j] = fmaf(av[i], bv[j], s[i][j]);
        }
#pragma unroll
        for (int i = 0; i < 4; i++) {
            const int gi = q0 + ty * 4 + i;
#pragma unroll
            for (int j = 0; j < 4; j++) {
                const int gj = k0 + tx * 4 + j;
                s[i][j] = (gj <= gi) ? s[i][j] * 0.125f - (float)(gi - gj) * slope
                                     : -1e30f;
            }
            float tm = fmaxf(fmaxf(s[i][0], s[i][1]), fmaxf(s[i][2], s[i][3]));
            tm = rmax16(tm);
            float mn = fmaxf(m_r[i], tm);
            float p = __expf(s[i][0] - mn) + __expf(s[i][1] - mn)
                    + __expf(s[i][2] - mn) + __expf(s[i][3] - mn);
            p = rsum16(p);
            l_r[i] = l_r[i] * __expf(m_r[i] - mn) + p;
            m_r[i] = mn;
        }
        __syncthreads();
    }

    float linv[4];
#pragma unroll
    for (int i = 0; i < 4; i++) linv[i] = 1.0f / l_r[i];

    float zacc[4][4];
#pragma unroll
    for (int i = 0; i < 4; i++)
#pragma unroll
        for (int j = 0; j < 4; j++) zacc[i][j] = 0.0f;

    for (int kt = 0; kt <= qt; kt++) {
        const int k0 = kt * 64;
        for (int idx = t; idx < 64 * 64; idx += 256) {
            int c = idx >> 6, d = idx & 63;
            KVs[d * SMP + c] = Kh[(size_t)(k0 + c) * 64 + d];
        }
        __syncthreads();

        float s[4][4];
#pragma unroll
        for (int i = 0; i < 4; i++)
#pragma unroll
            for (int j = 0; j < 4; j++) s[i][j] = 0.0f;
#pragma unroll 8
        for (int d = 0; d < 64; d++) {
            float4 a = *(const float4*)&Qs[d * SMP + ty * 4];
            float4 b = *(const float4*)&KVs[d * SMP + tx * 4];
            float av[4] = {a.x, a.y, a.z, a.w};
            float bv[4] = {b.x, b.y, b.z, b.w};
#pragma unroll
            for (int i = 0; i < 4; i++)
#pragma unroll
                for (int j = 0; j < 4; j++)
                    s[i][j] = fmaf(av[i], bv[j], s[i][j]);
        }
        float P[4][4];
#pragma unroll
        for (int i = 0; i < 4; i++) {
            const int gi = q0 + ty * 4 + i;
#pragma unroll
            for (int j = 0; j < 4; j++) {
                const int gj = k0 + tx * 4 + j;
                P[i][j] = (gj <= gi)
                    ? __expf(s[i][j] * 0.125f - (float)(gi - gj) * slope - m_r[i]) * linv[i]
                    : 0.0f;
            }
        }
        if (SA) {
#pragma unroll
            for (int i = 0; i < 4; i++) {
                float4 wv = make_float4(P[i][0], P[i][1], P[i][2], P[i][3]);
                *(float4*)&SA[((size_t)h * S_LEN + (q0 + ty * 4 + i)) * S_LEN + k0 + tx * 4] = wv;
            }
        }
        __syncthreads();

        for (int idx = t; idx < 64 * 64; idx += 256) {
            int c = idx >> 6, v = idx & 63;
            KVs[c * SMP + v] = Vh[(size_t)(k0 + c) * 64 + v];
        }
#pragma unroll
        for (int j = 0; j < 4; j++) {
            float4 wv = make_float4(P[0][j], P[1][j], P[2][j], P[3][j]);
            *(float4*)&Ps[(tx * 4 + j) * SMP + ty * 4] = wv;
        }
        __syncthreads();

#pragma unroll 8
        for (int c = 0; c < 64; c++) {
            float4 a = *(const float4*)&Ps[c * SMP + ty * 4];
            float4 b = *(const float4*)&KVs[c * SMP + tx * 4];
            float av[4] = {a.x, a.y, a.z, a.w};
            float bv[4] = {b.x, b.y, b.z, b.w};
#pragma unroll
            for (int i = 0; i < 4; i++)
#pragma unroll
                for (int j = 0; j < 4; j++)
                    zacc[i][j] = fmaf(av[i], bv[j], zacc[i][j]);
        }
        __syncthreads();
    }

    if (SA) {
        const float4 z4 = make_float4(0.f, 0.f, 0.f, 0.f);
        for (int kt = qt + 1; kt < S_LEN / 64; kt++) {
            const int k0 = kt * 64;
#pragma unroll
            for (int i = 0; i < 4; i++)
                *(float4*)&SA[((size_t)h * S_LEN + (q0 + ty * 4 + i)) * S_LEN + k0 + tx * 4] = z4;
        }
    }

#pragma unroll
    for (int i = 0; i < 4; i++) {
        float4 wv = make_float4(zacc[i][0], zacc[i][1], zacc[i][2], zacc[i][3]);
        *(float4*)&Z[(size_t)(q0 + ty * 4 + i) * D_MODEL + h * D_HEAD + tx * 4] = wv;
    }
}

// =================================================================
extern "C" void kernel_launch(void* const* d_in, const int* in_sizes, int n_in,
                              void* d_out, int out_size)
{
    const float* X   = (const float*)d_in[0];
    const float* WQ  = (const float*)d_in[1];
    const float* WK  = (const float*)d_in[2];
    const float* WV  = (const float*)d_in[3];
    const float* WOw = (const float*)d_in[4];
    const float* WOb = (const float*)d_in[5];
    const float* F1w = (const float*)d_in[6];
    const float* F1b = (const float*)d_in[7];
    const float* F2w = (const float*)d_in[8];
    const float* F2b = (const float*)d_in[9];

    float *Qp, *Kp, *Vp, *Zp, *Ap, *Hp, *Dp;
    cudaGetSymbolAddress((void**)&Qp, g_Q);
    cudaGetSymbolAddress((void**)&Kp, g_K);
    cudaGetSymbolAddress((void**)&Vp, g_V);
    cudaGetSymbolAddress((void**)&Zp, g_Z);
    cudaGetSymbolAddress((void**)&Ap, g_ATT);
    cudaGetSymbolAddress((void**)&Hp, g_HID);
    cudaGetSymbolAddress((void**)&Dp, g_DUMMY);

    const size_t SA_EL = (size_t)N_HEADS * S_LEN * S_LEN;
    const size_t OV_EL = (size_t)S_LEN * D_MODEL;
    float* out = (float*)d_out;
    float* sa;
    float* ov;
    if ((size_t)out_size >= SA_EL + OV_EL)      { sa = out;     ov = out + SA_EL; }
    else if ((size_t)out_size >= SA_EL)         { sa = out;     ov = Dp; }
    else                                        { sa = nullptr; ov = out; }

    const int attn_smem = 3 * 64 * SMP * 4;
    cudaFuncSetAttribute(attn_kernel, cudaFuncAttributeMaxDynamicSharedMemorySize, attn_smem);

    const int smem_ns = 2 * GTILE * 4;   // 34816 (fits default dyn-smem limit)
    const int smem_sp = 4 * GTILE * 4;   // 69632 (needs attribute)
    cudaFuncSetAttribute(gemm_tc<0,false,false,false,true,true>,
                         cudaFuncAttributeMaxDynamicSharedMemorySize, smem_sp);

    dim3 blk(256);

    // Q,K: split-tf32 (near-fp32 accuracy for SA path); V: plain tf32
    gemm_tc<0,false,false,false,true,true ><<<dim3(8, 16), blk, smem_sp>>>(X, WQ, nullptr, nullptr, Qp, S_LEN, D_MODEL, D_MODEL);
    gemm_tc<0,false,false,false,true,true ><<<dim3(8, 16), blk, smem_sp>>>(X, WK, nullptr, nullptr, Kp, S_LEN, D_MODEL, D_MODEL);
    gemm_tc<0,false,false,false,true,false><<<dim3(8, 16), blk, smem_ns>>>(X, WV, nullptr, nullptr, Vp, S_LEN, D_MODEL, D_MODEL);

    // attention (writes SA + z)
    attn_kernel<<<dim3(S_LEN / 64, N_HEADS), blk, attn_smem>>>(Qp, Kp, Vp, sa, Zp);

    // attouts = X + z @ WO^T + WO_b
    gemm_tc<1,true,false,true,false,false><<<dim3(8, 16), blk, smem_ns>>>(Zp, WOw, WOb, X, Ap, S_LEN, D_MODEL, D_MODEL);
    // hidden = relu(attouts @ FF1^T + b1)
    gemm_tc<1,true,true,false,false,false><<<dim3(32, 16), blk, smem_ns>>>(Ap, F1w, F1b, nullptr, Hp, S_LEN, D_FF, D_MODEL);
    // out = attouts + hidden @ FF2^T + b2
    gemm_tc<1,true,false,true,false,false><<<dim3(8, 16), blk, smem_ns>>>(Hp, F2w, F2b, Ap, ov, S_LEN, D_MODEL, D_FF);
}

// round 4
// speedup vs baseline: 1.8459x; 1.1599x over previous
#include <cuda_runtime.h>
#include <cstdint>

#define S_LEN   2048
#define D_MODEL 1024
#define N_HEADS 16
#define D_HEAD  64
#define D_FF    4096

// ---------------- scratch (no allocation allowed) ----------------
__device__ float g_Q[N_HEADS * S_LEN * D_HEAD];
__device__ float g_K[N_HEADS * S_LEN * D_HEAD];
__device__ float g_V[N_HEADS * S_LEN * D_HEAD];
__device__ float g_Z[S_LEN * D_MODEL];
__device__ float g_ATT[S_LEN * D_MODEL];
__device__ float g_HID[S_LEN * D_FF];
__device__ float g_L[N_HEADS * S_LEN];
__device__ float g_DUMMY[S_LEN * D_MODEL];

// =================================================================
// shared helpers
// =================================================================
__device__ __forceinline__ float to_tf32(float x) {
    float r;
    asm("cvt.rna.tf32.f32 %0, %1;" : "=f"(r) : "f"(x));
    return r;
}

__device__ __forceinline__ void mma8(float* c,
    uint32_t a0, uint32_t a1, uint32_t a2, uint32_t a3,
    uint32_t b0, uint32_t b1)
{
    asm volatile(
        "mma.sync.aligned.m16n8k8.row.col.f32.tf32.tf32.f32 "
        "{%0,%1,%2,%3},{%4,%5,%6,%7},{%8,%9},{%0,%1,%2,%3};"
        : "+f"(c[0]), "+f"(c[1]), "+f"(c[2]), "+f"(c[3])
        : "r"(a0), "r"(a1), "r"(a2), "r"(a3), "r"(b0), "r"(b1));
}

// =================================================================
// tf32 tensor-core GEMM (unchanged from R3)
// =================================================================
#define GP 136
#define GTILE (32 * GP)

template<int BMODE, bool BIAS, bool RELU, bool RESID, bool OUTHEAD, bool SPLIT>
__global__ __launch_bounds__(256) void gemm_tc(
    const float* __restrict__ A, const float* __restrict__ B,
    const float* __restrict__ bias, const float* __restrict__ resid,
    float* __restrict__ C, int M, int N, int K)
{
    extern __shared__ float sm[];
    float* Ahi = sm;
    float* Alo = SPLIT ? (sm + GTILE) : sm;
    float* Bhi = sm + (SPLIT ? 2 : 1) * GTILE;
    float* Blo = SPLIT ? (Bhi + GTILE) : Bhi;

    const int t    = threadIdx.x;
    const int lane = t & 31;
    const int w    = t >> 5;
    const int grp  = lane >> 2;
    const int qd   = lane & 3;
    const int wm   = (w & 3) * 32;
    const int wn   = (w >> 2) * 64;
    const int m0   = blockIdx.y * 128;
    const int n0   = blockIdx.x * 128;

    float acc[2][8][4];
#pragma unroll
    for (int i = 0; i < 2; i++)
#pragma unroll
        for (int j = 0; j < 8; j++)
#pragma unroll
            for (int k = 0; k < 4; k++) acc[i][j][k] = 0.0f;

    const int am  = t >> 1;
    const int akq = (t & 1) * 16;
    const int bn1 = t >> 1;
    const int bk1 = (t & 1) * 16;
    const int bk0 = t >> 3;
    const int bn0 = (t & 7) * 16;

    for (int k0 = 0; k0 < K; k0 += 32) {
        {
            const float* ap = A + (size_t)(m0 + am) * K + k0 + akq;
            float v[16];
            *(float4*)&v[0]  = *(const float4*)(ap);
            *(float4*)&v[4]  = *(const float4*)(ap + 4);
            *(float4*)&v[8]  = *(const float4*)(ap + 8);
            *(float4*)&v[12] = *(const float4*)(ap + 12);
#pragma unroll
            for (int j = 0; j < 16; j++) {
                float hi = to_tf32(v[j]);
                Ahi[(akq + j) * GP + am] = hi;
                if (SPLIT) Alo[(akq + j) * GP + am] = to_tf32(v[j] - hi);
            }
        }
        if (BMODE == 1) {
            const float* bp = B + (size_t)(n0 + bn1) * K + k0 + bk1;
            float v[16];
            *(float4*)&v[0]  = *(const float4*)(bp);
            *(float4*)&v[4]  = *(const float4*)(bp + 4);
            *(float4*)&v[8]  = *(const float4*)(bp + 8);
            *(float4*)&v[12] = *(const float4*)(bp + 12);
#pragma unroll
            for (int j = 0; j < 16; j++) {
                float hi = to_tf32(v[j]);
                Bhi[(bk1 + j) * GP + bn1] = hi;
                if (SPLIT) Blo[(bk1 + j) * GP + bn1] = to_tf32(v[j] - hi);
            }
        } else {
            const int ng = n0 + bn0;
            const int h  = ng >> 6;
            const int e  = ng & 63;
            const float* bp = B + ((size_t)h * K + (k0 + bk0)) * 64 + e;
            float v[16];
            *(float4*)&v[0]  = *(const float4*)(bp);
            *(float4*)&v[4]  = *(const float4*)(bp + 4);
            *(float4*)&v[8]  = *(const float4*)(bp + 8);
            *(float4*)&v[12] = *(const float4*)(bp + 12);
#pragma unroll
            for (int j = 0; j < 16; j++) {
                float hi = to_tf32(v[j]);
                Bhi[bk0 * GP + bn0 + j] = hi;
                if (SPLIT) Blo[bk0 * GP + bn0 + j] = to_tf32(v[j] - hi);
            }
        }
        __syncthreads();

#pragma unroll
        for (int ks = 0; ks < 32; ks += 8) {
            uint32_t afh[2][4], afl[2][4];
#pragma unroll
            for (int mt = 0; mt < 2; mt++) {
                const int mb = wm + mt * 16;
                afh[mt][0] = __float_as_uint(Ahi[(ks + qd)     * GP + mb + grp]);
                afh[mt][1] = __float_as_uint(Ahi[(ks + qd)     * GP + mb + grp + 8]);
                afh[mt][2] = __float_as_uint(Ahi[(ks + qd + 4) * GP + mb + grp]);
                afh[mt][3] = __float_as_uint(Ahi[(ks + qd + 4) * GP + mb + grp + 8]);
                if (SPLIT) {
                    afl[mt][0] = __float_as_uint(Alo[(ks + qd)     * GP + mb + grp]);
                    afl[mt][1] = __float_as_uint(Alo[(ks + qd)     * GP + mb + grp + 8]);
                    afl[mt][2] = __float_as_uint(Alo[(ks + qd + 4) * GP + mb + grp]);
                    afl[mt][3] = __float_as_uint(Alo[(ks + qd + 4) * GP + mb + grp + 8]);
                }
            }
#pragma unroll
            for (int nt = 0; nt < 8; nt++) {
                const int nb = wn + nt * 8;
                uint32_t bh0 = __float_as_uint(Bhi[(ks + qd)     * GP + nb + grp]);
                uint32_t bh1 = __float_as_uint(Bhi[(ks + qd + 4) * GP + nb + grp]);
#pragma unroll
                for (int mt = 0; mt < 2; mt++)
                    mma8(acc[mt][nt], afh[mt][0], afh[mt][1], afh[mt][2], afh[mt][3], bh0, bh1);
                if (SPLIT) {
                    uint32_t bl0 = __float_as_uint(Blo[(ks + qd)     * GP + nb + grp]);
                    uint32_t bl1 = __float_as_uint(Blo[(ks + qd + 4) * GP + nb + grp]);
#pragma unroll
                    for (int mt = 0; mt < 2; mt++) {
                        mma8(acc[mt][nt], afh[mt][0], afh[mt][1], afh[mt][2], afh[mt][3], bl0, bl1);
                        mma8(acc[mt][nt], afl[mt][0], afl[mt][1], afl[mt][2], afl[mt][3], bh0, bh1);
                    }
                }
            }
        }
        __syncthreads();
    }

#pragma unroll
    for (int mt = 0; mt < 2; mt++) {
#pragma unroll
        for (int nt = 0; nt < 8; nt++) {
            const int n  = n0 + wn + nt * 8 + 2 * qd;
            float2 v0 = make_float2(acc[mt][nt][0], acc[mt][nt][1]);
            float2 v1 = make_float2(acc[mt][nt][2], acc[mt][nt][3]);
            if (BIAS) {
                float2 bb = *(const float2*)&bias[n];
                v0.x += bb.x; v0.y += bb.y;
                v1.x += bb.x; v1.y += bb.y;
            }
            if (RELU) {
                v0.x = fmaxf(v0.x, 0.f); v0.y = fmaxf(v0.y, 0.f);
                v1.x = fmaxf(v1.x, 0.f); v1.y = fmaxf(v1.y, 0.f);
            }
            const int mA = m0 + wm + mt * 16 + grp;
            const int mB = mA + 8;
            if (RESID) {
                float2 r0 = *(const float2*)&resid[(size_t)mA * N + n];
                float2 r1 = *(const float2*)&resid[(size_t)mB * N + n];
                v0.x += r0.x; v0.y += r0.y;
                v1.x += r1.x; v1.y += r1.y;
            }
            if (OUTHEAD) {
                const int h = n >> 6;
                const int e = n & 63;
                *(float2*)&C[((size_t)h * M + mA) * 64 + e] = v0;
                *(float2*)&C[((size_t)h * M + mB) * 64 + e] = v1;
            } else {
                *(float2*)&C[(size_t)mA * N + n] = v0;
                *(float2*)&C[(size_t)mB * N + n] = v1;
            }
        }
    }
}

// =================================================================
// Tensor-core attention. Block = (head, 64-query tile), 256 thr, 8 warps.
// Warp tile 16(m) x 32(n). No-max softmax: P~=exp(s), l=sum, z=z~/l.
// SA written UNNORMALIZED; sa_rescale normalizes + zero-fills upper.
// Scores: split tf32 (hi*hi + hi*lo + lo*hi).  z: plain tf32.
// smem tiles stored naturally, pad 72 -> conflict-free frag LDS.
// =================================================================
#define AP 72

__global__ __launch_bounds__(256, 2) void attn_tc(
    const float* __restrict__ Q, const float* __restrict__ K,
    const float* __restrict__ V, float* __restrict__ SA,
    float* __restrict__ Z, float* __restrict__ Lsum)
{
    extern __shared__ float sm[];
    float* Qh_s = sm;               // [64][AP]
    float* Ql_s = sm + 64 * AP;     // [64][AP]
    float* Kh_s = sm + 2 * 64 * AP; // [64][AP]
    float* Kl_s = sm + 3 * 64 * AP; // [64][AP]
    float* Vs   = sm + 4 * 64 * AP; // [64][AP]
    float* Ps   = sm + 5 * 64 * AP; // [64][AP]

    const int t    = threadIdx.x;
    const int lane = t & 31;
    const int w    = t >> 5;
    const int grp  = lane >> 2;
    const int qd   = lane & 3;
    const int wm   = (w >> 1) * 16;   // 4 m-strips
    const int wn   = (w & 1) * 32;    // 2 n-halves
    const int qt   = blockIdx.x;
    const int h    = blockIdx.y;
    const int q0   = qt * 64;

    const float slope = exp2f(-0.5f * (float)(h + 1));
    const float* Qg = Q + (size_t)h * S_LEN * D_HEAD;
    const float* Kg = K + (size_t)h * S_LEN * D_HEAD;
    const float* Vg = V + (size_t)h * S_LEN * D_HEAD;

    // ---- load Q tile (hi/lo), natural layout ----
    {
        const int r  = t >> 2;
        const int dq = (t & 3) * 16;
        const float* qp = Qg + (size_t)(q0 + r) * 64 + dq;
        float v[16];
        *(float4*)&v[0]  = *(const float4*)(qp);
        *(float4*)&v[4]  = *(const float4*)(qp + 4);
        *(float4*)&v[8]  = *(const float4*)(qp + 8);
        *(float4*)&v[12] = *(const float4*)(qp + 12);
#pragma unroll
        for (int j = 0; j < 16; j++) {
            float hi = to_tf32(v[j]);
            Qh_s[r * AP + dq + j] = hi;
            Ql_s[r * AP + dq + j] = to_tf32(v[j] - hi);
        }
    }

    float zacc[4][4];
#pragma unroll
    for (int i = 0; i < 4; i++)
#pragma unroll
        for (int j = 0; j < 4; j++) zacc[i][j] = 0.0f;
    float la = 0.0f, lb = 0.0f;

    const int iA = q0 + wm + grp;
    const int iB = iA + 8;

    for (int kt = 0; kt <= qt; kt++) {
        const int k0 = kt * 64;
        __syncthreads();   // prev z-mma done before overwriting K/V tiles
        {
            const int c  = t >> 2;
            const int dq = (t & 3) * 16;
            const float* kp = Kg + (size_t)(k0 + c) * 64 + dq;
            const float* vp = Vg + (size_t)(k0 + c) * 64 + dq;
            float kv[16], vv[16];
            *(float4*)&kv[0]  = *(const float4*)(kp);
            *(float4*)&kv[4]  = *(const float4*)(kp + 4);
            *(float4*)&kv[8]  = *(const float4*)(kp + 8);
            *(float4*)&kv[12] = *(const float4*)(kp + 12);
            *(float4*)&vv[0]  = *(const float4*)(vp);
            *(float4*)&vv[4]  = *(const float4*)(vp + 4);
            *(float4*)&vv[8]  = *(const float4*)(vp + 8);
            *(float4*)&vv[12] = *(const float4*)(vp + 12);
#pragma unroll
            for (int j = 0; j < 16; j++) {
                float hi = to_tf32(kv[j]);
                Kh_s[c * AP + dq + j] = hi;
                Kl_s[c * AP + dq + j] = to_tf32(kv[j] - hi);
                Vs[c * AP + dq + j]   = to_tf32(vv[j]);
            }
        }
        __syncthreads();

        // ---- scores: S = Q K^T (split tf32) ----
        float sacc[4][4];
#pragma unroll
        for (int i = 0; i < 4; i++)
#pragma unroll
            for (int j = 0; j < 4; j++) sacc[i][j] = 0.0f;

#pragma unroll
        for (int ks = 0; ks < 64; ks += 8) {
            uint32_t ah0 = __float_as_uint(Qh_s[(wm + grp)     * AP + ks + qd]);
            uint32_t ah1 = __float_as_uint(Qh_s[(wm + grp + 8) * AP + ks + qd]);
            uint32_t ah2 = __float_as_uint(Qh_s[(wm + grp)     * AP + ks + qd + 4]);
            uint32_t ah3 = __float_as_uint(Qh_s[(wm + grp + 8) * AP + ks + qd + 4]);
            uint32_t al0 = __float_as_uint(Ql_s[(wm + grp)     * AP + ks + qd]);
            uint32_t al1 = __float_as_uint(Ql_s[(wm + grp + 8) * AP + ks + qd]);
            uint32_t al2 = __float_as_uint(Ql_s[(wm + grp)     * AP + ks + qd + 4]);
            uint32_t al3 = __float_as_uint(Ql_s[(wm + grp + 8) * AP + ks + qd + 4]);
#pragma unroll
            for (int nt = 0; nt < 4; nt++) {
                const int nc = wn + nt * 8 + grp;   // key index (transposed read)
                uint32_t bh0 = __float_as_uint(Kh_s[nc * AP + ks + qd]);
                uint32_t bh1 = __float_as_uint(Kh_s[nc * AP + ks + qd + 4]);
                uint32_t bl0 = __float_as_uint(Kl_s[nc * AP + ks + qd]);
                uint32_t bl1 = __float_as_uint(Kl_s[nc * AP + ks + qd + 4]);
                mma8(sacc[nt], ah0, ah1, ah2, ah3, bh0, bh1);
                mma8(sacc[nt], ah0, ah1, ah2, ah3, bl0, bl1);
                mma8(sacc[nt], al0, al1, al2, al3, bh0, bh1);
            }
        }

        // ---- epilogue: scale + alibi + causal, exp, SA store, Ps store ----
        const bool diag = (kt == qt);
#pragma unroll
        for (int nt = 0; nt < 4; nt++) {
            const int j0 = k0 + wn + nt * 8 + 2 * qd;
            float p0 = __expf(sacc[nt][0] * 0.125f - (float)(iA - j0) * slope);
            float p1 = __expf(sacc[nt][1] * 0.125f - (float)(iA - j0 - 1) * slope);
            float p2 = __expf(sacc[nt][2] * 0.125f - (float)(iB - j0) * slope);
            float p3 = __expf(sacc[nt][3] * 0.125f - (float)(iB - j0 - 1) * slope);
            if (diag) {
                if (j0     > iA) p0 = 0.0f;
                if (j0 + 1 > iA) p1 = 0.0f;
                if (j0     > iB) p2 = 0.0f;
                if (j0 + 1 > iB) p3 = 0.0f;
            }
            la += p0 + p1;
            lb += p2 + p3;
            if (SA) {
                *(float2*)&SA[((size_t)h * S_LEN + iA) * S_LEN + j0] = make_float2(p0, p1);
                *(float2*)&SA[((size_t)h * S_LEN + iB) * S_LEN + j0] = make_float2(p2, p3);
            }
            const int pc = wn + nt * 8 + 2 * qd;
            *(float2*)&Ps[(wm + grp)     * AP + pc] = make_float2(to_tf32(p0), to_tf32(p1));
            *(float2*)&Ps[(wm + grp + 8) * AP + pc] = make_float2(to_tf32(p2), to_tf32(p3));
        }
        __syncthreads();

        // ---- z += P V ----
#pragma unroll
        for (int ks = 0; ks < 64; ks += 8) {
            uint32_t a0 = __float_as_uint(Ps[(wm + grp)     * AP + ks + qd]);
            uint32_t a1 = __float_as_uint(Ps[(wm + grp + 8) * AP + ks + qd]);
            uint32_t a2 = __float_as_uint(Ps[(wm + grp)     * AP + ks + qd + 4]);
            uint32_t a3 = __float_as_uint(Ps[(wm + grp + 8) * AP + ks + qd + 4]);
#pragma unroll
            for (int nt = 0; nt < 4; nt++) {
                const int nv = wn + nt * 8 + grp;
                uint32_t b0 = __float_as_uint(Vs[(ks + qd)     * AP + nv]);
                uint32_t b1 = __float_as_uint(Vs[(ks + qd + 4) * AP + nv]);
                mma8(zacc[nt], a0, a1, a2, a3, b0, b1);
            }
        }
    }

    // ---- final row sums across quad + the two n-half warps ----
    la += __shfl_xor_sync(0xffffffffu, la, 1);
    la += __shfl_xor_sync(0xffffffffu, la, 2);
    lb += __shfl_xor_sync(0xffffffffu, lb, 1);
    lb += __shfl_xor_sync(0xffffffffu, lb, 2);
    __syncthreads();
    float* red = Kh_s;   // reuse: [2][64]
    if (qd == 0) {
        red[(w & 1) * 64 + wm + grp]     = la;
        red[(w & 1) * 64 + wm + grp + 8] = lb;
    }
    __syncthreads();
    const float lA = red[wm + grp]     + red[64 + wm + grp];
    const float lB = red[wm + grp + 8] + red[64 + wm + grp + 8];
    if ((w & 1) == 0 && qd == 0) {
        Lsum[h * S_LEN + iA] = lA;
        Lsum[h * S_LEN + iB] = lB;
    }
    const float liA = 1.0f / lA;
    const float liB = 1.0f / lB;

    // ---- write z/l into concat layout Z[s][h*64+v] ----
#pragma unroll
    for (int nt = 0; nt < 4; nt++) {
        const int v0 = h * D_HEAD + wn + nt * 8 + 2 * qd;
        *(float2*)&Z[(size_t)iA * D_MODEL + v0] = make_float2(zacc[nt][0] * liA, zacc[nt][1] * liA);
        *(float2*)&Z[(size_t)iB * D_MODEL + v0] = make_float2(zacc[nt][2] * liB, zacc[nt][3] * liB);
    }
}

// ---- SA rescale: one block per row; scale lower part, zero upper ----
__global__ __launch_bounds__(256) void sa_rescale(
    float* __restrict__ SA, const float* __restrict__ Lsum)
{
    const int row = blockIdx.x;          // h*2048 + i
    const int i   = row & (S_LEN - 1);
    const float linv = 1.0f / Lsum[row];
    float4* p = (float4*)(SA + (size_t)row * S_LEN);
    const int t = threadIdx.x;
#pragma unroll
    for (int rep = 0; rep < 2; rep++) {
        const int v  = t + rep * 256;    // float4 index, 512 total
        const int c0 = v * 4;
        if (c0 + 3 <= i) {
            float4 x = p[v];
            x.x *= linv; x.y *= linv; x.z *= linv; x.w *= linv;
            p[v] = x;
        } else if (c0 > i) {
            p[v] = make_float4(0.f, 0.f, 0.f, 0.f);
        } else {
            float4 x = p[v];
            x.x = (c0     <= i) ? x.x * linv : 0.f;
            x.y = (c0 + 1 <= i) ? x.y * linv : 0.f;
            x.z = (c0 + 2 <= i) ? x.z * linv : 0.f;
            x.w = (c0 + 3 <= i) ? x.w * linv : 0.f;
            p[v] = x;
        }
    }
}

// =================================================================
extern "C" void kernel_launch(void* const* d_in, const int* in_sizes, int n_in,
                              void* d_out, int out_size)
{
    const float* X   = (const float*)d_in[0];
    const float* WQ  = (const float*)d_in[1];
    const float* WK  = (const float*)d_in[2];
    const float* WV  = (const float*)d_in[3];
    const float* WOw = (const float*)d_in[4];
    const float* WOb = (const float*)d_in[5];
    const float* F1w = (const float*)d_in[6];
    const float* F1b = (const float*)d_in[7];
    const float* F2w = (const float*)d_in[8];
    const float* F2b = (const float*)d_in[9];

    float *Qp, *Kp, *Vp, *Zp, *Ap, *Hp, *Lp, *Dp;
    cudaGetSymbolAddress((void**)&Qp, g_Q);
    cudaGetSymbolAddress((void**)&Kp, g_K);
    cudaGetSymbolAddress((void**)&Vp, g_V);
    cudaGetSymbolAddress((void**)&Zp, g_Z);
    cudaGetSymbolAddress((void**)&Ap, g_ATT);
    cudaGetSymbolAddress((void**)&Hp, g_HID);
    cudaGetSymbolAddress((void**)&Lp, g_L);
    cudaGetSymbolAddress((void**)&Dp, g_DUMMY);

    const size_t SA_EL = (size_t)N_HEADS * S_LEN * S_LEN;
    const size_t OV_EL = (size_t)S_LEN * D_MODEL;
    float* out = (float*)d_out;
    float* sa;
    float* ov;
    if ((size_t)out_size >= SA_EL + OV_EL)      { sa = out;     ov = out + SA_EL; }
    else if ((size_t)out_size >= SA_EL)         { sa = out;     ov = Dp; }
    else                                        { sa = nullptr; ov = out; }

    const int attn_smem = 6 * 64 * AP * 4;   // 110592 B
    cudaFuncSetAttribute(attn_tc, cudaFuncAttributeMaxDynamicSharedMemorySize, attn_smem);

    const int smem_ns = 2 * GTILE * 4;
    const int smem_sp = 4 * GTILE * 4;
    cudaFuncSetAttribute(gemm_tc<0,false,false,false,true,true>,
                         cudaFuncAttributeMaxDynamicSharedMemorySize, smem_sp);

    dim3 blk(256);

    gemm_tc<0,false,false,false,true,true ><<<dim3(8, 16), blk, smem_sp>>>(X, WQ, nullptr, nullptr, Qp, S_LEN, D_MODEL, D_MODEL);
    gemm_tc<0,false,false,false,true,true ><<<dim3(8, 16), blk, smem_sp>>>(X, WK, nullptr, nullptr, Kp, S_LEN, D_MODEL, D_MODEL);
    gemm_tc<0,false,false,false,true,false><<<dim3(8, 16), blk, smem_ns>>>(X, WV, nullptr, nullptr, Vp, S_LEN, D_MODEL, D_MODEL);

    attn_tc<<<dim3(S_LEN / 64, N_HEADS), blk, attn_smem>>>(Qp, Kp, Vp, sa, Zp, Lp);
    if (sa)
        sa_rescale<<<dim3(N_HEADS * S_LEN), blk>>>(sa, Lp);

    gemm_tc<1,true,false,true,false,false><<<dim3(8, 16), blk, smem_ns>>>(Zp, WOw, WOb, X, Ap, S_LEN, D_MODEL, D_MODEL);
    gemm_tc<1,true,true,false,false,false><<<dim3(32, 16), blk, smem_ns>>>(Ap, F1w, F1b, nullptr, Hp, S_LEN, D_FF, D_MODEL);
    gemm_tc<1,true,false,true,false,false><<<dim3(8, 16), blk, smem_ns>>>(Hp, F2w, F2b, Ap, ov, S_LEN, D_MODEL, D_FF);
}

// round 6
// speedup vs baseline: 2.4948x; 1.3515x over previous
#include <cuda_runtime.h>
#include <cstdint>

#define S_LEN   2048
#define D_MODEL 1024
#define N_HEADS 16
#define D_HEAD  64
#define D_FF    4096

// ---------------- scratch (no allocation allowed) ----------------
__device__ float g_Q[N_HEADS * S_LEN * D_HEAD];
__device__ float g_K[N_HEADS * S_LEN * D_HEAD];
__device__ float g_V[N_HEADS * S_LEN * D_HEAD];
__device__ float g_Z[S_LEN * D_MODEL];
__device__ float g_ATT[S_LEN * D_MODEL];
__device__ float g_HID[S_LEN * D_FF];
__device__ float g_L[N_HEADS * S_LEN];
__device__ float g_WVr[D_MODEL * D_MODEL];
__device__ float g_WOr[D_MODEL * D_MODEL];
__device__ float g_F1r[D_FF * D_MODEL];
__device__ float g_F2r[D_MODEL * D_FF];
__device__ float g_DUMMY[S_LEN * D_MODEL];

// =================================================================
// helpers
// =================================================================
__device__ __forceinline__ float to_tf32(float x) {
    float r;
    asm("cvt.rna.tf32.f32 %0, %1;" : "=f"(r) : "f"(x));
    return r;
}

__device__ __forceinline__ void mma8(float* c,
    uint32_t a0, uint32_t a1, uint32_t a2, uint32_t a3,
    uint32_t b0, uint32_t b1)
{
    asm volatile(
        "mma.sync.aligned.m16n8k8.row.col.f32.tf32.tf32.f32 "
        "{%0,%1,%2,%3},{%4,%5,%6,%7},{%8,%9},{%0,%1,%2,%3};"
        : "+f"(c[0]), "+f"(c[1]), "+f"(c[2]), "+f"(c[3])
        : "r"(c ? 0 : 0), "r"(a1), "r"(a2), "r"(a3), "r"(b0), "r"(b1));
}
// (note: a0 passed via the hack above would be wrong; use proper version)
__device__ __forceinline__ void mma8f(float* c,
    float a0, float a1, float a2, float a3, float b0, float b1)
{
    asm volatile(
        "mma.sync.aligned.m16n8k8.row.col.f32.tf32.tf32.f32 "
        "{%0,%1,%2,%3},{%4,%5,%6,%7},{%8,%9},{%0,%1,%2,%3};"
        : "+f"(c[0]), "+f"(c[1]), "+f"(c[2]), "+f"(c[3])
        : "r"(__float_as_uint(a0)), "r"(__float_as_uint(a1)),
          "r"(__float_as_uint(a2)), "r"(__float_as_uint(a3)),
          "r"(__float_as_uint(b0)), "r"(__float_as_uint(b1)));
}

__device__ __forceinline__ void cp16(uint32_t dst_smem, const float* src) {
    asm volatile("cp.async.cg.shared.global [%0], [%1], 16;"
                 :: "r"(dst_smem), "l"(src));
}
#define CP_COMMIT() asm volatile("cp.async.commit_group;")
#define CP_WAIT2()  asm volatile("cp.async.wait_group 2;")

// ---- tf32 pre-round elementwise ----
__global__ __launch_bounds__(256) void round_tf32(
    const float* __restrict__ in, float* __restrict__ out, int n4)
{
    int i = blockIdx.x * 256 + threadIdx.x;
    if (i < n4) {
        float4 v = ((const float4*)in)[i];
        v.x = to_tf32(v.x); v.y = to_tf32(v.y);
        v.z = to_tf32(v.z); v.w = to_tf32(v.w);
        ((float4*)out)[i] = v;
    }
}

// =================================================================
// GEMM v2: 128x128 tile, BK=32, 256 thr (8 warps, 4Mx2N, warp 32x64),
// 3-stage cp.async ring, raw fp32 smem, convert at fragment load.
//   BMODE 0: B per-head [H][K][64] -> smem [k][128+pad]   (QKV)
//   BMODE 1: B [N][K] row-major    -> smem [n][32+pad]    (WO/FF)
//   SPLIT: 2-term tf32 split of both operands (Q,K projections)
//   CVT_A: cvt.rna A fragments (A source is raw fp32)
//   CVT_OUT: round output to tf32 on store
// =================================================================
#define TSZ 4608            // floats per stage per operand (128*36)
#define PA  36
#define PB0 136

template<int BMODE, bool BIAS, bool RELU, bool RESID, bool OUTHEAD,
         bool SPLIT, bool CVT_A, bool CVT_OUT>
__global__ __launch_bounds__(256, 2) void gemm2(
    const float* __restrict__ A, const float* __restrict__ B,
    const float* __restrict__ bias, const float* __restrict__ resid,
    float* __restrict__ C, int M, int N, int K)
{
    extern __shared__ float sm[];
    float* As0 = sm;
    float* Bs0 = sm + 3 * TSZ;

    const int t    = threadIdx.x;
    const int lane = t & 31;
    const int w    = t >> 5;
    const int grp  = lane >> 2;
    const int qd   = lane & 3;
    const int wm   = (w & 3) * 32;
    const int wn   = (w >> 2) * 64;
    const int m0   = blockIdx.y * 128;
    const int n0   = blockIdx.x * 128;

    float acc[2][8][4];
#pragma unroll
    for (int i = 0; i < 2; i++)
#pragma unroll
        for (int j = 0; j < 8; j++)
#pragma unroll
            for (int k = 0; k < 4; k++) acc[i][j][k] = 0.0f;

    const int KT = K >> 5;

    uint32_t sbaseA = (uint32_t)__cvta_generic_to_shared(As0);
    uint32_t sbaseB = (uint32_t)__cvta_generic_to_shared(Bs0);

    // copy issue for k-tile kt into stage s
    auto issue = [&](int kt, int s) {
        const uint32_t Ad = sbaseA + s * TSZ * 4;
        const uint32_t Bd = sbaseB + s * TSZ * 4;
        const int kb = kt * 32;
#pragma unroll
        for (int i = t; i < 1024; i += 256) {
            const int m = i >> 3, c = (i & 7) * 4;
            cp16(Ad + (m * PA + c) * 4, A + (size_t)(m0 + m) * K + kb + c);
        }
        if (BMODE == 1) {
#pragma unroll
            for (int i = t; i < 1024; i += 256) {
                const int n = i >> 3, c = (i & 7) * 4;
                cp16(Bd + (n * PA + c) * 4, B + (size_t)(n0 + n) * K + kb + c);
            }
        } else {
#pragma unroll
            for (int i = t; i < 1024; i += 256) {
                const int k = i >> 5, nq = (i & 31) * 4;
                const int h = (n0 + nq) >> 6, e = (n0 + nq) & 63;
                cp16(Bd + (k * PB0 + nq) * 4, B + ((size_t)h * K + kb + k) * 64 + e);
            }
        }
    };

    issue(0, 0); CP_COMMIT();
    issue(1, 1); CP_COMMIT();
    issue(2, 2); CP_COMMIT();

    for (int kt = 0; kt < KT; kt++) {
        const int s = kt % 3;
        CP_WAIT2();
        __syncthreads();

        const float* Ab = As0 + s * TSZ;
        const float* Bb = Bs0 + s * TSZ;

#pragma unroll
        for (int ks = 0; ks < 32; ks += 8) {
            float ar[2][4];
#pragma unroll
            for (int mt = 0; mt < 2; mt++) {
                const int r = (wm + mt * 16 + grp) * PA;
                ar[mt][0] = Ab[r + ks + qd];
                ar[mt][1] = Ab[r + 8 * PA + ks + qd];
                ar[mt][2] = Ab[r + ks + qd + 4];
                ar[mt][3] = Ab[r + 8 * PA + ks + qd + 4];
            }
            if (SPLIT) {
                float ah[2][4], al[2][4];
#pragma unroll
                for (int mt = 0; mt < 2; mt++)
#pragma unroll
                    for (int x = 0; x < 4; x++) {
                        ah[mt][x] = to_tf32(ar[mt][x]);
                        al[mt][x] = ar[mt][x] - ah[mt][x];
                    }
#pragma unroll
                for (int nt = 0; nt < 8; nt++) {
                    float b0r, b1r;
                    if (BMODE == 1) {
                        const int r = (wn + nt * 8 + grp) * PA;
                        b0r = Bb[r + ks + qd];
                        b1r = Bb[r + ks + qd + 4];
                    } else {
                        const int cn = wn + nt * 8 + grp;
                        b0r = Bb[(ks + qd) * PB0 + cn];
                        b1r = Bb[(ks + qd + 4) * PB0 + cn];
                    }
                    const float bh0 = to_tf32(b0r), bh1 = to_tf32(b1r);
                    const float bl0 = b0r - bh0,   bl1 = b1r - bh1;
#pragma unroll
                    for (int mt = 0; mt < 2; mt++) {
                        mma8f(acc[mt][nt], ah[mt][0], ah[mt][1], ah[mt][2], ah[mt][3], bh0, bh1);
                        mma8f(acc[mt][nt], ah[mt][0], ah[mt][1], ah[mt][2], ah[mt][3], bl0, bl1);
                        mma8f(acc[mt][nt], al[mt][0], al[mt][1], al[mt][2], al[mt][3], bh0, bh1);
                    }
                }
            } else {
                if (CVT_A) {
#pragma unroll
                    for (int mt = 0; mt < 2; mt++)
#pragma unroll
                        for (int x = 0; x < 4; x++) ar[mt][x] = to_tf32(ar[mt][x]);
                }
#pragma unroll
                for (int nt = 0; nt < 8; nt++) {
                    float b0, b1;
                    if (BMODE == 1) {
                        const int r = (wn + nt * 8 + grp) * PA;
                        b0 = Bb[r + ks + qd];
                        b1 = Bb[r + ks + qd + 4];
                    } else {
                        const int cn = wn + nt * 8 + grp;
                        b0 = Bb[(ks + qd) * PB0 + cn];
                        b1 = Bb[(ks + qd + 4) * PB0 + cn];
                    }
#pragma unroll
                    for (int mt = 0; mt < 2; mt++)
                        mma8f(acc[mt][nt], ar[mt][0], ar[mt][1], ar[mt][2], ar[mt][3], b0, b1);
                }
            }
        }
        __syncthreads();
        if (kt + 3 < KT) issue(kt + 3, s);
        CP_COMMIT();
    }

    // ---- epilogue ----
#pragma unroll
    for (int mt = 0; mt < 2; mt++) {
#pragma unroll
        for (int nt = 0; nt < 8; nt++) {
            const int n  = n0 + wn + nt * 8 + 2 * qd;
            float2 v0 = make_float2(acc[mt][nt][0], acc[mt][nt][1]);
            float2 v1 = make_float2(acc[mt][nt][2], acc[mt][nt][3]);
            if (BIAS) {
                float2 bb = *(const float2*)&bias[n];
                v0.x += bb.x; v0.y += bb.y;
                v1.x += bb.x; v1.y += bb.y;
            }
            if (RELU) {
                v0.x = fmaxf(v0.x, 0.f); v0.y = fmaxf(v0.y, 0.f);
                v1.x = fmaxf(v1.x, 0.f); v1.y = fmaxf(v1.y, 0.f);
            }
            const int mA = m0 + wm + mt * 16 + grp;
            const int mB = mA + 8;
            if (RESID) {
                float2 r0 = *(const float2*)&resid[(size_t)mA * N + n];
                float2 r1 = *(const float2*)&resid[(size_t)mB * N + n];
                v0.x += r0.x; v0.y += r0.y;
                v1.x += r1.x; v1.y += r1.y;
            }
            if (CVT_OUT) {
                v0.x = to_tf32(v0.x); v0.y = to_tf32(v0.y);
                v1.x = to_tf32(v1.x); v1.y = to_tf32(v1.y);
            }
            if (OUTHEAD) {
                const int h = n >> 6;
                const int e = n & 63;
                *(float2*)&C[((size_t)h * M + mA) * 64 + e] = v0;
                *(float2*)&C[((size_t)h * M + mB) * 64 + e] = v1;
            } else {
                *(float2*)&C[(size_t)mA * N + n] = v0;
                *(float2*)&C[(size_t)mB * N + n] = v1;
            }
        }
    }
}

// =================================================================
// Tensor-core attention (R4) + heavy-first block order + rounded Z out
// =================================================================
#define AP 72

__global__ __launch_bounds__(256, 2) void attn_tc(
    const float* __restrict__ Q, const float* __restrict__ K,
    const float* __restrict__ V, float* __restrict__ SA,
    float* __restrict__ Z, float* __restrict__ Lsum)
{
    extern __shared__ float sm[];
    float* Qh_s = sm;
    float* Ql_s = sm + 64 * AP;
    float* Kh_s = sm + 2 * 64 * AP;
    float* Kl_s = sm + 3 * 64 * AP;
    float* Vs   = sm + 4 * 64 * AP;
    float* Ps   = sm + 5 * 64 * AP;

    const int t    = threadIdx.x;
    const int lane = t & 31;
    const int w    = t >> 5;
    const int grp  = lane >> 2;
    const int qd   = lane & 3;
    const int wm   = (w >> 1) * 16;
    const int wn   = (w & 1) * 32;
    const int qt   = (int)gridDim.x - 1 - (int)blockIdx.x;   // heavy tiles first
    const int h    = blockIdx.y;
    const int q0   = qt * 64;

    const float slope = exp2f(-0.5f * (float)(h + 1));
    const float* Qg = Q + (size_t)h * S_LEN * D_HEAD;
    const float* Kg = K + (size_t)h * S_LEN * D_HEAD;
    const float* Vg = V + (size_t)h * S_LEN * D_HEAD;

    {
        const int r  = t >> 2;
        const int dq = (t & 3) * 16;
        const float* qp = Qg + (size_t)(q0 + r) * 64 + dq;
        float v[16];
        *(float4*)&v[0]  = *(const float4*)(qp);
        *(float4*)&v[4]  = *(const float4*)(qp + 4);
        *(float4*)&v[8]  = *(const float4*)(qp + 8);
        *(float4*)&v[12] = *(const float4*)(qp + 12);
#pragma unroll
        for (int j = 0; j < 16; j++) {
            float hi = to_tf32(v[j]);
            Qh_s[r * AP + dq + j] = hi;
            Ql_s[r * AP + dq + j] = to_tf32(v[j] - hi);
        }
    }

    float zacc[4][4];
#pragma unroll
    for (int i = 0; i < 4; i++)
#pragma unroll
        for (int j = 0; j < 4; j++) zacc[i][j] = 0.0f;
    float la = 0.0f, lb = 0.0f;

    const int iA = q0 + wm + grp;
    const int iB = iA + 8;

    for (int kt = 0; kt <= qt; kt++) {
        const int k0 = kt * 64;
        __syncthreads();
        {
            const int c  = t >> 2;
            const int dq = (t & 3) * 16;
            const float* kp = Kg + (size_t)(k0 + c) * 64 + dq;
            const float* vp = Vg + (size_t)(k0 + c) * 64 + dq;
            float kv[16], vv[16];
            *(float4*)&kv[0]  = *(const float4*)(kp);
            *(float4*)&kv[4]  = *(const float4*)(kp + 4);
            *(float4*)&kv[8]  = *(const float4*)(kp + 8);
            *(float4*)&kv[12] = *(const float4*)(kp + 12);
            *(float4*)&vv[0]  = *(const float4*)(vp);
            *(float4*)&vv[4]  = *(const float4*)(vp + 4);
            *(float4*)&vv[8]  = *(const float4*)(vp + 8);
            *(float4*)&vv[12] = *(const float4*)(vp + 12);
#pragma unroll
            for (int j = 0; j < 16; j++) {
                float hi = to_tf32(kv[j]);
                Kh_s[c * AP + dq + j] = hi;
                Kl_s[c * AP + dq + j] = to_tf32(kv[j] - hi);
                Vs[c * AP + dq + j]   = to_tf32(vv[j]);
            }
        }
        __syncthreads();

        float sacc[4][4];
#pragma unroll
        for (int i = 0; i < 4; i++)
#pragma unroll
            for (int j = 0; j < 4; j++) sacc[i][j] = 0.0f;

#pragma unroll
        for (int ks = 0; ks < 64; ks += 8) {
            float ah0 = Qh_s[(wm + grp)     * AP + ks + qd];
            float ah1 = Qh_s[(wm + grp + 8) * AP + ks + qd];
            float ah2 = Qh_s[(wm + grp)     * AP + ks + qd + 4];
            float ah3 = Qh_s[(wm + grp + 8) * AP + ks + qd + 4];
            float al0 = Ql_s[(wm + grp)     * AP + ks + qd];
            float al1 = Ql_s[(wm + grp + 8) * AP + ks + qd];
            float al2 = Ql_s[(wm + grp)     * AP + ks + qd + 4];
            float al3 = Ql_s[(wm + grp + 8) * AP + ks + qd + 4];
#pragma unroll
            for (int nt = 0; nt < 4; nt++) {
                const int nc = wn + nt * 8 + grp;
                float bh0 = Kh_s[nc * AP + ks + qd];
                float bh1 = Kh_s[nc * AP + ks + qd + 4];
                float bl0 = Kl_s[nc * AP + ks + qd];
                float bl1 = Kl_s[nc * AP + ks + qd + 4];
                mma8f(sacc[nt], ah0, ah1, ah2, ah3, bh0, bh1);
                mma8f(sacc[nt], ah0, ah1, ah2, ah3, bl0, bl1);
                mma8f(sacc[nt], al0, al1, al2, al3, bh0, bh1);
            }
        }

        const bool diag = (kt == qt);
#pragma unroll
        for (int nt = 0; nt < 4; nt++) {
            const int j0 = k0 + wn + nt * 8 + 2 * qd;
            float p0 = __expf(sacc[nt][0] * 0.125f - (float)(iA - j0) * slope);
            float p1 = __expf(sacc[nt][1] * 0.125f - (float)(iA - j0 - 1) * slope);
            float p2 = __expf(sacc[nt][2] * 0.125f - (float)(iB - j0) * slope);
            float p3 = __expf(sacc[nt][3] * 0.125f - (float)(iB - j0 - 1) * slope);
            if (diag) {
                if (j0     > iA) p0 = 0.0f;
                if (j0 + 1 > iA) p1 = 0.0f;
                if (j0     > iB) p2 = 0.0f;
                if (j0 + 1 > iB) p3 = 0.0f;
            }
            la += p0 + p1;
            lb += p2 + p3;
            if (SA) {
                *(float2*)&SA[((size_t)h * S_LEN + iA) * S_LEN + j0] = make_float2(p0, p1);
                *(float2*)&SA[((size_t)h * S_LEN + iB) * S_LEN + j0] = make_float2(p2, p3);
            }
            const int pc = wn + nt * 8 + 2 * qd;
            *(float2*)&Ps[(wm + grp)     * AP + pc] = make_float2(to_tf32(p0), to_tf32(p1));
            *(float2*)&Ps[(wm + grp + 8) * AP + pc] = make_float2(to_tf32(p2), to_tf32(p3));
        }
        __syncthreads();

#pragma unroll
        for (int ks = 0; ks < 64; ks += 8) {
            float a0 = Ps[(wm + grp)     * AP + ks + qd];
            float a1 = Ps[(wm + grp + 8) * AP + ks + qd];
            float a2 = Ps[(wm + grp)     * AP + ks + qd + 4];
            float a3 = Ps[(wm + grp + 8) * AP + ks + qd + 4];
#pragma unroll
            for (int nt = 0; nt < 4; nt++) {
                const int nv = wn + nt * 8 + grp;
                float b0 = Vs[(ks + qd)     * AP + nv];
                float b1 = Vs[(ks + qd + 4) * AP + nv];
                mma8f(zacc[nt], a0, a1, a2, a3, b0, b1);
            }
        }
    }

    la += __shfl_xor_sync(0xffffffffu, la, 1);
    la += __shfl_xor_sync(0xffffffffu, la, 2);
    lb += __shfl_xor_sync(0xffffffffu, lb, 1);
    lb += __shfl_xor_sync(0xffffffffu, lb, 2);
    __syncthreads();
    float* red = Kh_s;
    if (qd == 0) {
        red[(w & 1) * 64 + wm + grp]     = la;
        red[(w & 1) * 64 + wm + grp + 8] = lb;
    }
    __syncthreads();
    const float lA = red[wm + grp]     + red[64 + wm + grp];
    const float lB = red[wm + grp + 8] + red[64 + wm + grp + 8];
    if ((w & 1) == 0 && qd == 0) {
        Lsum[h * S_LEN + iA] = lA;
        Lsum[h * S_LEN + iB] = lB;
    }
    const float liA = 1.0f / lA;
    const float liB = 1.0f / lB;

#pragma unroll
    for (int nt = 0; nt < 4; nt++) {
        const int v0 = h * D_HEAD + wn + nt * 8 + 2 * qd;
        *(float2*)&Z[(size_t)iA * D_MODEL + v0] =
            make_float2(to_tf32(zacc[nt][0] * liA), to_tf32(zacc[nt][1] * liA));
        *(float2*)&Z[(size_t)iB * D_MODEL + v0] =
            make_float2(to_tf32(zacc[nt][2] * liB), to_tf32(zacc[nt][3] * liB));
    }
}

// ---- SA rescale ----
__global__ __launch_bounds__(256) void sa_rescale(
    float* __restrict__ SA, const float* __restrict__ Lsum)
{
    const int row = blockIdx.x;
    const int i   = row & (S_LEN - 1);
    const float linv = 1.0f / Lsum[row];
    float4* p = (float4*)(SA + (size_t)row * S_LEN);
    const int t = threadIdx.x;
#pragma unroll
    for (int rep = 0; rep < 2; rep++) {
        const int v  = t + rep * 256;
        const int c0 = v * 4;
        if (c0 + 3 <= i) {
            float4 x = p[v];
            x.x *= linv; x.y *= linv; x.z *= linv; x.w *= linv;
            p[v] = x;
        } else if (c0 > i) {
            p[v] = make_float4(0.f, 0.f, 0.f, 0.f);
        } else {
            float4 x = p[v];
            x.x = (c0     <= i) ? x.x * linv : 0.f;
            x.y = (c0 + 1 <= i) ? x.y * linv : 0.f;
            x.z = (c0 + 2 <= i) ? x.z * linv : 0.f;
            x.w = (c0 + 3 <= i) ? x.w * linv : 0.f;
            p[v] = x;
        }
    }
}

// =================================================================
extern "C" void kernel_launch(void* const* d_in, const int* in_sizes, int n_in,
                              void* d_out, int out_size)
{
    const float* X   = (const float*)d_in[0];
    const float* WQ  = (const float*)d_in[1];
    const float* WK  = (const float*)d_in[2];
    const float* WV  = (const float*)d_in[3];
    const float* WOw = (const float*)d_in[4];
    const float* WOb = (const float*)d_in[5];
    const float* F1w = (const float*)d_in[6];
    const float* F1b = (const float*)d_in[7];
    const float* F2w = (const float*)d_in[8];
    const float* F2b = (const float*)d_in[9];

    float *Qp, *Kp, *Vp, *Zp, *Ap, *Hp, *Lp, *Dp, *WVr, *WOr, *F1r, *F2r;
    cudaGetSymbolAddress((void**)&Qp, g_Q);
    cudaGetSymbolAddress((void**)&Kp, g_K);
    cudaGetSymbolAddress((void**)&Vp, g_V);
    cudaGetSymbolAddress((void**)&Zp, g_Z);
    cudaGetSymbolAddress((void**)&Ap, g_ATT);
    cudaGetSymbolAddress((void**)&Hp, g_HID);
    cudaGetSymbolAddress((void**)&Lp, g_L);
    cudaGetSymbolAddress((void**)&Dp, g_DUMMY);
    cudaGetSymbolAddress((void**)&WVr, g_WVr);
    cudaGetSymbolAddress((void**)&WOr, g_WOr);
    cudaGetSymbolAddress((void**)&F1r, g_F1r);
    cudaGetSymbolAddress((void**)&F2r, g_F2r);

    const size_t SA_EL = (size_t)N_HEADS * S_LEN * S_LEN;
    const size_t OV_EL = (size_t)S_LEN * D_MODEL;
    float* out = (float*)d_out;
    float* sa;
    float* ov;
    if ((size_t)out_size >= SA_EL + OV_EL)      { sa = out;     ov = out + SA_EL; }
    else if ((size_t)out_size >= SA_EL)         { sa = out;     ov = Dp; }
    else                                        { sa = nullptr; ov = out; }

    const int attn_smem = 6 * 64 * AP * 4;     // 110592
    const int gemm_smem = 6 * TSZ * 4;         // 110592
    cudaFuncSetAttribute(attn_tc, cudaFuncAttributeMaxDynamicSharedMemorySize, attn_smem);
    cudaFuncSetAttribute(gemm2<0,false,false,false,true,true ,false,false>,
                         cudaFuncAttributeMaxDynamicSharedMemorySize, gemm_smem);
    cudaFuncSetAttribute(gemm2<0,false,false,false,true,false,true ,false>,
                         cudaFuncAttributeMaxDynamicSharedMemorySize, gemm_smem);
    cudaFuncSetAttribute(gemm2<1,true ,false,true ,false,false,false,false>,
                         cudaFuncAttributeMaxDynamicSharedMemorySize, gemm_smem);
    cudaFuncSetAttribute(gemm2<1,true ,true ,false,false,false,true ,true >,
                         cudaFuncAttributeMaxDynamicSharedMemorySize, gemm_smem);

    dim3 blk(256);

    // pre-round weights for the non-split GEMMs (B operands)
    round_tf32<<<dim3((D_MODEL*D_MODEL/4 + 255)/256), blk>>>(WV,  WVr, D_MODEL*D_MODEL/4);
    round_tf32<<<dim3((D_MODEL*D_MODEL/4 + 255)/256), blk>>>(WOw, WOr, D_MODEL*D_MODEL/4);
    round_tf32<<<dim3((D_FF*D_MODEL/4   + 255)/256), blk>>>(F1w, F1r, D_FF*D_MODEL/4);
    round_tf32<<<dim3((D_MODEL*D_FF/4   + 255)/256), blk>>>(F2w, F2r, D_MODEL*D_FF/4);

    // Q,K: split tf32; V: plain (A=X cvt at load, B pre-rounded)
    gemm2<0,false,false,false,true,true ,false,false><<<dim3(8, 16), blk, gemm_smem>>>(X, WQ,  nullptr, nullptr, Qp, S_LEN, D_MODEL, D_MODEL);
    gemm2<0,false,false,false,true,true ,false,false><<<dim3(8, 16), blk, gemm_smem>>>(X, WK,  nullptr, nullptr, Kp, S_LEN, D_MODEL, D_MODEL);
    gemm2<0,false,false,false,true,false,true ,false><<<dim3(8, 16), blk, gemm_smem>>>(X, WVr, nullptr, nullptr, Vp, S_LEN, D_MODEL, D_MODEL);

    attn_tc<<<dim3(S_LEN / 64, N_HEADS), blk, attn_smem>>>(Qp, Kp, Vp, sa, Zp, Lp);
    if (sa)
        sa_rescale<<<dim3(N_HEADS * S_LEN), blk>>>(sa, Lp);

    // attouts = X + Z @ WO^T + b   (Z pre-rounded at write)
    gemm2<1,true ,false,true ,false,false,false,false><<<dim3(8, 16), blk, gemm_smem>>>(Zp, WOr, WOb, X, Ap, S_LEN, D_MODEL, D_MODEL);
    // hidden = round(relu(attouts @ FF1^T + b1))   (A cvt at load)
    gemm2<1,true ,true ,false,false,false,true ,true ><<<dim3(32, 16), blk, gemm_smem>>>(Ap, F1r, F1b, nullptr, Hp, S_LEN, D_FF, D_MODEL);
    // out = attouts + hidden @ FF2^T + b2   (hidden pre-rounded)
    gemm2<1,true ,false,true ,false,false,false,false><<<dim3(8, 16), blk, gemm_smem>>>(Hp, F2r, F2b, Ap, ov, S_LEN, D_MODEL, D_FF);
}

// round 7
// speedup vs baseline: 3.0664x; 1.2291x over previous
#include <cuda_runtime.h>
#include <cstdint>

#define S_LEN   2048
#define D_MODEL 1024
#define N_HEADS 16
#define D_HEAD  64
#define D_FF    4096

// ---------------- scratch (no allocation allowed) ----------------
__device__ float    g_V[N_HEADS * S_LEN * D_HEAD];
__device__ float    g_Z[S_LEN * D_MODEL];
__device__ float    g_ATT[S_LEN * D_MODEL];
__device__ float    g_HID[S_LEN * D_FF];
__device__ float    g_L[N_HEADS * S_LEN];
__device__ float    g_DUMMY[S_LEN * D_MODEL];
// packed bf16x2 (hi/lo) operands
__device__ uint32_t g_Xh2[S_LEN * (D_MODEL / 2)];
__device__ uint32_t g_Xl2[S_LEN * (D_MODEL / 2)];
__device__ uint32_t g_WQh2[N_HEADS * D_HEAD * (D_MODEL / 2)];
__device__ uint32_t g_WQl2[N_HEADS * D_HEAD * (D_MODEL / 2)];
__device__ uint32_t g_WKh2[N_HEADS * D_HEAD * (D_MODEL / 2)];
__device__ uint32_t g_WKl2[N_HEADS * D_HEAD * (D_MODEL / 2)];
__device__ uint32_t g_Qh2[N_HEADS * S_LEN * (D_HEAD / 2)];
__device__ uint32_t g_Ql2[N_HEADS * S_LEN * (D_HEAD / 2)];
__device__ uint32_t g_Kh2[N_HEADS * S_LEN * (D_HEAD / 2)];
__device__ uint32_t g_Kl2[N_HEADS * S_LEN * (D_HEAD / 2)];

// =================================================================
// helpers
// =================================================================
__device__ __forceinline__ float to_tf32(float x) {
    float r;
    asm("cvt.rna.tf32.f32 %0, %1;" : "=f"(r) : "f"(x));
    return r;
}

__device__ __forceinline__ void mma8f(float* c,
    float a0, float a1, float a2, float a3, float b0, float b1)
{
    asm volatile(
        "mma.sync.aligned.m16n8k8.row.col.f32.tf32.tf32.f32 "
        "{%0,%1,%2,%3},{%4,%5,%6,%7},{%8,%9},{%0,%1,%2,%3};"
        : "+f"(c[0]), "+f"(c[1]), "+f"(c[2]), "+f"(c[3])
        : "r"(__float_as_uint(a0)), "r"(__float_as_uint(a1)),
          "r"(__float_as_uint(a2)), "r"(__float_as_uint(a3)),
          "r"(__float_as_uint(b0)), "r"(__float_as_uint(b1)));
}

__device__ __forceinline__ void mma16(float* c,
    uint32_t a0, uint32_t a1, uint32_t a2, uint32_t a3,
    uint32_t b0, uint32_t b1)
{
    asm volatile(
        "mma.sync.aligned.m16n8k16.row.col.f32.bf16.bf16.f32 "
        "{%0,%1,%2,%3},{%4,%5,%6,%7},{%8,%9},{%0,%1,%2,%3};"
        : "+f"(c[0]), "+f"(c[1]), "+f"(c[2]), "+f"(c[3])
        : "r"(a0), "r"(a1), "r"(a2), "r"(a3), "r"(b0), "r"(b1));
}

// pack (x0,x1) -> bf16x2 hi (low half = x0) and lo (residual)
__device__ __forceinline__ void pack2(float x0, float x1, uint32_t& hi, uint32_t& lo) {
    asm("cvt.rn.bf16x2.f32 %0, %1, %2;" : "=r"(hi) : "f"(x1), "f"(x0));
    float f0 = __uint_as_float(hi << 16);
    float f1 = __uint_as_float(hi & 0xffff0000u);
    asm("cvt.rn.bf16x2.f32 %0, %1, %2;" : "=r"(lo) : "f"(x1 - f1), "f"(x0 - f0));
}

__device__ __forceinline__ void cp16(uint32_t dst_smem, const void* src) {
    asm volatile("cp.async.cg.shared.global [%0], [%1], 16;"
                 :: "r"(dst_smem), "l"(src));
}
#define CP_COMMIT() asm volatile("cp.async.commit_group;")
#define CP_WAIT1()  asm volatile("cp.async.wait_group 1;")
#define CP_WAIT2()  asm volatile("cp.async.wait_group 2;")

// =================================================================
// prep: pack X and per-head weights into bf16x2 hi/lo
// =================================================================
__global__ __launch_bounds__(256) void pack_x(
    const float* __restrict__ in, uint32_t* __restrict__ oh,
    uint32_t* __restrict__ ol, int n4)
{
    int i = blockIdx.x * 256 + threadIdx.x;
    if (i < n4) {
        float4 v = ((const float4*)in)[i];
        uint32_t h0, l0, h1, l1;
        pack2(v.x, v.y, h0, l0);
        pack2(v.z, v.w, h1, l1);
        ((uint2*)oh)[i] = make_uint2(h0, h1);
        ((uint2*)ol)[i] = make_uint2(l0, l1);
    }
}

// W [H][K][64] -> packed [h*64+e][K/2]
__global__ __launch_bounds__(256) void pack_w(
    const float* __restrict__ in, uint32_t* __restrict__ oh,
    uint32_t* __restrict__ ol)
{
    int i  = blockIdx.x * 256 + threadIdx.x;   // 16*64*512
    int e  = i & 63;
    int kp = (i >> 6) & 511;
    int h  = i >> 15;
    float x0 = in[((size_t)h * 1024 + 2 * kp)     * 64 + e];
    float x1 = in[((size_t)h * 1024 + 2 * kp + 1) * 64 + e];
    uint32_t hi, lo;
    pack2(x0, x1, hi, lo);
    oh[((size_t)h * 64 + e) * 512 + kp] = hi;
    ol[((size_t)h * 64 + e) * 512 + kp] = lo;
}

// =================================================================
// Q/K projection: split-bf16 GEMM. 128x128 tile, BK=32 (16 u32 pairs),
// 2-stage cp.async. Output packed bf16x2 hi/lo in head layout [h][s][32].
// =================================================================
#define QKP 20      // padded row stride in u32
#define QSTG (128 * QKP)

__global__ __launch_bounds__(256, 2) void gemm_qk(
    const uint32_t* __restrict__ Ah2g, const uint32_t* __restrict__ Al2g,
    const uint32_t* __restrict__ Bh2g, const uint32_t* __restrict__ Bl2g,
    uint32_t* __restrict__ Oh, uint32_t* __restrict__ Ol)
{
    extern __shared__ float sm[];
    uint32_t* smu = (uint32_t*)sm;

    const int t    = threadIdx.x;
    const int lane = t & 31;
    const int w    = t >> 5;
    const int grp  = lane >> 2;
    const int qd   = lane & 3;
    const int wm   = (w & 3) * 32;
    const int wn   = (w >> 2) * 64;
    const int m0   = blockIdx.y * 128;
    const int n0   = blockIdx.x * 128;

    float acc[2][8][4];
#pragma unroll
    for (int i = 0; i < 2; i++)
#pragma unroll
        for (int j = 0; j < 8; j++)
#pragma unroll
            for (int k = 0; k < 4; k++) acc[i][j][k] = 0.0f;

    const uint32_t sb = (uint32_t)__cvta_generic_to_shared(smu);

    auto issue = [&](int kt, int s) {
        const int kb = kt * 16;
        const uint32_t base = sb + (uint32_t)s * 4 * QSTG * 4;
#pragma unroll
        for (int i = t; i < 512; i += 256) {
            const int r = i >> 2, c = (i & 3) * 4;
            const uint32_t d = base + (r * QKP + c) * 4;
            cp16(d,                Ah2g + (size_t)(m0 + r) * 512 + kb + c);
            cp16(d + QSTG * 4,     Al2g + (size_t)(m0 + r) * 512 + kb + c);
            const int n = n0 + r;
            const size_t wo = ((size_t)(n >> 6) * 64 + (n & 63)) * 512 + kb + c;
            cp16(d + 2 * QSTG * 4, Bh2g + wo);
            cp16(d + 3 * QSTG * 4, Bl2g + wo);
        }
    };

    issue(0, 0); CP_COMMIT();
    issue(1, 1); CP_COMMIT();

    for (int kt = 0; kt < 32; kt++) {
        CP_WAIT1();
        __syncthreads();
        const uint32_t* Ah = smu + (kt & 1) * 4 * QSTG;
        const uint32_t* Al = Ah + QSTG;
        const uint32_t* Bh = Ah + 2 * QSTG;
        const uint32_t* Bl = Ah + 3 * QSTG;

#pragma unroll
        for (int ks2 = 0; ks2 < 16; ks2 += 8) {
            uint32_t ah[2][4], al[2][4];
#pragma unroll
            for (int mt = 0; mt < 2; mt++) {
                const int r = (wm + mt * 16 + grp) * QKP;
                ah[mt][0] = Ah[r + ks2 + qd];
                ah[mt][1] = Ah[r + 8 * QKP + ks2 + qd];
                ah[mt][2] = Ah[r + ks2 + qd + 4];
                ah[mt][3] = Ah[r + 8 * QKP + ks2 + qd + 4];
                al[mt][0] = Al[r + ks2 + qd];
                al[mt][1] = Al[r + 8 * QKP + ks2 + qd];
                al[mt][2] = Al[r + ks2 + qd + 4];
                al[mt][3] = Al[r + 8 * QKP + ks2 + qd + 4];
            }
#pragma unroll
            for (int nt = 0; nt < 8; nt++) {
                const int rb = (wn + nt * 8 + grp) * QKP;
                uint32_t bh0 = Bh[rb + ks2 + qd];
                uint32_t bh1 = Bh[rb + ks2 + qd + 4];
                uint32_t bl0 = Bl[rb + ks2 + qd];
                uint32_t bl1 = Bl[rb + ks2 + qd + 4];
#pragma unroll
                for (int mt = 0; mt < 2; mt++) {
                    mma16(acc[mt][nt], ah[mt][0], ah[mt][1], ah[mt][2], ah[mt][3], bh0, bh1);
                    mma16(acc[mt][nt], ah[mt][0], ah[mt][1], ah[mt][2], ah[mt][3], bl0, bl1);
                    mma16(acc[mt][nt], al[mt][0], al[mt][1], al[mt][2], al[mt][3], bh0, bh1);
                }
            }
        }
        __syncthreads();
        if (kt + 2 < 32) issue(kt + 2, kt & 1);
        CP_COMMIT();
    }

    // epilogue: pack d-pairs (cols 2qd,2qd+1) into bf16x2 hi/lo head layout
#pragma unroll
    for (int mt = 0; mt < 2; mt++) {
#pragma unroll
        for (int nt = 0; nt < 8; nt++) {
            const int n  = n0 + wn + nt * 8 + 2 * qd;
            const int h  = n >> 6;
            const int dp = (n & 63) >> 1;
            const int mA = blockIdx.y * 128 + wm + mt * 16 + grp;
            const int mB = mA + 8;
            uint32_t hi, lo;
            pack2(acc[mt][nt][0], acc[mt][nt][1], hi, lo);
            Oh[((size_t)h * S_LEN + mA) * 32 + dp] = hi;
            Ol[((size_t)h * S_LEN + mA) * 32 + dp] = lo;
            pack2(acc[mt][nt][2], acc[mt][nt][3], hi, lo);
            Oh[((size_t)h * S_LEN + mB) * 32 + dp] = hi;
            Ol[((size_t)h * S_LEN + mB) * 32 + dp] = lo;
        }
    }
}

// =================================================================
// Plain tf32 GEMM (V/WO/FF): 3-stage cp.async, convert at frag load.
// =================================================================
#define TSZ 4608
#define PA  36
#define PB0 136

template<int BMODE, bool BIAS, bool RELU, bool RESID, bool OUTHEAD,
         bool CVT_A, bool CVT_B, bool CVT_OUT>
__global__ __launch_bounds__(256, 2) void gemm2(
    const float* __restrict__ A, const float* __restrict__ B,
    const float* __restrict__ bias, const float* __restrict__ resid,
    float* __restrict__ C, int M, int N, int K)
{
    extern __shared__ float sm[];
    float* As0 = sm;
    float* Bs0 = sm + 3 * TSZ;

    const int t    = threadIdx.x;
    const int lane = t & 31;
    const int w    = t >> 5;
    const int grp  = lane >> 2;
    const int qd   = lane & 3;
    const int wm   = (w & 3) * 32;
    const int wn   = (w >> 2) * 64;
    const int m0   = blockIdx.y * 128;
    const int n0   = blockIdx.x * 128;

    float acc[2][8][4];
#pragma unroll
    for (int i = 0; i < 2; i++)
#pragma unroll
        for (int j = 0; j < 8; j++)
#pragma unroll
            for (int k = 0; k < 4; k++) acc[i][j][k] = 0.0f;

    const int KT = K >> 5;
    uint32_t sbaseA = (uint32_t)__cvta_generic_to_shared(As0);
    uint32_t sbaseB = (uint32_t)__cvta_generic_to_shared(Bs0);

    auto issue = [&](int kt, int s) {
        const uint32_t Ad = sbaseA + s * TSZ * 4;
        const uint32_t Bd = sbaseB + s * TSZ * 4;
        const int kb = kt * 32;
#pragma unroll
        for (int i = t; i < 1024; i += 256) {
            const int m = i >> 3, c = (i & 7) * 4;
            cp16(Ad + (m * PA + c) * 4, A + (size_t)(m0 + m) * K + kb + c);
        }
        if (BMODE == 1) {
#pragma unroll
            for (int i = t; i < 1024; i += 256) {
                const int n = i >> 3, c = (i & 7) * 4;
                cp16(Bd + (n * PA + c) * 4, B + (size_t)(n0 + n) * K + kb + c);
            }
        } else {
#pragma unroll
            for (int i = t; i < 1024; i += 256) {
                const int k = i >> 5, nq = (i & 31) * 4;
                const int h = (n0 + nq) >> 6, e = (n0 + nq) & 63;
                cp16(Bd + (k * PB0 + nq) * 4, B + ((size_t)h * K + kb + k) * 64 + e);
            }
        }
    };

    issue(0, 0); CP_COMMIT();
    issue(1, 1); CP_COMMIT();
    issue(2, 2); CP_COMMIT();

    for (int kt = 0; kt < KT; kt++) {
        const int s = kt % 3;
        CP_WAIT2();
        __syncthreads();
        const float* Ab = As0 + s * TSZ;
        const float* Bb = Bs0 + s * TSZ;

#pragma unroll
        for (int ks = 0; ks < 32; ks += 8) {
            float ar[2][4];
#pragma unroll
            for (int mt = 0; mt < 2; mt++) {
                const int r = (wm + mt * 16 + grp) * PA;
                ar[mt][0] = Ab[r + ks + qd];
                ar[mt][1] = Ab[r + 8 * PA + ks + qd];
                ar[mt][2] = Ab[r + ks + qd + 4];
                ar[mt][3] = Ab[r + 8 * PA + ks + qd + 4];
            }
            if (CVT_A) {
#pragma unroll
                for (int mt = 0; mt < 2; mt++)
#pragma unroll
                    for (int x = 0; x < 4; x++) ar[mt][x] = to_tf32(ar[mt][x]);
            }
#pragma unroll
            for (int nt = 0; nt < 8; nt++) {
                float b0, b1;
                if (BMODE == 1) {
                    const int r = (wn + nt * 8 + grp) * PA;
                    b0 = Bb[r + ks + qd];
                    b1 = Bb[r + ks + qd + 4];
                } else {
                    const int cn = wn + nt * 8 + grp;
                    b0 = Bb[(ks + qd) * PB0 + cn];
                    b1 = Bb[(ks + qd + 4) * PB0 + cn];
                }
                if (CVT_B) { b0 = to_tf32(b0); b1 = to_tf32(b1); }
#pragma unroll
                for (int mt = 0; mt < 2; mt++)
                    mma8f(acc[mt][nt], ar[mt][0], ar[mt][1], ar[mt][2], ar[mt][3], b0, b1);
            }
        }
        __syncthreads();
        if (kt + 3 < KT) issue(kt + 3, s);
        CP_COMMIT();
    }

#pragma unroll
    for (int mt = 0; mt < 2; mt++) {
#pragma unroll
        for (int nt = 0; nt < 8; nt++) {
            const int n  = n0 + wn + nt * 8 + 2 * qd;
            float2 v0 = make_float2(acc[mt][nt][0], acc[mt][nt][1]);
            float2 v1 = make_float2(acc[mt][nt][2], acc[mt][nt][3]);
            if (BIAS) {
                float2 bb = *(const float2*)&bias[n];
                v0.x += bb.x; v0.y += bb.y;
                v1.x += bb.x; v1.y += bb.y;
            }
            if (RELU) {
                v0.x = fmaxf(v0.x, 0.f); v0.y = fmaxf(v0.y, 0.f);
                v1.x = fmaxf(v1.x, 0.f); v1.y = fmaxf(v1.y, 0.f);
            }
            const int mA = m0 + wm + mt * 16 + grp;
            const int mB = mA + 8;
            if (RESID) {
                float2 r0 = *(const float2*)&resid[(size_t)mA * N + n];
                float2 r1 = *(const float2*)&resid[(size_t)mB * N + n];
                v0.x += r0.x; v0.y += r0.y;
                v1.x += r1.x; v1.y += r1.y;
            }
            if (CVT_OUT) {
                v0.x = to_tf32(v0.x); v0.y = to_tf32(v0.y);
                v1.x = to_tf32(v1.x); v1.y = to_tf32(v1.y);
            }
            if (OUTHEAD) {
                const int h = n >> 6;
                const int e = n & 63;
                *(float2*)&C[((size_t)h * M + mA) * 64 + e] = v0;
                *(float2*)&C[((size_t)h * M + mB) * 64 + e] = v1;
            } else {
                *(float2*)&C[(size_t)mA * N + n] = v0;
                *(float2*)&C[(size_t)mB * N + n] = v1;
            }
        }
    }
}

// =================================================================
// Attention: scores via split-bf16 mma (Q/K pre-packed), z via tf32.
// =================================================================
#define AP  72      // float stride for Vs/Ps
#define KP2 36      // u32 stride for packed Q/K tiles
#define QTILE (64 * KP2)

__global__ __launch_bounds__(256, 2) void attn_tc(
    const uint32_t* __restrict__ Qh2, const uint32_t* __restrict__ Ql2,
    const uint32_t* __restrict__ Kh2, const uint32_t* __restrict__ Kl2,
    const float* __restrict__ V, float* __restrict__ SA,
    float* __restrict__ Z, float* __restrict__ Lsum)
{
    extern __shared__ float sm[];
    uint32_t* Qh_s = (uint32_t*)sm;
    uint32_t* Ql_s = Qh_s + QTILE;
    uint32_t* Kh_s = Qh_s + 2 * QTILE;
    uint32_t* Kl_s = Qh_s + 3 * QTILE;
    float*    Vs   = sm + 4 * QTILE;
    float*    Ps   = Vs + 64 * AP;

    const int t    = threadIdx.x;
    const int lane = t & 31;
    const int w    = t >> 5;
    const int grp  = lane >> 2;
    const int qd   = lane & 3;
    const int wm   = (w >> 1) * 16;
    const int wn   = (w & 1) * 32;
    const int qt   = (int)gridDim.x - 1 - (int)blockIdx.x;   // heavy first
    const int h    = blockIdx.y;
    const int q0   = qt * 64;

    const float slope = exp2f(-0.5f * (float)(h + 1));
    const float* Vg = V + (size_t)h * S_LEN * D_HEAD;
    const uint32_t* Qhg = Qh2 + (size_t)h * S_LEN * 32;
    const uint32_t* Qlg = Ql2 + (size_t)h * S_LEN * 32;
    const uint32_t* Khg = Kh2 + (size_t)h * S_LEN * 32;
    const uint32_t* Klg = Kl2 + (size_t)h * S_LEN * 32;

    // load packed Q tile
    {
        const int r  = t >> 2;
        const int c8 = (t & 3) * 8;
        *(uint4*)&Qh_s[r * KP2 + c8]     = *(const uint4*)(Qhg + (size_t)(q0 + r) * 32 + c8);
        *(uint4*)&Qh_s[r * KP2 + c8 + 4] = *(const uint4*)(Qhg + (size_t)(q0 + r) * 32 + c8 + 4);
        *(uint4*)&Ql_s[r * KP2 + c8]     = *(const uint4*)(Qlg + (size_t)(q0 + r) * 32 + c8);
        *(uint4*)&Ql_s[r * KP2 + c8 + 4] = *(const uint4*)(Qlg + (size_t)(q0 + r) * 32 + c8 + 4);
    }

    float zacc[4][4];
#pragma unroll
    for (int i = 0; i < 4; i++)
#pragma unroll
        for (int j = 0; j < 4; j++) zacc[i][j] = 0.0f;
    float la = 0.0f, lb = 0.0f;

    const int iA = q0 + wm + grp;
    const int iB = iA + 8;

    for (int kt = 0; kt <= qt; kt++) {
        const int k0 = kt * 64;
        __syncthreads();
        {
            const int r  = t >> 2;
            const int c8 = (t & 3) * 8;
            *(uint4*)&Kh_s[r * KP2 + c8]     = *(const uint4*)(Khg + (size_t)(k0 + r) * 32 + c8);
            *(uint4*)&Kh_s[r * KP2 + c8 + 4] = *(const uint4*)(Khg + (size_t)(k0 + r) * 32 + c8 + 4);
            *(uint4*)&Kl_s[r * KP2 + c8]     = *(const uint4*)(Klg + (size_t)(k0 + r) * 32 + c8);
            *(uint4*)&Kl_s[r * KP2 + c8 + 4] = *(const uint4*)(Klg + (size_t)(k0 + r) * 32 + c8 + 4);
            const int dq = (t & 3) * 16;
            const float* vp = Vg + (size_t)(k0 + r) * 64 + dq;
            float vv[16];
            *(float4*)&vv[0]  = *(const float4*)(vp);
            *(float4*)&vv[4]  = *(const float4*)(vp + 4);
            *(float4*)&vv[8]  = *(const float4*)(vp + 8);
            *(float4*)&vv[12] = *(const float4*)(vp + 12);
#pragma unroll
            for (int j = 0; j < 16; j++)
                Vs[r * AP + dq + j] = to_tf32(vv[j]);
        }
        __syncthreads();

        // ---- scores: split-bf16, 3 mma per k16 ----
        float sacc[4][4];
#pragma unroll
        for (int i = 0; i < 4; i++)
#pragma unroll
            for (int j = 0; j < 4; j++) sacc[i][j] = 0.0f;

#pragma unroll
        for (int kp8 = 0; kp8 < 32; kp8 += 8) {
            const int rA = (wm + grp) * KP2;
            uint32_t ah0 = Qh_s[rA + kp8 + qd];
            uint32_t ah1 = Qh_s[rA + 8 * KP2 + kp8 + qd];
            uint32_t ah2 = Qh_s[rA + kp8 + qd + 4];
            uint32_t ah3 = Qh_s[rA + 8 * KP2 + kp8 + qd + 4];
            uint32_t al0 = Ql_s[rA + kp8 + qd];
            uint32_t al1 = Ql_s[rA + 8 * KP2 + kp8 + qd];
            uint32_t al2 = Ql_s[rA + kp8 + qd + 4];
            uint32_t al3 = Ql_s[rA + 8 * KP2 + kp8 + qd + 4];
#pragma unroll
            for (int nt = 0; nt < 4; nt++) {
                const int rb = (wn + nt * 8 + grp) * KP2;
                uint32_t bh0 = Kh_s[rb + kp8 + qd];
                uint32_t bh1 = Kh_s[rb + kp8 + qd + 4];
                uint32_t bl0 = Kl_s[rb + kp8 + qd];
                uint32_t bl1 = Kl_s[rb + kp8 + qd + 4];
                mma16(sacc[nt], ah0, ah1, ah2, ah3, bh0, bh1);
                mma16(sacc[nt], ah0, ah1, ah2, ah3, bl0, bl1);
                mma16(sacc[nt], al0, al1, al2, al3, bh0, bh1);
            }
        }

        const bool diag = (kt == qt);
#pragma unroll
        for (int nt = 0; nt < 4; nt++) {
            const int j0 = k0 + wn + nt * 8 + 2 * qd;
            float p0 = __expf(sacc[nt][0] * 0.125f - (float)(iA - j0) * slope);
            float p1 = __expf(sacc[nt][1] * 0.125f - (float)(iA - j0 - 1) * slope);
            float p2 = __expf(sacc[nt][2] * 0.125f - (float)(iB - j0) * slope);
            float p3 = __expf(sacc[nt][3] * 0.125f - (float)(iB - j0 - 1) * slope);
            if (diag) {
                if (j0     > iA) p0 = 0.0f;
                if (j0 + 1 > iA) p1 = 0.0f;
                if (j0     > iB) p2 = 0.0f;
                if (j0 + 1 > iB) p3 = 0.0f;
            }
            la += p0 + p1;
            lb += p2 + p3;
            if (SA) {
                *(float2*)&SA[((size_t)h * S_LEN + iA) * S_LEN + j0] = make_float2(p0, p1);
                *(float2*)&SA[((size_t)h * S_LEN + iB) * S_LEN + j0] = make_float2(p2, p3);
            }
            const int pc = wn + nt * 8 + 2 * qd;
            *(float2*)&Ps[(wm + grp)     * AP + pc] = make_float2(to_tf32(p0), to_tf32(p1));
            *(float2*)&Ps[(wm + grp + 8) * AP + pc] = make_float2(to_tf32(p2), to_tf32(p3));
        }
        __syncthreads();

        // ---- z += P V (tf32) ----
#pragma unroll
        for (int ks = 0; ks < 64; ks += 8) {
            float a0 = Ps[(wm + grp)     * AP + ks + qd];
            float a1 = Ps[(wm + grp + 8) * AP + ks + qd];
            float a2 = Ps[(wm + grp)     * AP + ks + qd + 4];
            float a3 = Ps[(wm + grp + 8) * AP + ks + qd + 4];
#pragma unroll
            for (int nt = 0; nt < 4; nt++) {
                const int nv = wn + nt * 8 + grp;
                float b0 = Vs[(ks + qd)     * AP + nv];
                float b1 = Vs[(ks + qd + 4) * AP + nv];
                mma8f(zacc[nt], a0, a1, a2, a3, b0, b1);
            }
        }
    }

    la += __shfl_xor_sync(0xffffffffu, la, 1);
    la += __shfl_xor_sync(0xffffffffu, la, 2);
    lb += __shfl_xor_sync(0xffffffffu, lb, 1);
    lb += __shfl_xor_sync(0xffffffffu, lb, 2);
    __syncthreads();
    float* red = (float*)Kh_s;
    if (qd == 0) {
        red[(w & 1) * 64 + wm + grp]     = la;
        red[(w & 1) * 64 + wm + grp + 8] = lb;
    }
    __syncthreads();
    const float lA = red[wm + grp]     + red[64 + wm + grp];
    const float lB = red[wm + grp + 8] + red[64 + wm + grp + 8];
    if ((w & 1) == 0 && qd == 0) {
        Lsum[h * S_LEN + iA] = lA;
        Lsum[h * S_LEN + iB] = lB;
    }
    const float liA = 1.0f / lA;
    const float liB = 1.0f / lB;

#pragma unroll
    for (int nt = 0; nt < 4; nt++) {
        const int v0 = h * D_HEAD + wn + nt * 8 + 2 * qd;
        *(float2*)&Z[(size_t)iA * D_MODEL + v0] =
            make_float2(to_tf32(zacc[nt][0] * liA), to_tf32(zacc[nt][1] * liA));
        *(float2*)&Z[(size_t)iB * D_MODEL + v0] =
            make_float2(to_tf32(zacc[nt][2] * liB), to_tf32(zacc[nt][3] * liB));
    }
}

// ---- SA rescale ----
__global__ __launch_bounds__(256) void sa_rescale(
    float* __restrict__ SA, const float* __restrict__ Lsum)
{
    const int row = blockIdx.x;
    const int i   = row & (S_LEN - 1);
    const float linv = 1.0f / Lsum[row];
    float4* p = (float4*)(SA + (size_t)row * S_LEN);
    const int t = threadIdx.x;
#pragma unroll
    for (int rep = 0; rep < 2; rep++) {
        const int v  = t + rep * 256;
        const int c0 = v * 4;
        if (c0 + 3 <= i) {
            float4 x = p[v];
            x.x *= linv; x.y *= linv; x.z *= linv; x.w *= linv;
            p[v] = x;
        } else if (c0 > i) {
            p[v] = make_float4(0.f, 0.f, 0.f, 0.f);
        } else {
            float4 x = p[v];
            x.x = (c0     <= i) ? x.x * linv : 0.f;
            x.y = (c0 + 1 <= i) ? x.y * linv : 0.f;
            x.z = (c0 + 2 <= i) ? x.z * linv : 0.f;
            x.w = (c0 + 3 <= i) ? x.w * linv : 0.f;
            p[v] = x;
        }
    }
}

// =================================================================
extern "C" void kernel_launch(void* const* d_in, const int* in_sizes, int n_in,
                              void* d_out, int out_size)
{
    const float* X   = (const float*)d_in[0];
    const float* WQ  = (const float*)d_in[1];
    const float* WK  = (const float*)d_in[2];
    const float* WV  = (const float*)d_in[3];
    const float* WOw = (const float*)d_in[4];
    const float* WOb = (const float*)d_in[5];
    const float* F1w = (const float*)d_in[6];
    const float* F1b = (const float*)d_in[7];
    const float* F2w = (const float*)d_in[8];
    const float* F2b = (const float*)d_in[9];

    float *Vp, *Zp, *Ap, *Hp, *Lp, *Dp;
    uint32_t *Xh2, *Xl2, *WQh2, *WQl2, *WKh2, *WKl2, *Qh2, *Ql2, *Kh2, *Kl2;
    cudaGetSymbolAddress((void**)&Vp, g_V);
    cudaGetSymbolAddress((void**)&Zp, g_Z);
    cudaGetSymbolAddress((void**)&Ap, g_ATT);
    cudaGetSymbolAddress((void**)&Hp, g_HID);
    cudaGetSymbolAddress((void**)&Lp, g_L);
    cudaGetSymbolAddress((void**)&Dp, g_DUMMY);
    cudaGetSymbolAddress((void**)&Xh2, g_Xh2);
    cudaGetSymbolAddress((void**)&Xl2, g_Xl2);
    cudaGetSymbolAddress((void**)&WQh2, g_WQh2);
    cudaGetSymbolAddress((void**)&WQl2, g_WQl2);
    cudaGetSymbolAddress((void**)&WKh2, g_WKh2);
    cudaGetSymbolAddress((void**)&WKl2, g_WKl2);
    cudaGetSymbolAddress((void**)&Qh2, g_Qh2);
    cudaGetSymbolAddress((void**)&Ql2, g_Ql2);
    cudaGetSymbolAddress((void**)&Kh2, g_Kh2);
    cudaGetSymbolAddress((void**)&Kl2, g_Kl2);

    const size_t SA_EL = (size_t)N_HEADS * S_LEN * S_LEN;
    const size_t OV_EL = (size_t)S_LEN * D_MODEL;
    float* out = (float*)d_out;
    float* sa;
    float* ov;
    if ((size_t)out_size >= SA_EL + OV_EL)      { sa = out;     ov = out + SA_EL; }
    else if ((size_t)out_size >= SA_EL)         { sa = out;     ov = Dp; }
    else                                        { sa = nullptr; ov = out; }

    const int attn_smem = (4 * QTILE + 2 * 64 * AP) * 4;   // 73728
    const int gemm_smem = 6 * TSZ * 4;                     // 110592
    const int qk_smem   = 8 * QSTG * 4;                    // 81920
    cudaFuncSetAttribute(attn_tc, cudaFuncAttributeMaxDynamicSharedMemorySize, attn_smem);
    cudaFuncSetAttribute(gemm_qk, cudaFuncAttributeMaxDynamicSharedMemorySize, qk_smem);
    cudaFuncSetAttribute(gemm2<0,false,false,false,true ,true ,true ,false>,
                         cudaFuncAttributeMaxDynamicSharedMemorySize, gemm_smem);
    cudaFuncSetAttribute(gemm2<1,true ,false,true ,false,false,true ,false>,
                         cudaFuncAttributeMaxDynamicSharedMemorySize, gemm_smem);
    cudaFuncSetAttribute(gemm2<1,true ,true ,false,false,true ,true ,true >,
                         cudaFuncAttributeMaxDynamicSharedMemorySize, gemm_smem);

    dim3 blk(256);

    // pack operands for split-bf16 path
    pack_x<<<dim3(2048), blk>>>(X, Xh2, Xl2, S_LEN * D_MODEL / 4);
    pack_w<<<dim3(2048), blk>>>(WQ, WQh2, WQl2);
    pack_w<<<dim3(2048), blk>>>(WK, WKh2, WKl2);

    // Q,K projections: split-bf16, packed output
    gemm_qk<<<dim3(8, 16), blk, qk_smem>>>(Xh2, Xl2, WQh2, WQl2, Qh2, Ql2);
    gemm_qk<<<dim3(8, 16), blk, qk_smem>>>(Xh2, Xl2, WKh2, WKl2, Kh2, Kl2);
    // V projection: plain tf32
    gemm2<0,false,false,false,true ,true ,true ,false><<<dim3(8, 16), blk, gemm_smem>>>(X, WV, nullptr, nullptr, Vp, S_LEN, D_MODEL, D_MODEL);

    attn_tc<<<dim3(S_LEN / 64, N_HEADS), blk, attn_smem>>>(Qh2, Ql2, Kh2, Kl2, Vp, sa, Zp, Lp);
    if (sa)
        sa_rescale<<<dim3(N_HEADS * S_LEN), blk>>>(sa, Lp);

    gemm2<1,true ,false,true ,false,false,true ,false><<<dim3(8, 16), blk, gemm_smem>>>(Zp, WOw, WOb, X, Ap, S_LEN, D_MODEL, D_MODEL);
    gemm2<1,true ,true ,false,false,true ,true ,true ><<<dim3(32, 16), blk, gemm_smem>>>(Ap, F1w, F1b, nullptr, Hp, S_LEN, D_FF, D_MODEL);
    gemm2<1,true ,false,true ,false,false,true ,false><<<dim3(8, 16), blk, gemm_smem>>>(Hp, F2w, F2b, Ap, ov, S_LEN, D_MODEL, D_FF);
}

// round 8
// speedup vs baseline: 3.1703x; 1.0339x over previous
#include <cuda_runtime.h>
#include <cstdint>

#define S_LEN   2048
#define D_MODEL 1024
#define N_HEADS 16
#define D_HEAD  64
#define D_FF    4096

// ---------------- scratch (no allocation allowed) ----------------
__device__ float    g_V[N_HEADS * S_LEN * D_HEAD];
__device__ float    g_Z[S_LEN * D_MODEL];
__device__ float    g_ATT[S_LEN * D_MODEL];
__device__ float    g_HID[S_LEN * D_FF];
__device__ float    g_L[N_HEADS * S_LEN];
__device__ float    g_DUMMY[S_LEN * D_MODEL];
// packed bf16x2 (hi/lo) operands
__device__ uint32_t g_Xh2[S_LEN * (D_MODEL / 2)];
__device__ uint32_t g_Xl2[S_LEN * (D_MODEL / 2)];
__device__ uint32_t g_WQh2[N_HEADS * D_HEAD * (D_MODEL / 2)];
__device__ uint32_t g_WQl2[N_HEADS * D_HEAD * (D_MODEL / 2)];
__device__ uint32_t g_WKh2[N_HEADS * D_HEAD * (D_MODEL / 2)];
__device__ uint32_t g_WKl2[N_HEADS * D_HEAD * (D_MODEL / 2)];
__device__ uint32_t g_Qh2[N_HEADS * S_LEN * (D_HEAD / 2)];
__device__ uint32_t g_Ql2[N_HEADS * S_LEN * (D_HEAD / 2)];
__device__ uint32_t g_Kh2[N_HEADS * S_LEN * (D_HEAD / 2)];
__device__ uint32_t g_Kl2[N_HEADS * S_LEN * (D_HEAD / 2)];

// =================================================================
// helpers
// =================================================================
__device__ __forceinline__ float to_tf32(float x) {
    float r;
    asm("cvt.rna.tf32.f32 %0, %1;" : "=f"(r) : "f"(x));
    return r;
}

__device__ __forceinline__ void mma8f(float* c,
    float a0, float a1, float a2, float a3, float b0, float b1)
{
    asm volatile(
        "mma.sync.aligned.m16n8k8.row.col.f32.tf32.tf32.f32 "
        "{%0,%1,%2,%3},{%4,%5,%6,%7},{%8,%9},{%0,%1,%2,%3};"
        : "+f"(c[0]), "+f"(c[1]), "+f"(c[2]), "+f"(c[3])
        : "r"(__float_as_uint(a0)), "r"(__float_as_uint(a1)),
          "r"(__float_as_uint(a2)), "r"(__float_as_uint(a3)),
          "r"(__float_as_uint(b0)), "r"(__float_as_uint(b1)));
}

__device__ __forceinline__ void mma16(float* c,
    uint32_t a0, uint32_t a1, uint32_t a2, uint32_t a3,
    uint32_t b0, uint32_t b1)
{
    asm volatile(
        "mma.sync.aligned.m16n8k16.row.col.f32.bf16.bf16.f32 "
        "{%0,%1,%2,%3},{%4,%5,%6,%7},{%8,%9},{%0,%1,%2,%3};"
        : "+f"(c[0]), "+f"(c[1]), "+f"(c[2]), "+f"(c[3])
        : "r"(a0), "r"(a1), "r"(a2), "r"(a3), "r"(b0), "r"(b1));
}

__device__ __forceinline__ void pack2(float x0, float x1, uint32_t& hi, uint32_t& lo) {
    asm("cvt.rn.bf16x2.f32 %0, %1, %2;" : "=r"(hi) : "f"(x1), "f"(x0));
    float f0 = __uint_as_float(hi << 16);
    float f1 = __uint_as_float(hi & 0xffff0000u);
    asm("cvt.rn.bf16x2.f32 %0, %1, %2;" : "=r"(lo) : "f"(x1 - f1), "f"(x0 - f0));
}

__device__ __forceinline__ void cp16(uint32_t dst_smem, const void* src) {
    asm volatile("cp.async.cg.shared.global [%0], [%1], 16;"
                 :: "r"(dst_smem), "l"(src));
}
#define CP_COMMIT() asm volatile("cp.async.commit_group;")
#define CP_WAIT1()  asm volatile("cp.async.wait_group 1;")
#define CP_WAIT2()  asm volatile("cp.async.wait_group 2;")

// =================================================================
// prep: pack X and per-head weights into bf16x2 hi/lo
// =================================================================
__global__ __launch_bounds__(256) void pack_x(
    const float* __restrict__ in, uint32_t* __restrict__ oh,
    uint32_t* __restrict__ ol, int n4)
{
    int i = blockIdx.x * 256 + threadIdx.x;
    if (i < n4) {
        float4 v = ((const float4*)in)[i];
        uint32_t h0, l0, h1, l1;
        pack2(v.x, v.y, h0, l0);
        pack2(v.z, v.w, h1, l1);
        ((uint2*)oh)[i] = make_uint2(h0, h1);
        ((uint2*)ol)[i] = make_uint2(l0, l1);
    }
}

__global__ __launch_bounds__(256) void pack_w(
    const float* __restrict__ in, uint32_t* __restrict__ oh,
    uint32_t* __restrict__ ol)
{
    int i  = blockIdx.x * 256 + threadIdx.x;
    int e  = i & 63;
    int kp = (i >> 6) & 511;
    int h  = i >> 15;
    float x0 = in[((size_t)h * 1024 + 2 * kp)     * 64 + e];
    float x1 = in[((size_t)h * 1024 + 2 * kp + 1) * 64 + e];
    uint32_t hi, lo;
    pack2(x0, x1, hi, lo);
    oh[((size_t)h * 64 + e) * 512 + kp] = hi;
    ol[((size_t)h * 64 + e) * 512 + kp] = lo;
}

// =================================================================
// Q+K projection (merged, blockIdx.z selects weight/output pair)
// =================================================================
#define QKP 20
#define QSTG (128 * QKP)

__global__ __launch_bounds__(256, 2) void gemm_qk(
    const uint32_t* __restrict__ Ah2g, const uint32_t* __restrict__ Al2g,
    const uint32_t* __restrict__ BQh, const uint32_t* __restrict__ BQl,
    const uint32_t* __restrict__ BKh, const uint32_t* __restrict__ BKl,
    uint32_t* __restrict__ OQh, uint32_t* __restrict__ OQl,
    uint32_t* __restrict__ OKh, uint32_t* __restrict__ OKl)
{
    extern __shared__ float sm[];
    uint32_t* smu = (uint32_t*)sm;

    const int t    = threadIdx.x;
    const int lane = t & 31;
    const int w    = t >> 5;
    const int grp  = lane >> 2;
    const int qd   = lane & 3;
    const int wm   = (w & 3) * 32;
    const int wn   = (w >> 2) * 64;
    const int m0   = blockIdx.y * 128;
    const int n0   = blockIdx.x * 128;

    const uint32_t* Bh2g = blockIdx.z ? BKh : BQh;
    const uint32_t* Bl2g = blockIdx.z ? BKl : BQl;
    uint32_t* Oh = blockIdx.z ? OKh : OQh;
    uint32_t* Ol = blockIdx.z ? OKl : OQl;

    float acc[2][8][4];
#pragma unroll
    for (int i = 0; i < 2; i++)
#pragma unroll
        for (int j = 0; j < 8; j++)
#pragma unroll
            for (int k = 0; k < 4; k++) acc[i][j][k] = 0.0f;

    const uint32_t sb = (uint32_t)__cvta_generic_to_shared(smu);

    auto issue = [&](int kt, int s) {
        const int kb = kt * 16;
        const uint32_t base = sb + (uint32_t)s * 4 * QSTG * 4;
#pragma unroll
        for (int i = t; i < 512; i += 256) {
            const int r = i >> 2, c = (i & 3) * 4;
            const uint32_t d = base + (r * QKP + c) * 4;
            cp16(d,                Ah2g + (size_t)(m0 + r) * 512 + kb + c);
            cp16(d + QSTG * 4,     Al2g + (size_t)(m0 + r) * 512 + kb + c);
            const int n = n0 + r;
            const size_t wo = ((size_t)(n >> 6) * 64 + (n & 63)) * 512 + kb + c;
            cp16(d + 2 * QSTG * 4, Bh2g + wo);
            cp16(d + 3 * QSTG * 4, Bl2g + wo);
        }
    };

    issue(0, 0); CP_COMMIT();
    issue(1, 1); CP_COMMIT();

    for (int kt = 0; kt < 32; kt++) {
        CP_WAIT1();
        __syncthreads();
        const uint32_t* Ah = smu + (kt & 1) * 4 * QSTG;
        const uint32_t* Al = Ah + QSTG;
        const uint32_t* Bh = Ah + 2 * QSTG;
        const uint32_t* Bl = Ah + 3 * QSTG;

#pragma unroll
        for (int ks2 = 0; ks2 < 16; ks2 += 8) {
            uint32_t ah[2][4], al[2][4];
#pragma unroll
            for (int mt = 0; mt < 2; mt++) {
                const int r = (wm + mt * 16 + grp) * QKP;
                ah[mt][0] = Ah[r + ks2 + qd];
                ah[mt][1] = Ah[r + 8 * QKP + ks2 + qd];
                ah[mt][2] = Ah[r + ks2 + qd + 4];
                ah[mt][3] = Ah[r + 8 * QKP + ks2 + qd + 4];
                al[mt][0] = Al[r + ks2 + qd];
                al[mt][1] = Al[r + 8 * QKP + ks2 + qd];
                al[mt][2] = Al[r + ks2 + qd + 4];
                al[mt][3] = Al[r + 8 * QKP + ks2 + qd + 4];
            }
#pragma unroll
            for (int nt = 0; nt < 8; nt++) {
                const int rb = (wn + nt * 8 + grp) * QKP;
                uint32_t bh0 = Bh[rb + ks2 + qd];
                uint32_t bh1 = Bh[rb + ks2 + qd + 4];
                uint32_t bl0 = Bl[rb + ks2 + qd];
                uint32_t bl1 = Bl[rb + ks2 + qd + 4];
#pragma unroll
                for (int mt = 0; mt < 2; mt++) {
                    mma16(acc[mt][nt], ah[mt][0], ah[mt][1], ah[mt][2], ah[mt][3], bh0, bh1);
                    mma16(acc[mt][nt], ah[mt][0], ah[mt][1], ah[mt][2], ah[mt][3], bl0, bl1);
                    mma16(acc[mt][nt], al[mt][0], al[mt][1], al[mt][2], al[mt][3], bh0, bh1);
                }
            }
        }
        __syncthreads();
        if (kt + 2 < 32) issue(kt + 2, kt & 1);
        CP_COMMIT();
    }

#pragma unroll
    for (int mt = 0; mt < 2; mt++) {
#pragma unroll
        for (int nt = 0; nt < 8; nt++) {
            const int n  = n0 + wn + nt * 8 + 2 * qd;
            const int h  = n >> 6;
            const int dp = (n & 63) >> 1;
            const int mA = blockIdx.y * 128 + wm + mt * 16 + grp;
            const int mB = mA + 8;
            uint32_t hi, lo;
            pack2(acc[mt][nt][0], acc[mt][nt][1], hi, lo);
            Oh[((size_t)h * S_LEN + mA) * 32 + dp] = hi;
            Ol[((size_t)h * S_LEN + mA) * 32 + dp] = lo;
            pack2(acc[mt][nt][2], acc[mt][nt][3], hi, lo);
            Oh[((size_t)h * S_LEN + mB) * 32 + dp] = hi;
            Ol[((size_t)h * S_LEN + mB) * 32 + dp] = lo;
        }
    }
}

// =================================================================
// Plain tf32 GEMM (V/WO/FF)
// =================================================================
#define TSZ 4608
#define PA  36
#define PB0 136

template<int BMODE, bool BIAS, bool RELU, bool RESID, bool OUTHEAD,
         bool CVT_A, bool CVT_B, bool CVT_OUT>
__global__ __launch_bounds__(256, 2) void gemm2(
    const float* __restrict__ A, const float* __restrict__ B,
    const float* __restrict__ bias, const float* __restrict__ resid,
    float* __restrict__ C, int M, int N, int K)
{
    extern __shared__ float sm[];
    float* As0 = sm;
    float* Bs0 = sm + 3 * TSZ;

    const int t    = threadIdx.x;
    const int lane = t & 31;
    const int w    = t >> 5;
    const int grp  = lane >> 2;
    const int qd   = lane & 3;
    const int wm   = (w & 3) * 32;
    const int wn   = (w >> 2) * 64;
    const int m0   = blockIdx.y * 128;
    const int n0   = blockIdx.x * 128;

    float acc[2][8][4];
#pragma unroll
    for (int i = 0; i < 2; i++)
#pragma unroll
        for (int j = 0; j < 8; j++)
#pragma unroll
            for (int k = 0; k < 4; k++) acc[i][j][k] = 0.0f;

    const int KT = K >> 5;
    uint32_t sbaseA = (uint32_t)__cvta_generic_to_shared(As0);
    uint32_t sbaseB = (uint32_t)__cvta_generic_to_shared(Bs0);

    auto issue = [&](int kt, int s) {
        const uint32_t Ad = sbaseA + s * TSZ * 4;
        const uint32_t Bd = sbaseB + s * TSZ * 4;
        const int kb = kt * 32;
#pragma unroll
        for (int i = t; i < 1024; i += 256) {
            const int m = i >> 3, c = (i & 7) * 4;
            cp16(Ad + (m * PA + c) * 4, A + (size_t)(m0 + m) * K + kb + c);
        }
        if (BMODE == 1) {
#pragma unroll
            for (int i = t; i < 1024; i += 256) {
                const int n = i >> 3, c = (i & 7) * 4;
                cp16(Bd + (n * PA + c) * 4, B + (size_t)(n0 + n) * K + kb + c);
            }
        } else {
#pragma unroll
            for (int i = t; i < 1024; i += 256) {
                const int k = i >> 5, nq = (i & 31) * 4;
                const int h = (n0 + nq) >> 6, e = (n0 + nq) & 63;
                cp16(Bd + (k * PB0 + nq) * 4, B + ((size_t)h * K + kb + k) * 64 + e);
            }
        }
    };

    issue(0, 0); CP_COMMIT();
    issue(1, 1); CP_COMMIT();
    issue(2, 2); CP_COMMIT();

    for (int kt = 0; kt < KT; kt++) {
        const int s = kt % 3;
        CP_WAIT2();
        __syncthreads();
        const float* Ab = As0 + s * TSZ;
        const float* Bb = Bs0 + s * TSZ;

#pragma unroll
        for (int ks = 0; ks < 32; ks += 8) {
            float ar[2][4];
#pragma unroll
            for (int mt = 0; mt < 2; mt++) {
                const int r = (wm + mt * 16 + grp) * PA;
                ar[mt][0] = Ab[r + ks + qd];
                ar[mt][1] = Ab[r + 8 * PA + ks + qd];
                ar[mt][2] = Ab[r + ks + qd + 4];
                ar[mt][3] = Ab[r + 8 * PA + ks + qd + 4];
            }
            if (CVT_A) {
#pragma unroll
                for (int mt = 0; mt < 2; mt++)
#pragma unroll
                    for (int x = 0; x < 4; x++) ar[mt][x] = to_tf32(ar[mt][x]);
            }
#pragma unroll
            for (int nt = 0; nt < 8; nt++) {
                float b0, b1;
                if (BMODE == 1) {
                    const int r = (wn + nt * 8 + grp) * PA;
                    b0 = Bb[r + ks + qd];
                    b1 = Bb[r + ks + qd + 4];
                } else {
                    const int cn = wn + nt * 8 + grp;
                    b0 = Bb[(ks + qd) * PB0 + cn];
                    b1 = Bb[(ks + qd + 4) * PB0 + cn];
                }
                if (CVT_B) { b0 = to_tf32(b0); b1 = to_tf32(b1); }
#pragma unroll
                for (int mt = 0; mt < 2; mt++)
                    mma8f(acc[mt][nt], ar[mt][0], ar[mt][1], ar[mt][2], ar[mt][3], b0, b1);
            }
        }
        __syncthreads();
        if (kt + 3 < KT) issue(kt + 3, s);
        CP_COMMIT();
    }

#pragma unroll
    for (int mt = 0; mt < 2; mt++) {
#pragma unroll
        for (int nt = 0; nt < 8; nt++) {
            const int n  = n0 + wn + nt * 8 + 2 * qd;
            float2 v0 = make_float2(acc[mt][nt][0], acc[mt][nt][1]);
            float2 v1 = make_float2(acc[mt][nt][2], acc[mt][nt][3]);
            if (BIAS) {
                float2 bb = *(const float2*)&bias[n];
                v0.x += bb.x; v0.y += bb.y;
                v1.x += bb.x; v1.y += bb.y;
            }
            if (RELU) {
                v0.x = fmaxf(v0.x, 0.f); v0.y = fmaxf(v0.y, 0.f);
                v1.x = fmaxf(v1.x, 0.f); v1.y = fmaxf(v1.y, 0.f);
            }
            const int mA = m0 + wm + mt * 16 + grp;
            const int mB = mA + 8;
            if (RESID) {
                float2 r0 = *(const float2*)&resid[(size_t)mA * N + n];
                float2 r1 = *(const float2*)&resid[(size_t)mB * N + n];
                v0.x += r0.x; v0.y += r0.y;
                v1.x += r1.x; v1.y += r1.y;
            }
            if (CVT_OUT) {
                v0.x = to_tf32(v0.x); v0.y = to_tf32(v0.y);
                v1.x = to_tf32(v1.x); v1.y = to_tf32(v1.y);
            }
            if (OUTHEAD) {
                const int h = n >> 6;
                const int e = n & 63;
                *(float2*)&C[((size_t)h * M + mA) * 64 + e] = v0;
                *(float2*)&C[((size_t)h * M + mB) * 64 + e] = v1;
            } else {
                *(float2*)&C[(size_t)mA * N + n] = v0;
                *(float2*)&C[(size_t)mB * N + n] = v1;
            }
        }
    }
}

// =================================================================
// Attention (unchanged from R7)
// =================================================================
#define AP  72
#define KP2 36
#define QTILE (64 * KP2)

__global__ __launch_bounds__(256, 2) void attn_tc(
    const uint32_t* __restrict__ Qh2, const uint32_t* __restrict__ Ql2,
    const uint32_t* __restrict__ Kh2, const uint32_t* __restrict__ Kl2,
    const float* __restrict__ V, float* __restrict__ SA,
    float* __restrict__ Z, float* __restrict__ Lsum)
{
    extern __shared__ float sm[];
    uint32_t* Qh_s = (uint32_t*)sm;
    uint32_t* Ql_s = Qh_s + QTILE;
    uint32_t* Kh_s = Qh_s + 2 * QTILE;
    uint32_t* Kl_s = Qh_s + 3 * QTILE;
    float*    Vs   = sm + 4 * QTILE;
    float*    Ps   = Vs + 64 * AP;

    const int t    = threadIdx.x;
    const int lane = t & 31;
    const int w    = t >> 5;
    const int grp  = lane >> 2;
    const int qd   = lane & 3;
    const int wm   = (w >> 1) * 16;
    const int wn   = (w & 1) * 32;
    const int qt   = (int)gridDim.x - 1 - (int)blockIdx.x;
    const int h    = blockIdx.y;
    const int q0   = qt * 64;

    const float slope = exp2f(-0.5f * (float)(h + 1));
    const float* Vg = V + (size_t)h * S_LEN * D_HEAD;
    const uint32_t* Qhg = Qh2 + (size_t)h * S_LEN * 32;
    const uint32_t* Qlg = Ql2 + (size_t)h * S_LEN * 32;
    const uint32_t* Khg = Kh2 + (size_t)h * S_LEN * 32;
    const uint32_t* Klg = Kl2 + (size_t)h * S_LEN * 32;

    {
        const int r  = t >> 2;
        const int c8 = (t & 3) * 8;
        *(uint4*)&Qh_s[r * KP2 + c8]     = *(const uint4*)(Qhg + (size_t)(q0 + r) * 32 + c8);
        *(uint4*)&Qh_s[r * KP2 + c8 + 4] = *(const uint4*)(Qhg + (size_t)(q0 + r) * 32 + c8 + 4);
        *(uint4*)&Ql_s[r * KP2 + c8]     = *(const uint4*)(Qlg + (size_t)(q0 + r) * 32 + c8);
        *(uint4*)&Ql_s[r * KP2 + c8 + 4] = *(const uint4*)(Qlg + (size_t)(q0 + r) * 32 + c8 + 4);
    }

    float zacc[4][4];
#pragma unroll
    for (int i = 0; i < 4; i++)
#pragma unroll
        for (int j = 0; j < 4; j++) zacc[i][j] = 0.0f;
    float la = 0.0f, lb = 0.0f;

    const int iA = q0 + wm + grp;
    const int iB = iA + 8;

    for (int kt = 0; kt <= qt; kt++) {
        const int k0 = kt * 64;
        __syncthreads();
        {
            const int r  = t >> 2;
            const int c8 = (t & 3) * 8;
            *(uint4*)&Kh_s[r * KP2 + c8]     = *(const uint4*)(Khg + (size_t)(k0 + r) * 32 + c8);
            *(uint4*)&Kh_s[r * KP2 + c8 + 4] = *(const uint4*)(Khg + (size_t)(k0 + r) * 32 + c8 + 4);
            *(uint4*)&Kl_s[r * KP2 + c8]     = *(const uint4*)(Klg + (size_t)(k0 + r) * 32 + c8);
            *(uint4*)&Kl_s[r * KP2 + c8 + 4] = *(const uint4*)(Klg + (size_t)(k0 + r) * 32 + c8 + 4);
            const int dq = (t & 3) * 16;
            const float* vp = Vg + (size_t)(k0 + r) * 64 + dq;
            float vv[16];
            *(float4*)&vv[0]  = *(const float4*)(vp);
            *(float4*)&vv[4]  = *(const float4*)(vp + 4);
            *(float4*)&vv[8]  = *(const float4*)(vp + 8);
            *(float4*)&vv[12] = *(const float4*)(vp + 12);
#pragma unroll
            for (int j = 0; j < 16; j++)
                Vs[r * AP + dq + j] = to_tf32(vv[j]);
        }
        __syncthreads();

        float sacc[4][4];
#pragma unroll
        for (int i = 0; i < 4; i++)
#pragma unroll
            for (int j = 0; j < 4; j++) sacc[i][j] = 0.0f;

#pragma unroll
        for (int kp8 = 0; kp8 < 32; kp8 += 8) {
            const int rA = (wm + grp) * KP2;
            uint32_t ah0 = Qh_s[rA + kp8 + qd];
            uint32_t ah1 = Qh_s[rA + 8 * KP2 + kp8 + qd];
            uint32_t ah2 = Qh_s[rA + kp8 + qd + 4];
            uint32_t ah3 = Qh_s[rA + 8 * KP2 + kp8 + qd + 4];
            uint32_t al0 = Ql_s[rA + kp8 + qd];
            uint32_t al1 = Ql_s[rA + 8 * KP2 + kp8 + qd];
            uint32_t al2 = Ql_s[rA + kp8 + qd + 4];
            uint32_t al3 = Ql_s[rA + 8 * KP2 + kp8 + qd + 4];
#pragma unroll
            for (int nt = 0; nt < 4; nt++) {
                const int rb = (wn + nt * 8 + grp) * KP2;
                uint32_t bh0 = Kh_s[rb + kp8 + qd];
                uint32_t bh1 = Kh_s[rb + kp8 + qd + 4];
                uint32_t bl0 = Kl_s[rb + kp8 + qd];
                uint32_t bl1 = Kl_s[rb + kp8 + qd + 4];
                mma16(sacc[nt], ah0, ah1, ah2, ah3, bh0, bh1);
                mma16(sacc[nt], ah0, ah1, ah2, ah3, bl0, bl1);
                mma16(sacc[nt], al0, al1, al2, al3, bh0, bh1);
            }
        }

        const bool diag = (kt == qt);
#pragma unroll
        for (int nt = 0; nt < 4; nt++) {
            const int j0 = k0 + wn + nt * 8 + 2 * qd;
            float p0 = __expf(sacc[nt][0] * 0.125f - (float)(iA - j0) * slope);
            float p1 = __expf(sacc[nt][1] * 0.125f - (float)(iA - j0 - 1) * slope);
            float p2 = __expf(sacc[nt][2] * 0.125f - (float)(iB - j0) * slope);
            float p3 = __expf(sacc[nt][3] * 0.125f - (float)(iB - j0 - 1) * slope);
            if (diag) {
                if (j0     > iA) p0 = 0.0f;
                if (j0 + 1 > iA) p1 = 0.0f;
                if (j0     > iB) p2 = 0.0f;
                if (j0 + 1 > iB) p3 = 0.0f;
            }
            la += p0 + p1;
            lb += p2 + p3;
            if (SA) {
                *(float2*)&SA[((size_t)h * S_LEN + iA) * S_LEN + j0] = make_float2(p0, p1);
                *(float2*)&SA[((size_t)h * S_LEN + iB) * S_LEN + j0] = make_float2(p2, p3);
            }
            const int pc = wn + nt * 8 + 2 * qd;
            *(float2*)&Ps[(wm + grp)     * AP + pc] = make_float2(to_tf32(p0), to_tf32(p1));
            *(float2*)&Ps[(wm + grp + 8) * AP + pc] = make_float2(to_tf32(p2), to_tf32(p3));
        }
        __syncthreads();

#pragma unroll
        for (int ks = 0; ks < 64; ks += 8) {
            float a0 = Ps[(wm + grp)     * AP + ks + qd];
            float a1 = Ps[(wm + grp + 8) * AP + ks + qd];
            float a2 = Ps[(wm + grp)     * AP + ks + qd + 4];
            float a3 = Ps[(wm + grp + 8) * AP + ks + qd + 4];
#pragma unroll
            for (int nt = 0; nt < 4; nt++) {
                const int nv = wn + nt * 8 + grp;
                float b0 = Vs[(ks + qd)     * AP + nv];
                float b1 = Vs[(ks + qd + 4) * AP + nv];
                mma8f(zacc[nt], a0, a1, a2, a3, b0, b1);
            }
        }
    }

    la += __shfl_xor_sync(0xffffffffu, la, 1);
    la += __shfl_xor_sync(0xffffffffu, la, 2);
    lb += __shfl_xor_sync(0xffffffffu, lb, 1);
    lb += __shfl_xor_sync(0xffffffffu, lb, 2);
    __syncthreads();
    float* red = (float*)Kh_s;
    if (qd == 0) {
        red[(w & 1) * 64 + wm + grp]     = la;
        red[(w & 1) * 64 + wm + grp + 8] = lb;
    }
    __syncthreads();
    const float lA = red[wm + grp]     + red[64 + wm + grp];
    const float lB = red[wm + grp + 8] + red[64 + wm + grp + 8];
    if ((w & 1) == 0 && qd == 0) {
        Lsum[h * S_LEN + iA] = lA;
        Lsum[h * S_LEN + iB] = lB;
    }
    const float liA = 1.0f / lA;
    const float liB = 1.0f / lB;

#pragma unroll
    for (int nt = 0; nt < 4; nt++) {
        const int v0 = h * D_HEAD + wn + nt * 8 + 2 * qd;
        *(float2*)&Z[(size_t)iA * D_MODEL + v0] =
            make_float2(to_tf32(zacc[nt][0] * liA), to_tf32(zacc[nt][1] * liA));
        *(float2*)&Z[(size_t)iB * D_MODEL + v0] =
            make_float2(to_tf32(zacc[nt][2] * liB), to_tf32(zacc[nt][3] * liB));
    }
}

// ---- SA upper-triangle zero-fill (tile granularity) ----
__global__ __launch_bounds__(256) void sa_zero(float* __restrict__ SA)
{
    const int row   = blockIdx.x;                 // h*2048 + i
    const int i     = row & (S_LEN - 1);
    const int start = (((i >> 6) + 1) << 6) >> 2; // first float4 beyond diag tile
    float4* p = (float4*)(SA + (size_t)row * S_LEN);
    const float4 z4 = make_float4(0.f, 0.f, 0.f, 0.f);
    for (int v = start + threadIdx.x; v < S_LEN / 4; v += 256)
        p[v] = z4;
}

// ---- SA rescale: lower tiles only (masked zeros stay zero) ----
__global__ __launch_bounds__(256) void sa_rescale(
    float* __restrict__ SA, const float* __restrict__ Lsum)
{
    const int row = blockIdx.x;
    const int i   = row & (S_LEN - 1);
    const int end = (((i >> 6) + 1) << 6) >> 2;   // float4 count to scale
    const float linv = 1.0f / Lsum[row];
    float4* p = (float4*)(SA + (size_t)row * S_LEN);
    for (int v = threadIdx.x; v < end; v += 256) {
        float4 x = p[v];
        x.x *= linv; x.y *= linv; x.z *= linv; x.w *= linv;
        p[v] = x;
    }
}

// =================================================================
extern "C" void kernel_launch(void* const* d_in, const int* in_sizes, int n_in,
                              void* d_out, int out_size)
{
    const float* X   = (const float*)d_in[0];
    const float* WQ  = (const float*)d_in[1];
    const float* WK  = (const float*)d_in[2];
    const float* WV  = (const float*)d_in[3];
    const float* WOw = (const float*)d_in[4];
    const float* WOb = (const float*)d_in[5];
    const float* F1w = (const float*)d_in[6];
    const float* F1b = (const float*)d_in[7];
    const float* F2w = (const float*)d_in[8];
    const float* F2b = (const float*)d_in[9];

    float *Vp, *Zp, *Ap, *Hp, *Lp, *Dp;
    uint32_t *Xh2, *Xl2, *WQh2, *WQl2, *WKh2, *WKl2, *Qh2, *Ql2, *Kh2, *Kl2;
    cudaGetSymbolAddress((void**)&Vp, g_V);
    cudaGetSymbolAddress((void**)&Zp, g_Z);
    cudaGetSymbolAddress((void**)&Ap, g_ATT);
    cudaGetSymbolAddress((void**)&Hp, g_HID);
    cudaGetSymbolAddress((void**)&Lp, g_L);
    cudaGetSymbolAddress((void**)&Dp, g_DUMMY);
    cudaGetSymbolAddress((void**)&Xh2, g_Xh2);
    cudaGetSymbolAddress((void**)&Xl2, g_Xl2);
    cudaGetSymbolAddress((void**)&WQh2, g_WQh2);
    cudaGetSymbolAddress((void**)&WQl2, g_WQl2);
    cudaGetSymbolAddress((void**)&WKh2, g_WKh2);
    cudaGetSymbolAddress((void**)&WKl2, g_WKl2);
    cudaGetSymbolAddress((void**)&Qh2, g_Qh2);
    cudaGetSymbolAddress((void**)&Ql2, g_Ql2);
    cudaGetSymbolAddress((void**)&Kh2, g_Kh2);
    cudaGetSymbolAddress((void**)&Kl2, g_Kl2);

    const size_t SA_EL = (size_t)N_HEADS * S_LEN * S_LEN;
    const size_t OV_EL = (size_t)S_LEN * D_MODEL;
    float* out = (float*)d_out;
    float* sa;
    float* ov;
    if ((size_t)out_size >= SA_EL + OV_EL)      { sa = out;     ov = out + SA_EL; }
    else if ((size_t)out_size >= SA_EL)         { sa = out;     ov = Dp; }
    else                                        { sa = nullptr; ov = out; }

    const int attn_smem = (4 * QTILE + 2 * 64 * AP) * 4;
    const int gemm_smem = 6 * TSZ * 4;
    const int qk_smem   = 8 * QSTG * 4;
    cudaFuncSetAttribute(attn_tc, cudaFuncAttributeMaxDynamicSharedMemorySize, attn_smem);
    cudaFuncSetAttribute(gemm_qk, cudaFuncAttributeMaxDynamicSharedMemorySize, qk_smem);
    cudaFuncSetAttribute(gemm2<0,false,false,false,true ,true ,true ,false>,
                         cudaFuncAttributeMaxDynamicSharedMemorySize, gemm_smem);
    cudaFuncSetAttribute(gemm2<1,true ,false,true ,false,false,true ,false>,
                         cudaFuncAttributeMaxDynamicSharedMemorySize, gemm_smem);
    cudaFuncSetAttribute(gemm2<1,true ,true ,false,false,true ,true ,true >,
                         cudaFuncAttributeMaxDynamicSharedMemorySize, gemm_smem);

    // lazily created side stream + events (host objects only; work is
    // identical on every call, so determinism is preserved)
    static cudaStream_t s2 = nullptr;
    static cudaEvent_t evStart = nullptr, evAttn = nullptr, evSide = nullptr;
    if (!s2) {
        cudaStreamCreateWithFlags(&s2, cudaStreamNonBlocking);
        cudaEventCreateWithFlags(&evStart, cudaEventDisableTiming);
        cudaEventCreateWithFlags(&evAttn,  cudaEventDisableTiming);
        cudaEventCreateWithFlags(&evSide,  cudaEventDisableTiming);
    }

    dim3 blk(256);

    // ---- fork: zero the SA upper triangle on the side stream ----
    if (sa) {
        cudaEventRecord(evStart, 0);
        cudaStreamWaitEvent(s2, evStart, 0);
        sa_zero<<<dim3(N_HEADS * S_LEN), blk, 0, s2>>>(sa);
    }

    // ---- main stream: pack, projections, attention ----
    pack_x<<<dim3(2048), blk>>>(X, Xh2, Xl2, S_LEN * D_MODEL / 4);
    pack_w<<<dim3(2048), blk>>>(WQ, WQh2, WQl2);
    pack_w<<<dim3(2048), blk>>>(WK, WKh2, WKl2);

    gemm_qk<<<dim3(8, 16, 2), blk, qk_smem>>>(Xh2, Xl2,
        WQh2, WQl2, WKh2, WKl2, Qh2, Ql2, Kh2, Kl2);
    gemm2<0,false,false,false,true ,true ,true ,false><<<dim3(8, 16), blk, gemm_smem>>>(X, WV, nullptr, nullptr, Vp, S_LEN, D_MODEL, D_MODEL);

    attn_tc<<<dim3(S_LEN / 64, N_HEADS), blk, attn_smem>>>(Qh2, Ql2, Kh2, Kl2, Vp, sa, Zp, Lp);

    // ---- fork: rescale SA on the side stream, overlapping WO/FF ----
    if (sa) {
        cudaEventRecord(evAttn, 0);
        cudaStreamWaitEvent(s2, evAttn, 0);
        sa_rescale<<<dim3(N_HEADS * S_LEN), blk, 0, s2>>>(sa, Lp);
        cudaEventRecord(evSide, s2);
    }

    gemm2<1,true ,false,true ,false,false,true ,false><<<dim3(8, 16), blk, gemm_smem>>>(Zp, WOw, WOb, X, Ap, S_LEN, D_MODEL, D_MODEL);
    gemm2<1,true ,true ,false,false,true ,true ,true ><<<dim3(32, 16), blk, gemm_smem>>>(Ap, F1w, F1b, nullptr, Hp, S_LEN, D_FF, D_MODEL);
    gemm2<1,true ,false,true ,false,false,true ,false><<<dim3(8, 16), blk, gemm_smem>>>(Hp, F2w, F2b, Ap, ov, S_LEN, D_MODEL, D_FF);

    // ---- join side stream back into the capture stream ----
    if (sa)
        cudaStreamWaitEvent(0, evSide, 0);
}

// round 10
// speedup vs baseline: 3.9773x; 1.2546x over previous
#include <cuda_runtime.h>
#include <cstdint>

#define S_LEN   2048
#define D_MODEL 1024
#define N_HEADS 16
#define D_HEAD  64
#define D_FF    4096

// ---------------- scratch (no allocation allowed) ----------------
__device__ float    g_V[N_HEADS * S_LEN * D_HEAD];
__device__ float    g_ATT[S_LEN * D_MODEL];
__device__ float    g_L[N_HEADS * S_LEN];
__device__ float    g_DUMMY[S_LEN * D_MODEL];
// bf16x2 (hi/lo) packed operands for Q/K path
__device__ uint32_t g_Xh2[S_LEN * (D_MODEL / 2)];
__device__ uint32_t g_Xl2[S_LEN * (D_MODEL / 2)];
__device__ uint32_t g_WQh2[N_HEADS * D_HEAD * (D_MODEL / 2)];
__device__ uint32_t g_WQl2[N_HEADS * D_HEAD * (D_MODEL / 2)];
__device__ uint32_t g_WKh2[N_HEADS * D_HEAD * (D_MODEL / 2)];
__device__ uint32_t g_WKl2[N_HEADS * D_HEAD * (D_MODEL / 2)];
__device__ uint32_t g_Qh2[N_HEADS * S_LEN * (D_HEAD / 2)];
__device__ uint32_t g_Ql2[N_HEADS * S_LEN * (D_HEAD / 2)];
__device__ uint32_t g_Kh2[N_HEADS * S_LEN * (D_HEAD / 2)];
__device__ uint32_t g_Kl2[N_HEADS * S_LEN * (D_HEAD / 2)];
// fp16x2 packed operands for V/WO/FF path
__device__ uint32_t g_Xf2[S_LEN * (D_MODEL / 2)];
__device__ uint32_t g_WVf2[D_MODEL * (D_MODEL / 2)];
__device__ uint32_t g_WOf2[D_MODEL * (D_MODEL / 2)];
__device__ uint32_t g_F1f2[D_FF * (D_MODEL / 2)];
__device__ uint32_t g_F2f2[D_MODEL * (D_FF / 2)];
__device__ uint32_t g_Zf2[S_LEN * (D_MODEL / 2)];
__device__ uint32_t g_ATTf2[S_LEN * (D_MODEL / 2)];
__device__ uint32_t g_HIDf2[S_LEN * (D_FF / 2)];

// =================================================================
// helpers
// =================================================================
__device__ __forceinline__ float to_tf32(float x) {
    float r;
    asm("cvt.rna.tf32.f32 %0, %1;" : "=f"(r) : "f"(x));
    return r;
}

__device__ __forceinline__ void mma8f(float* c,
    float a0, float a1, float a2, float a3, float b0, float b1)
{
    asm volatile(
        "mma.sync.aligned.m16n8k8.row.col.f32.tf32.tf32.f32 "
        "{%0,%1,%2,%3},{%4,%5,%6,%7},{%8,%9},{%0,%1,%2,%3};"
        : "+f"(c[0]), "+f"(c[1]), "+f"(c[2]), "+f"(c[3])
        : "r"(__float_as_uint(a0)), "r"(__float_as_uint(a1)),
          "r"(__float_as_uint(a2)), "r"(__float_as_uint(a3)),
          "r"(__float_as_uint(b0)), "r"(__float_as_uint(b1)));
}

__device__ __forceinline__ void mma16(float* c,
    uint32_t a0, uint32_t a1, uint32_t a2, uint32_t a3,
    uint32_t b0, uint32_t b1)
{
    asm volatile(
        "mma.sync.aligned.m16n8k16.row.col.f32.bf16.bf16.f32 "
        "{%0,%1,%2,%3},{%4,%5,%6,%7},{%8,%9},{%0,%1,%2,%3};"
        : "+f"(c[0]), "+f"(c[1]), "+f"(c[2]), "+f"(c[3])
        : "r"(a0), "r"(a1), "r"(a2), "r"(a3), "r"(b0), "r"(b1));
}

__device__ __forceinline__ void mma16h(float* c,
    uint32_t a0, uint32_t a1, uint32_t a2, uint32_t a3,
    uint32_t b0, uint32_t b1)
{
    asm volatile(
        "mma.sync.aligned.m16n8k16.row.col.f32.f16.f16.f32 "
        "{%0,%1,%2,%3},{%4,%5,%6,%7},{%8,%9},{%0,%1,%2,%3};"
        : "+f"(c[0]), "+f"(c[1]), "+f"(c[2]), "+f"(c[3])
        : "r"(a0), "r"(a1), "r"(a2), "r"(a3), "r"(b0), "r"(b1));
}

__device__ __forceinline__ void pack2(float x0, float x1, uint32_t& hi, uint32_t& lo) {
    asm("cvt.rn.bf16x2.f32 %0, %1, %2;" : "=r"(hi) : "f"(x1), "f"(x0));
    float f0 = __uint_as_float(hi << 16);
    float f1 = __uint_as_float(hi & 0xffff0000u);
    asm("cvt.rn.bf16x2.f32 %0, %1, %2;" : "=r"(lo) : "f"(x1 - f1), "f"(x0 - f0));
}

__device__ __forceinline__ uint32_t packh2(float x0, float x1) {
    uint32_t r;
    asm("cvt.rn.f16x2.f32 %0, %1, %2;" : "=r"(r) : "f"(x1), "f"(x0));
    return r;
}

__device__ __forceinline__ void cp16(uint32_t dst_smem, const void* src) {
    asm volatile("cp.async.cg.shared.global [%0], [%1], 16;"
                 :: "r"(dst_smem), "l"(src));
}
#define CP_COMMIT() asm volatile("cp.async.commit_group;")
#define CP_WAIT1()  asm volatile("cp.async.wait_group 1;")
#define CP_WAIT2()  asm volatile("cp.async.wait_group 2;")

// =================================================================
// pack kernels
// =================================================================
// X: fp32 [s][1024] -> bf16 hi/lo pairs + fp16 pairs
__global__ __launch_bounds__(256) void pack_x(
    const float* __restrict__ in, uint32_t* __restrict__ oh,
    uint32_t* __restrict__ ol, uint32_t* __restrict__ of, int n4)
{
    int i = blockIdx.x * 256 + threadIdx.x;
    if (i < n4) {
        float4 v = ((const float4*)in)[i];
        uint32_t h0, l0, h1, l1;
        pack2(v.x, v.y, h0, l0);
        pack2(v.z, v.w, h1, l1);
        ((uint2*)oh)[i] = make_uint2(h0, h1);
        ((uint2*)ol)[i] = make_uint2(l0, l1);
        ((uint2*)of)[i] = make_uint2(packh2(v.x, v.y), packh2(v.z, v.w));
    }
}

// per-head W [H][K][64] -> bf16 hi/lo [h*64+e][K/2]
__global__ __launch_bounds__(256) void pack_w(
    const float* __restrict__ in, uint32_t* __restrict__ oh,
    uint32_t* __restrict__ ol)
{
    int i  = blockIdx.x * 256 + threadIdx.x;
    int e  = i & 63;
    int kp = (i >> 6) & 511;
    int h  = i >> 15;
    float x0 = in[((size_t)h * 1024 + 2 * kp)     * 64 + e];
    float x1 = in[((size_t)h * 1024 + 2 * kp + 1) * 64 + e];
    uint32_t hi, lo;
    pack2(x0, x1, hi, lo);
    oh[((size_t)h * 64 + e) * 512 + kp] = hi;
    ol[((size_t)h * 64 + e) * 512 + kp] = lo;
}

// per-head W [H][K][64] -> fp16 [h*64+e][K/2]
__global__ __launch_bounds__(256) void pack_wf_head(
    const float* __restrict__ in, uint32_t* __restrict__ of)
{
    int i  = blockIdx.x * 256 + threadIdx.x;
    int e  = i & 63;
    int kp = (i >> 6) & 511;
    int h  = i >> 15;
    float x0 = in[((size_t)h * 1024 + 2 * kp)     * 64 + e];
    float x1 = in[((size_t)h * 1024 + 2 * kp + 1) * 64 + e];
    of[((size_t)h * 64 + e) * 512 + kp] = packh2(x0, x1);
}

// row-major W [N][K] -> fp16 [N][K/2]
__global__ __launch_bounds__(256) void pack_wf_row(
    const float* __restrict__ in, uint32_t* __restrict__ of, int npair)
{
    int i = blockIdx.x * 256 + threadIdx.x;
    if (i < npair) {
        float2 v = ((const float2*)in)[i];
        of[i] = packh2(v.x, v.y);
    }
}

// =================================================================
// Q+K projection (split-bf16, merged via blockIdx.z) — unchanged R8
// =================================================================
#define QKP 20
#define QSTG (128 * QKP)

__global__ __launch_bounds__(256, 2) void gemm_qk(
    const uint32_t* __restrict__ Ah2g, const uint32_t* __restrict__ Al2g,
    const uint32_t* __restrict__ BQh, const uint32_t* __restrict__ BQl,
    const uint32_t* __restrict__ BKh, const uint32_t* __restrict__ BKl,
    uint32_t* __restrict__ OQh, uint32_t* __restrict__ OQl,
    uint32_t* __restrict__ OKh, uint32_t* __restrict__ OKl)
{
    extern __shared__ float sm[];
    uint32_t* smu = (uint32_t*)sm;

    const int t    = threadIdx.x;
    const int lane = t & 31;
    const int w    = t >> 5;
    const int grp  = lane >> 2;
    const int qd   = lane & 3;
    const int wm   = (w & 3) * 32;
    const int wn   = (w >> 2) * 64;
    const int m0   = blockIdx.y * 128;
    const int n0   = blockIdx.x * 128;

    const uint32_t* Bh2g = blockIdx.z ? BKh : BQh;
    const uint32_t* Bl2g = blockIdx.z ? BKl : BQl;
    uint32_t* Oh = blockIdx.z ? OKh : OQh;
    uint32_t* Ol = blockIdx.z ? OKl : OQl;

    float acc[2][8][4];
#pragma unroll
    for (int i = 0; i < 2; i++)
#pragma unroll
        for (int j = 0; j < 8; j++)
#pragma unroll
            for (int k = 0; k < 4; k++) acc[i][j][k] = 0.0f;

    const uint32_t sb = (uint32_t)__cvta_generic_to_shared(smu);

    auto issue = [&](int kt, int s) {
        const int kb = kt * 16;
        const uint32_t base = sb + (uint32_t)s * 4 * QSTG * 4;
#pragma unroll
        for (int i = t; i < 512; i += 256) {
            const int r = i >> 2, c = (i & 3) * 4;
            const uint32_t d = base + (r * QKP + c) * 4;
            cp16(d,                Ah2g + (size_t)(m0 + r) * 512 + kb + c);
            cp16(d + QSTG * 4,     Al2g + (size_t)(m0 + r) * 512 + kb + c);
            const size_t wo = (size_t)(n0 + r) * 512 + kb + c;
            cp16(d + 2 * QSTG * 4, Bh2g + wo);
            cp16(d + 3 * QSTG * 4, Bl2g + wo);
        }
    };

    issue(0, 0); CP_COMMIT();
    issue(1, 1); CP_COMMIT();

    for (int kt = 0; kt < 32; kt++) {
        CP_WAIT1();
        __syncthreads();
        const uint32_t* Ah = smu + (kt & 1) * 4 * QSTG;
        const uint32_t* Al = Ah + QSTG;
        const uint32_t* Bh = Ah + 2 * QSTG;
        const uint32_t* Bl = Ah + 3 * QSTG;

#pragma unroll
        for (int ks2 = 0; ks2 < 16; ks2 += 8) {
            uint32_t ah[2][4], al[2][4];
#pragma unroll
            for (int mt = 0; mt < 2; mt++) {
                const int r = (wm + mt * 16 + grp) * QKP;
                ah[mt][0] = Ah[r + ks2 + qd];
                ah[mt][1] = Ah[r + 8 * QKP + ks2 + qd];
                ah[mt][2] = Ah[r + ks2 + qd + 4];
                ah[mt][3] = Ah[r + 8 * QKP + ks2 + qd + 4];
                al[mt][0] = Al[r + ks2 + qd];
                al[mt][1] = Al[r + 8 * QKP + ks2 + qd];
                al[mt][2] = Al[r + ks2 + qd + 4];
                al[mt][3] = Al[r + 8 * QKP + ks2 + qd + 4];
            }
#pragma unroll
            for (int nt = 0; nt < 8; nt++) {
                const int rb = (wn + nt * 8 + grp) * QKP;
                uint32_t bh0 = Bh[rb + ks2 + qd];
                uint32_t bh1 = Bh[rb + ks2 + qd + 4];
                uint32_t bl0 = Bl[rb + ks2 + qd];
                uint32_t bl1 = Bl[rb + ks2 + qd + 4];
#pragma unroll
                for (int mt = 0; mt < 2; mt++) {
                    mma16(acc[mt][nt], ah[mt][0], ah[mt][1], ah[mt][2], ah[mt][3], bh0, bh1);
                    mma16(acc[mt][nt], ah[mt][0], ah[mt][1], ah[mt][2], ah[mt][3], bl0, bl1);
                    mma16(acc[mt][nt], al[mt][0], al[mt][1], al[mt][2], al[mt][3], bh0, bh1);
                }
            }
        }
        __syncthreads();
        if (kt + 2 < 32) issue(kt + 2, kt & 1);
        CP_COMMIT();
    }

#pragma unroll
    for (int mt = 0; mt < 2; mt++) {
#pragma unroll
        for (int nt = 0; nt < 8; nt++) {
            const int n  = n0 + wn + nt * 8 + 2 * qd;
            const int h  = n >> 6;
            const int dp = (n & 63) >> 1;
            const int mA = blockIdx.y * 128 + wm + mt * 16 + grp;
            const int mB = mA + 8;
            uint32_t hi, lo;
            pack2(acc[mt][nt][0], acc[mt][nt][1], hi, lo);
            Oh[((size_t)h * S_LEN + mA) * 32 + dp] = hi;
            Ol[((size_t)h * S_LEN + mA) * 32 + dp] = lo;
            pack2(acc[mt][nt][2], acc[mt][nt][3], hi, lo);
            Oh[((size_t)h * S_LEN + mB) * 32 + dp] = hi;
            Ol[((size_t)h * S_LEN + mB) * 32 + dp] = lo;
        }
    }
}

// =================================================================
// fp16 GEMM (V/WO/FF): operands pre-packed u32 half2 along k.
// 128x128 tile, BK=32 elems (16 u32), 3-stage cp.async.
// =================================================================
#define FP  20            // u32 row stride
#define FSTG (128 * FP)   // u32 per operand per stage

template<bool BIAS, bool RELU, bool RESID, bool OUTHEAD, bool OUTF32, bool OUTPACK>
__global__ __launch_bounds__(256, 2) void gemm_f16(
    const uint32_t* __restrict__ A2, const uint32_t* __restrict__ B2,
    const float* __restrict__ bias, const float* __restrict__ resid,
    float* __restrict__ Cf, uint32_t* __restrict__ Cp,
    int M, int N, int K)
{
    extern __shared__ float sm[];
    uint32_t* smu = (uint32_t*)sm;

    const int t    = threadIdx.x;
    const int lane = t & 31;
    const int w    = t >> 5;
    const int grp  = lane >> 2;
    const int qd   = lane & 3;
    const int wm   = (w & 3) * 32;
    const int wn   = (w >> 2) * 64;
    const int m0   = blockIdx.y * 128;
    const int n0   = blockIdx.x * 128;
    const int K2   = K >> 1;
    const int KT   = K >> 5;

    float acc[2][8][4];
#pragma unroll
    for (int i = 0; i < 2; i++)
#pragma unroll
        for (int j = 0; j < 8; j++)
#pragma unroll
            for (int k = 0; k < 4; k++) acc[i][j][k] = 0.0f;

    const uint32_t sb = (uint32_t)__cvta_generic_to_shared(smu);

    auto issue = [&](int kt, int s) {
        const int kb = kt * 16;
        const uint32_t base = sb + (uint32_t)s * 2 * FSTG * 4;
#pragma unroll
        for (int i = t; i < 512; i += 256) {
            const int r = i >> 2, c = (i & 3) * 4;
            const uint32_t d = base + (r * FP + c) * 4;
            cp16(d,            A2 + (size_t)(m0 + r) * K2 + kb + c);
            cp16(d + FSTG * 4, B2 + (size_t)(n0 + r) * K2 + kb + c);
        }
    };

    issue(0, 0); CP_COMMIT();
    issue(1, 1); CP_COMMIT();
    issue(2, 2); CP_COMMIT();

    for (int kt = 0; kt < KT; kt++) {
        const int s = kt % 3;
        CP_WAIT2();
        __syncthreads();
        const uint32_t* Ab = smu + s * 2 * FSTG;
        const uint32_t* Bb = Ab + FSTG;

#pragma unroll
        for (int ks2 = 0; ks2 < 16; ks2 += 8) {
            uint32_t af[2][4];
#pragma unroll
            for (int mt = 0; mt < 2; mt++) {
                const int r = (wm + mt * 16 + grp) * FP;
                af[mt][0] = Ab[r + ks2 + qd];
                af[mt][1] = Ab[r + 8 * FP + ks2 + qd];
                af[mt][2] = Ab[r + ks2 + qd + 4];
                af[mt][3] = Ab[r + 8 * FP + ks2 + qd + 4];
            }
#pragma unroll
            for (int nt = 0; nt < 8; nt++) {
                const int rb = (wn + nt * 8 + grp) * FP;
                uint32_t b0 = Bb[rb + ks2 + qd];
                uint32_t b1 = Bb[rb + ks2 + qd + 4];
#pragma unroll
                for (int mt = 0; mt < 2; mt++)
                    mma16h(acc[mt][nt], af[mt][0], af[mt][1], af[mt][2], af[mt][3], b0, b1);
            }
        }
        __syncthreads();
        if (kt + 3 < KT) issue(kt + 3, s);
        CP_COMMIT();
    }

#pragma unroll
    for (int mt = 0; mt < 2; mt++) {
#pragma unroll
        for (int nt = 0; nt < 8; nt++) {
            const int n  = n0 + wn + nt * 8 + 2 * qd;
            float2 v0 = make_float2(acc[mt][nt][0], acc[mt][nt][1]);
            float2 v1 = make_float2(acc[mt][nt][2], acc[mt][nt][3]);
            if (BIAS) {
                float2 bb = *(const float2*)&bias[n];
                v0.x += bb.x; v0.y += bb.y;
                v1.x += bb.x; v1.y += bb.y;
            }
            if (RELU) {
                v0.x = fmaxf(v0.x, 0.f); v0.y = fmaxf(v0.y, 0.f);
                v1.x = fmaxf(v1.x, 0.f); v1.y = fmaxf(v1.y, 0.f);
            }
            const int mA = m0 + wm + mt * 16 + grp;
            const int mB = mA + 8;
            if (RESID) {
                float2 r0 = *(const float2*)&resid[(size_t)mA * N + n];
                float2 r1 = *(const float2*)&resid[(size_t)mB * N + n];
                v0.x += r0.x; v0.y += r0.y;
                v1.x += r1.x; v1.y += r1.y;
            }
            if (OUTHEAD) {
                const int h = n >> 6;
                const int e = n & 63;
                *(float2*)&Cf[((size_t)h * M + mA) * 64 + e] = v0;
                *(float2*)&Cf[((size_t)h * M + mB) * 64 + e] = v1;
            } else if (OUTF32) {
                *(float2*)&Cf[(size_t)mA * N + n] = v0;
                *(float2*)&Cf[(size_t)mB * N + n] = v1;
            }
            if (OUTPACK) {
                Cp[(size_t)mA * (N >> 1) + (n >> 1)] = packh2(v0.x, v0.y);
                Cp[(size_t)mB * (N >> 1) + (n >> 1)] = packh2(v1.x, v1.y);
            }
        }
    }
}

// =================================================================
// Attention (R8 core; Z emitted fp16-packed)
// =================================================================
#define AP  72
#define KP2 36
#define QTILE (64 * KP2)

__global__ __launch_bounds__(256, 2) void attn_tc(
    const uint32_t* __restrict__ Qh2, const uint32_t* __restrict__ Ql2,
    const uint32_t* __restrict__ Kh2, const uint32_t* __restrict__ Kl2,
    const float* __restrict__ V, float* __restrict__ SA,
    uint32_t* __restrict__ Zf2, float* __restrict__ Lsum)
{
    extern __shared__ float sm[];
    uint32_t* Qh_s = (uint32_t*)sm;
    uint32_t* Ql_s = Qh_s + QTILE;
    uint32_t* Kh_s = Qh_s + 2 * QTILE;
    uint32_t* Kl_s = Qh_s + 3 * QTILE;
    float*    Vs   = sm + 4 * QTILE;
    float*    Ps   = Vs + 64 * AP;

    const int t    = threadIdx.x;
    const int lane = t & 31;
    const int w    = t >> 5;
    const int grp  = lane >> 2;
    const int qd   = lane & 3;
    const int wm   = (w >> 1) * 16;
    const int wn   = (w & 1) * 32;
    const int qt   = (int)gridDim.x - 1 - (int)blockIdx.x;
    const int h    = blockIdx.y;
    const int q0   = qt * 64;

    const float slope = exp2f(-0.5f * (float)(h + 1));
    const float* Vg = V + (size_t)h * S_LEN * D_HEAD;
    const uint32_t* Qhg = Qh2 + (size_t)h * S_LEN * 32;
    const uint32_t* Qlg = Ql2 + (size_t)h * S_LEN * 32;
    const uint32_t* Khg = Kh2 + (size_t)h * S_LEN * 32;
    const uint32_t* Klg = Kl2 + (size_t)h * S_LEN * 32;

    {
        const int r  = t >> 2;
        const int c8 = (t & 3) * 8;
        *(uint4*)&Qh_s[r * KP2 + c8]     = *(const uint4*)(Qhg + (size_t)(q0 + r) * 32 + c8);
        *(uint4*)&Qh_s[r * KP2 + c8 + 4] = *(const uint4*)(Qhg + (size_t)(q0 + r) * 32 + c8 + 4);
        *(uint4*)&Ql_s[r * KP2 + c8]     = *(const uint4*)(Qlg + (size_t)(q0 + r) * 32 + c8);
        *(uint4*)&Ql_s[r * KP2 + c8 + 4] = *(const uint4*)(Qlg + (size_t)(q0 + r) * 32 + c8 + 4);
    }

    float zacc[4][4];
#pragma unroll
    for (int i = 0; i < 4; i++)
#pragma unroll
        for (int j = 0; j < 4; j++) zacc[i][j] = 0.0f;
    float la = 0.0f, lb = 0.0f;

    const int iA = q0 + wm + grp;
    const int iB = iA + 8;

    for (int kt = 0; kt <= qt; kt++) {
        const int k0 = kt * 64;
        __syncthreads();
        {
            const int r  = t >> 2;
            const int c8 = (t & 3) * 8;
            *(uint4*)&Kh_s[r * KP2 + c8]     = *(const uint4*)(Khg + (size_t)(k0 + r) * 32 + c8);
            *(uint4*)&Kh_s[r * KP2 + c8 + 4] = *(const uint4*)(Khg + (size_t)(k0 + r) * 32 + c8 + 4);
            *(uint4*)&Kl_s[r * KP2 + c8]     = *(const uint4*)(Klg + (size_t)(k0 + r) * 32 + c8);
            *(uint4*)&Kl_s[r * KP2 + c8 + 4] = *(const uint4*)(Klg + (size_t)(k0 + r) * 32 + c8 + 4);
            const int dq = (t & 3) * 16;
            const float* vp = Vg + (size_t)(k0 + r) * 64 + dq;
            float vv[16];
            *(float4*)&vv[0]  = *(const float4*)(vp);
            *(float4*)&vv[4]  = *(const float4*)(vp + 4);
            *(float4*)&vv[8]  = *(const float4*)(vp + 8);
            *(float4*)&vv[12] = *(const float4*)(vp + 12);
#pragma unroll
            for (int j = 0; j < 16; j++)
                Vs[r * AP + dq + j] = to_tf32(vv[j]);
        }
        __syncthreads();

        float sacc[4][4];
#pragma unroll
        for (int i = 0; i < 4; i++)
#pragma unroll
            for (int j = 0; j < 4; j++) sacc[i][j] = 0.0f;

#pragma unroll
        for (int kp8 = 0; kp8 < 32; kp8 += 8) {
            const int rA = (wm + grp) * KP2;
            uint32_t ah0 = Qh_s[rA + kp8 + qd];
            uint32_t ah1 = Qh_s[rA + 8 * KP2 + kp8 + qd];
            uint32_t ah2 = Qh_s[rA + kp8 + qd + 4];
            uint32_t ah3 = Qh_s[rA + 8 * KP2 + kp8 + qd + 4];
            uint32_t al0 = Ql_s[rA + kp8 + qd];
            uint32_t al1 = Ql_s[rA + 8 * KP2 + kp8 + qd];
            uint32_t al2 = Ql_s[rA + kp8 + qd + 4];
            uint32_t al3 = Ql_s[rA + 8 * KP2 + kp8 + qd + 4];
#pragma unroll
            for (int nt = 0; nt < 4; nt++) {
                const int rb = (wn + nt * 8 + grp) * KP2;
                uint32_t bh0 = Kh_s[rb + kp8 + qd];
                uint32_t bh1 = Kh_s[rb + kp8 + qd + 4];
                uint32_t bl0 = Kl_s[rb + kp8 + qd];
                uint32_t bl1 = Kl_s[rb + kp8 + qd + 4];
                mma16(sacc[nt], ah0, ah1, ah2, ah3, bh0, bh1);
                mma16(sacc[nt], ah0, ah1, ah2, ah3, bl0, bl1);
                mma16(sacc[nt], al0, al1, al2, al3, bh0, bh1);
            }
        }

        const bool diag = (kt == qt);
#pragma unroll
        for (int nt = 0; nt < 4; nt++) {
            const int j0 = k0 + wn + nt * 8 + 2 * qd;
            float p0 = __expf(sacc[nt][0] * 0.125f - (float)(iA - j0) * slope);
            float p1 = __expf(sacc[nt][1] * 0.125f - (float)(iA - j0 - 1) * slope);
            float p2 = __expf(sacc[nt][2] * 0.125f - (float)(iB - j0) * slope);
            float p3 = __expf(sacc[nt][3] * 0.125f - (float)(iB - j0 - 1) * slope);
            if (diag) {
                if (j0     > iA) p0 = 0.0f;
                if (j0 + 1 > iA) p1 = 0.0f;
                if (j0     > iB) p2 = 0.0f;
                if (j0 + 1 > iB) p3 = 0.0f;
            }
            la += p0 + p1;
            lb += p2 + p3;
            if (SA) {
                *(float2*)&SA[((size_t)h * S_LEN + iA) * S_LEN + j0] = make_float2(p0, p1);
                *(float2*)&SA[((size_t)h * S_LEN + iB) * S_LEN + j0] = make_float2(p2, p3);
            }
            const int pc = wn + nt * 8 + 2 * qd;
            *(float2*)&Ps[(wm + grp)     * AP + pc] = make_float2(to_tf32(p0), to_tf32(p1));
            *(float2*)&Ps[(wm + grp + 8) * AP + pc] = make_float2(to_tf32(p2), to_tf32(p3));
        }
        __syncthreads();

#pragma unroll
        for (int ks = 0; ks < 64; ks += 8) {
            float a0 = Ps[(wm + grp)     * AP + ks + qd];
            float a1 = Ps[(wm + grp + 8) * AP + ks + qd];
            float a2 = Ps[(wm + grp)     * AP + ks + qd + 4];
            float a3 = Ps[(wm + grp + 8) * AP + ks + qd + 4];
#pragma unroll
            for (int nt = 0; nt < 4; nt++) {
                const int nv = wn + nt * 8 + grp;
                float b0 = Vs[(ks + qd)     * AP + nv];
                float b1 = Vs[(ks + qd + 4) * AP + nv];
                mma8f(zacc[nt], a0, a1, a2, a3, b0, b1);
            }
        }
    }

    la += __shfl_xor_sync(0xffffffffu, la, 1);
    la += __shfl_xor_sync(0xffffffffu, la, 2);
    lb += __shfl_xor_sync(0xffffffffu, lb, 1);
    lb += __shfl_xor_sync(0xffffffffu, lb, 2);
    __syncthreads();
    float* red = (float*)Kh_s;
    if (qd == 0) {
        red[(w & 1) * 64 + wm + grp]     = la;
        red[(w & 1) * 64 + wm + grp + 8] = lb;
    }
    __syncthreads();
    const float lA = red[wm + grp]     + red[64 + wm + grp];
    const float lB = red[wm + grp + 8] + red[64 + wm + grp + 8];
    if ((w & 1) == 0 && qd == 0) {
        Lsum[h * S_LEN + iA] = lA;
        Lsum[h * S_LEN + iB] = lB;
    }
    const float liA = 1.0f / lA;
    const float liB = 1.0f / lB;

#pragma unroll
    for (int nt = 0; nt < 4; nt++) {
        const int v0 = h * D_HEAD + wn + nt * 8 + 2 * qd;
        Zf2[(size_t)iA * (D_MODEL / 2) + (v0 >> 1)] =
            packh2(zacc[nt][0] * liA, zacc[nt][1] * liA);
        Zf2[(size_t)iB * (D_MODEL / 2) + (v0 >> 1)] =
            packh2(zacc[nt][2] * liB, zacc[nt][3] * liB);
    }
}

// ---- SA upper-triangle zero-fill (tile granularity) ----
__global__ __launch_bounds__(256) void sa_zero(float* __restrict__ SA)
{
    const int row   = blockIdx.x;
    const int i     = row & (S_LEN - 1);
    const int start = (((i >> 6) + 1) << 6) >> 2;
    float4* p = (float4*)(SA + (size_t)row * S_LEN);
    const float4 z4 = make_float4(0.f, 0.f, 0.f, 0.f);
    for (int v = start + threadIdx.x; v < S_LEN / 4; v += 256)
        p[v] = z4;
}

// ---- SA rescale: lower tiles only ----
__global__ __launch_bounds__(256) void sa_rescale(
    float* __restrict__ SA, const float* __restrict__ Lsum)
{
    const int row = blockIdx.x;
    const int i   = row & (S_LEN - 1);
    const int end = (((i >> 6) + 1) << 6) >> 2;
    const float linv = 1.0f / Lsum[row];
    float4* p = (float4*)(SA + (size_t)row * S_LEN);
    for (int v = threadIdx.x; v < end; v += 256) {
        float4 x = p[v];
        x.x *= linv; x.y *= linv; x.z *= linv; x.w *= linv;
        p[v] = x;
    }
}

// =================================================================
extern "C" void kernel_launch(void* const* d_in, const int* in_sizes, int n_in,
                              void* d_out, int out_size)
{
    const float* X   = (const float*)d_in[0];
    const float* WQ  = (const float*)d_in[1];
    const float* WK  = (const float*)d_in[2];
    const float* WV  = (const float*)d_in[3];
    const float* WOw = (const float*)d_in[4];
    const float* WOb = (const float*)d_in[5];
    const float* F1w = (const float*)d_in[6];
    const float* F1b = (const float*)d_in[7];
    const float* F2w = (const float*)d_in[8];
    const float* F2b = (const float*)d_in[9];

    float *Vp, *Ap, *Lp, *Dp;
    uint32_t *Xh2, *Xl2, *WQh2, *WQl2, *WKh2, *WKl2, *Qh2, *Ql2, *Kh2, *Kl2;
    uint32_t *Xf2, *WVf2, *WOf2, *F1f2, *F2f2, *Zf2, *ATTf2, *HIDf2;
    cudaGetSymbolAddress((void**)&Vp, g_V);
    cudaGetSymbolAddress((void**)&Ap, g_ATT);
    cudaGetSymbolAddress((void**)&Lp, g_L);
    cudaGetSymbolAddress((void**)&Dp, g_DUMMY);
    cudaGetSymbolAddress((void**)&Xh2, g_Xh2);
    cudaGetSymbolAddress((void**)&Xl2, g_Xl2);
    cudaGetSymbolAddress((void**)&WQh2, g_WQh2);
    cudaGetSymbolAddress((void**)&WQl2, g_WQl2);
    cudaGetSymbolAddress((void**)&WKh2, g_WKh2);
    cudaGetSymbolAddress((void**)&WKl2, g_WKl2);
    cudaGetSymbolAddress((void**)&Qh2, g_Qh2);
    cudaGetSymbolAddress((void**)&Ql2, g_Ql2);
    cudaGetSymbolAddress((void**)&Kh2, g_Kh2);
    cudaGetSymbolAddress((void**)&Kl2, g_Kl2);
    cudaGetSymbolAddress((void**)&Xf2, g_Xf2);
    cudaGetSymbolAddress((void**)&WVf2, g_WVf2);
    cudaGetSymbolAddress((void**)&WOf2, g_WOf2);
    cudaGetSymbolAddress((void**)&F1f2, g_F1f2);
    cudaGetSymbolAddress((void**)&F2f2, g_F2f2);
    cudaGetSymbolAddress((void**)&Zf2, g_Zf2);
    cudaGetSymbolAddress((void**)&ATTf2, g_ATTf2);
    cudaGetSymbolAddress((void**)&HIDf2, g_HIDf2);

    const size_t SA_EL = (size_t)N_HEADS * S_LEN * S_LEN;
    const size_t OV_EL = (size_t)S_LEN * D_MODEL;
    float* out = (float*)d_out;
    float* sa;
    float* ov;
    if ((size_t)out_size >= SA_EL + OV_EL)      { sa = out;     ov = out + SA_EL; }
    else if ((size_t)out_size >= SA_EL)         { sa = out;     ov = Dp; }
    else                                        { sa = nullptr; ov = out; }

    const int attn_smem = (4 * QTILE + 2 * 64 * AP) * 4;
    const int qk_smem   = 8 * QSTG * 4;
    const int f16_smem  = 6 * FSTG * 4;     // 61440
    cudaFuncSetAttribute(attn_tc, cudaFuncAttributeMaxDynamicSharedMemorySize, attn_smem);
    cudaFuncSetAttribute(gemm_qk, cudaFuncAttributeMaxDynamicSharedMemorySize, qk_smem);
    cudaFuncSetAttribute(gemm_f16<false,false,false,true ,false,false>,
                         cudaFuncAttributeMaxDynamicSharedMemorySize, f16_smem);
    cudaFuncSetAttribute(gemm_f16<true ,false,true ,false,true ,true >,
                         cudaFuncAttributeMaxDynamicSharedMemorySize, f16_smem);
    cudaFuncSetAttribute(gemm_f16<true ,true ,false,false,false,true >,
                         cudaFuncAttributeMaxDynamicSharedMemorySize, f16_smem);
    cudaFuncSetAttribute(gemm_f16<true ,false,true ,false,true ,false>,
                         cudaFuncAttributeMaxDynamicSharedMemorySize, f16_smem);

    static cudaStream_t s2 = nullptr;
    static cudaEvent_t evStart = nullptr, evAttn = nullptr, evSide = nullptr, evPack = nullptr;
    if (!s2) {
        cudaStreamCreateWithFlags(&s2, cudaStreamNonBlocking);
        cudaEventCreateWithFlags(&evStart, cudaEventDisableTiming);
        cudaEventCreateWithFlags(&evAttn,  cudaEventDisableTiming);
        cudaEventCreateWithFlags(&evSide,  cudaEventDisableTiming);
        cudaEventCreateWithFlags(&evPack,  cudaEventDisableTiming);
    }

    dim3 blk(256);

    // ---- side stream: SA zero + weight packs for the late GEMMs ----
    cudaEventRecord(evStart, 0);
    cudaStreamWaitEvent(s2, evStart, 0);
    if (sa)
        sa_zero<<<dim3(N_HEADS * S_LEN), blk, 0, s2>>>(sa);
    pack_wf_row<<<dim3(2048), blk, 0, s2>>>(WOw, WOf2, D_MODEL * D_MODEL / 2);
    pack_wf_row<<<dim3(8192), blk, 0, s2>>>(F1w, F1f2, D_FF * D_MODEL / 2);
    pack_wf_row<<<dim3(8192), blk, 0, s2>>>(F2w, F2f2, D_MODEL * D_FF / 2);
    cudaEventRecord(evPack, s2);

    // ---- main stream ----
    pack_x<<<dim3(2048), blk>>>(X, Xh2, Xl2, Xf2, S_LEN * D_MODEL / 4);
    pack_w<<<dim3(2048), blk>>>(WQ, WQh2, WQl2);
    pack_w<<<dim3(2048), blk>>>(WK, WKh2, WKl2);
    pack_wf_head<<<dim3(2048), blk>>>(WV, WVf2);

    gemm_qk<<<dim3(8, 16, 2), blk, qk_smem>>>(Xh2, Xl2,
        WQh2, WQl2, WKh2, WKl2, Qh2, Ql2, Kh2, Kl2);
    // V = X @ WV (fp16), head-layout fp32 out
    gemm_f16<false,false,false,true ,false,false><<<dim3(8, 16), blk, f16_smem>>>(
        Xf2, WVf2, nullptr, nullptr, Vp, nullptr, S_LEN, D_MODEL, D_MODEL);

    attn_tc<<<dim3(S_LEN / 64, N_HEADS), blk, attn_smem>>>(Qh2, Ql2, Kh2, Kl2, Vp, sa, Zf2, Lp);

    // ---- fork: rescale SA overlapping WO/FF ----
    cudaEventRecord(evAttn, 0);
    if (sa) {
        cudaStreamWaitEvent(s2, evAttn, 0);
        sa_rescale<<<dim3(N_HEADS * S_LEN), blk, 0, s2>>>(sa, Lp);
        cudaEventRecord(evSide, s2);
    }

    // weight packs must be done before WO/FF GEMMs
    cudaStreamWaitEvent(0, evPack, 0);

    // ATT = X + Z @ WO^T + b  (fp32 + packed fp16 out)
    gemm_f16<true ,false,true ,false,true ,true ><<<dim3(8, 16), blk, f16_smem>>>(
        Zf2, WOf2, WOb, X, Ap, ATTf2, S_LEN, D_MODEL, D_MODEL);
    // HID = relu(ATT @ FF1^T + b1)  (packed fp16 only)
    gemm_f16<true ,true ,false,false,false,true ><<<dim3(32, 16), blk, f16_smem>>>(
        ATTf2, F1f2, F1b, nullptr, nullptr, HIDf2, S_LEN, D_FF, D_MODEL);
    // out = ATT + HID @ FF2^T + b2  (fp32 out)
    gemm_f16<true ,false,true ,false,true ,false><<<dim3(8, 16), blk, f16_smem>>>(
        HIDf2, F2f2, F2b, Ap, ov, nullptr, S_LEN, D_MODEL, D_FF);

    if (sa)
        cudaStreamWaitEvent(0, evSide, 0);
}

// round 11
// speedup vs baseline: 4.5605x; 1.1466x over previous
#include <cuda_runtime.h>
#include <cstdint>

#define S_LEN   2048
#define D_MODEL 1024
#define N_HEADS 16
#define D_HEAD  64
#define D_FF    4096

// ---------------- scratch (no allocation allowed) ----------------
__device__ float    g_ATT[S_LEN * D_MODEL];
__device__ float    g_L[N_HEADS * S_LEN];
__device__ float    g_DUMMY[S_LEN * D_MODEL];
// bf16x2 (hi/lo) packed operands for Q/K path
__device__ uint32_t g_Xh2[S_LEN * (D_MODEL / 2)];
__device__ uint32_t g_Xl2[S_LEN * (D_MODEL / 2)];
__device__ uint32_t g_WQh2[N_HEADS * D_HEAD * (D_MODEL / 2)];
__device__ uint32_t g_WQl2[N_HEADS * D_HEAD * (D_MODEL / 2)];
__device__ uint32_t g_WKh2[N_HEADS * D_HEAD * (D_MODEL / 2)];
__device__ uint32_t g_WKl2[N_HEADS * D_HEAD * (D_MODEL / 2)];
__device__ uint32_t g_Qh2[N_HEADS * S_LEN * (D_HEAD / 2)];
__device__ uint32_t g_Ql2[N_HEADS * S_LEN * (D_HEAD / 2)];
__device__ uint32_t g_Kh2[N_HEADS * S_LEN * (D_HEAD / 2)];
__device__ uint32_t g_Kl2[N_HEADS * S_LEN * (D_HEAD / 2)];
// fp16x2 packed operands
__device__ uint32_t g_Xf2[S_LEN * (D_MODEL / 2)];
__device__ uint32_t g_WVf2[D_MODEL * (D_MODEL / 2)];
__device__ uint32_t g_WOf2[D_MODEL * (D_MODEL / 2)];
__device__ uint32_t g_F1f2[D_FF * (D_MODEL / 2)];
__device__ uint32_t g_F2f2[D_MODEL * (D_FF / 2)];
__device__ uint32_t g_Vf2[N_HEADS * S_LEN * (D_HEAD / 2)];
__device__ uint32_t g_Zf2[S_LEN * (D_MODEL / 2)];
__device__ uint32_t g_ATTf2[S_LEN * (D_MODEL / 2)];
__device__ uint32_t g_HIDf2[S_LEN * (D_FF / 2)];

// =================================================================
// helpers
// =================================================================
__device__ __forceinline__ void mma16(float* c,
    uint32_t a0, uint32_t a1, uint32_t a2, uint32_t a3,
    uint32_t b0, uint32_t b1)
{
    asm volatile(
        "mma.sync.aligned.m16n8k16.row.col.f32.bf16.bf16.f32 "
        "{%0,%1,%2,%3},{%4,%5,%6,%7},{%8,%9},{%0,%1,%2,%3};"
        : "+f"(c[0]), "+f"(c[1]), "+f"(c[2]), "+f"(c[3])
        : "r"(a0), "r"(a1), "r"(a2), "r"(a3), "r"(b0), "r"(b1));
}

__device__ __forceinline__ void mma16h(float* c,
    uint32_t a0, uint32_t a1, uint32_t a2, uint32_t a3,
    uint32_t b0, uint32_t b1)
{
    asm volatile(
        "mma.sync.aligned.m16n8k16.row.col.f32.f16.f16.f32 "
        "{%0,%1,%2,%3},{%4,%5,%6,%7},{%8,%9},{%0,%1,%2,%3};"
        : "+f"(c[0]), "+f"(c[1]), "+f"(c[2]), "+f"(c[3])
        : "r"(a0), "r"(a1), "r"(a2), "r"(a3), "r"(b0), "r"(b1));
}

__device__ __forceinline__ void ldsm_x4_t(
    uint32_t& r0, uint32_t& r1, uint32_t& r2, uint32_t& r3, uint32_t addr)
{
    asm volatile(
        "ldmatrix.sync.aligned.m8n8.x4.trans.shared.b16 {%0,%1,%2,%3}, [%4];"
        : "=r"(r0), "=r"(r1), "=r"(r2), "=r"(r3) : "r"(addr));
}

__device__ __forceinline__ void pack2(float x0, float x1, uint32_t& hi, uint32_t& lo) {
    asm("cvt.rn.bf16x2.f32 %0, %1, %2;" : "=r"(hi) : "f"(x1), "f"(x0));
    float f0 = __uint_as_float(hi << 16);
    float f1 = __uint_as_float(hi & 0xffff0000u);
    asm("cvt.rn.bf16x2.f32 %0, %1, %2;" : "=r"(lo) : "f"(x1 - f1), "f"(x0 - f0));
}

__device__ __forceinline__ uint32_t packh2(float x0, float x1) {
    uint32_t r;
    asm("cvt.rn.f16x2.f32 %0, %1, %2;" : "=r"(r) : "f"(x1), "f"(x0));
    return r;
}

__device__ __forceinline__ void cp16(uint32_t dst_smem, const void* src) {
    asm volatile("cp.async.cg.shared.global [%0], [%1], 16;"
                 :: "r"(dst_smem), "l"(src));
}
#define CP_COMMIT() asm volatile("cp.async.commit_group;")
#define CP_WAIT1()  asm volatile("cp.async.wait_group 1;")
#define CP_WAIT2()  asm volatile("cp.async.wait_group 2;")

// =================================================================
// pack kernels
// =================================================================
__global__ __launch_bounds__(256) void pack_x(
    const float* __restrict__ in, uint32_t* __restrict__ oh,
    uint32_t* __restrict__ ol, uint32_t* __restrict__ of, int n4)
{
    int i = blockIdx.x * 256 + threadIdx.x;
    if (i < n4) {
        float4 v = ((const float4*)in)[i];
        uint32_t h0, l0, h1, l1;
        pack2(v.x, v.y, h0, l0);
        pack2(v.z, v.w, h1, l1);
        ((uint2*)oh)[i] = make_uint2(h0, h1);
        ((uint2*)ol)[i] = make_uint2(l0, l1);
        ((uint2*)of)[i] = make_uint2(packh2(v.x, v.y), packh2(v.z, v.w));
    }
}

__global__ __launch_bounds__(256) void pack_w(
    const float* __restrict__ in, uint32_t* __restrict__ oh,
    uint32_t* __restrict__ ol)
{
    int i  = blockIdx.x * 256 + threadIdx.x;
    int e  = i & 63;
    int kp = (i >> 6) & 511;
    int h  = i >> 15;
    float x0 = in[((size_t)h * 1024 + 2 * kp)     * 64 + e];
    float x1 = in[((size_t)h * 1024 + 2 * kp + 1) * 64 + e];
    uint32_t hi, lo;
    pack2(x0, x1, hi, lo);
    oh[((size_t)h * 64 + e) * 512 + kp] = hi;
    ol[((size_t)h * 64 + e) * 512 + kp] = lo;
}

__global__ __launch_bounds__(256) void pack_wf_head(
    const float* __restrict__ in, uint32_t* __restrict__ of)
{
    int i  = blockIdx.x * 256 + threadIdx.x;
    int e  = i & 63;
    int kp = (i >> 6) & 511;
    int h  = i >> 15;
    float x0 = in[((size_t)h * 1024 + 2 * kp)     * 64 + e];
    float x1 = in[((size_t)h * 1024 + 2 * kp + 1) * 64 + e];
    of[((size_t)h * 64 + e) * 512 + kp] = packh2(x0, x1);
}

__global__ __launch_bounds__(256) void pack_wf_row(
    const float* __restrict__ in, uint32_t* __restrict__ of, int npair)
{
    int i = blockIdx.x * 256 + threadIdx.x;
    if (i < npair) {
        float2 v = ((const float2*)in)[i];
        of[i] = packh2(v.x, v.y);
    }
}

// =================================================================
// Q+K projection (split-bf16, merged via blockIdx.z)
// =================================================================
#define QKP 20
#define QSTG (128 * QKP)

__global__ __launch_bounds__(256, 2) void gemm_qk(
    const uint32_t* __restrict__ Ah2g, const uint32_t* __restrict__ Al2g,
    const uint32_t* __restrict__ BQh, const uint32_t* __restrict__ BQl,
    const uint32_t* __restrict__ BKh, const uint32_t* __restrict__ BKl,
    uint32_t* __restrict__ OQh, uint32_t* __restrict__ OQl,
    uint32_t* __restrict__ OKh, uint32_t* __restrict__ OKl)
{
    extern __shared__ float sm[];
    uint32_t* smu = (uint32_t*)sm;

    const int t    = threadIdx.x;
    const int lane = t & 31;
    const int w    = t >> 5;
    const int grp  = lane >> 2;
    const int qd   = lane & 3;
    const int wm   = (w & 3) * 32;
    const int wn   = (w >> 2) * 64;
    const int m0   = blockIdx.y * 128;
    const int n0   = blockIdx.x * 128;

    const uint32_t* Bh2g = blockIdx.z ? BKh : BQh;
    const uint32_t* Bl2g = blockIdx.z ? BKl : BQl;
    uint32_t* Oh = blockIdx.z ? OKh : OQh;
    uint32_t* Ol = blockIdx.z ? OKl : OQl;

    float acc[2][8][4];
#pragma unroll
    for (int i = 0; i < 2; i++)
#pragma unroll
        for (int j = 0; j < 8; j++)
#pragma unroll
            for (int k = 0; k < 4; k++) acc[i][j][k] = 0.0f;

    const uint32_t sb = (uint32_t)__cvta_generic_to_shared(smu);

    auto issue = [&](int kt, int s) {
        const int kb = kt * 16;
        const uint32_t base = sb + (uint32_t)s * 4 * QSTG * 4;
#pragma unroll
        for (int i = t; i < 512; i += 256) {
            const int r = i >> 2, c = (i & 3) * 4;
            const uint32_t d = base + (r * QKP + c) * 4;
            cp16(d,                Ah2g + (size_t)(m0 + r) * 512 + kb + c);
            cp16(d + QSTG * 4,     Al2g + (size_t)(m0 + r) * 512 + kb + c);
            const size_t wo = (size_t)(n0 + r) * 512 + kb + c;
            cp16(d + 2 * QSTG * 4, Bh2g + wo);
            cp16(d + 3 * QSTG * 4, Bl2g + wo);
        }
    };

    issue(0, 0); CP_COMMIT();
    issue(1, 1); CP_COMMIT();

    for (int kt = 0; kt < 32; kt++) {
        CP_WAIT1();
        __syncthreads();
        const uint32_t* Ah = smu + (kt & 1) * 4 * QSTG;
        const uint32_t* Al = Ah + QSTG;
        const uint32_t* Bh = Ah + 2 * QSTG;
        const uint32_t* Bl = Ah + 3 * QSTG;

#pragma unroll
        for (int ks2 = 0; ks2 < 16; ks2 += 8) {
            uint32_t ah[2][4], al[2][4];
#pragma unroll
            for (int mt = 0; mt < 2; mt++) {
                const int r = (wm + mt * 16 + grp) * QKP;
                ah[mt][0] = Ah[r + ks2 + qd];
                ah[mt][1] = Ah[r + 8 * QKP + ks2 + qd];
                ah[mt][2] = Ah[r + ks2 + qd + 4];
                ah[mt][3] = Ah[r + 8 * QKP + ks2 + qd + 4];
                al[mt][0] = Al[r + ks2 + qd];
                al[mt][1] = Al[r + 8 * QKP + ks2 + qd];
                al[mt][2] = Al[r + ks2 + qd + 4];
                al[mt][3] = Al[r + 8 * QKP + ks2 + qd + 4];
            }
#pragma unroll
            for (int nt = 0; nt < 8; nt++) {
                const int rb = (wn + nt * 8 + grp) * QKP;
                uint32_t bh0 = Bh[rb + ks2 + qd];
                uint32_t bh1 = Bh[rb + ks2 + qd + 4];
                uint32_t bl0 = Bl[rb + ks2 + qd];
                uint32_t bl1 = Bl[rb + ks2 + qd + 4];
#pragma unroll
                for (int mt = 0; mt < 2; mt++) {
                    mma16(acc[mt][nt], ah[mt][0], ah[mt][1], ah[mt][2], ah[mt][3], bh0, bh1);
                    mma16(acc[mt][nt], ah[mt][0], ah[mt][1], ah[mt][2], ah[mt][3], bl0, bl1);
                    mma16(acc[mt][nt], al[mt][0], al[mt][1], al[mt][2], al[mt][3], bh0, bh1);
                }
            }
        }
        __syncthreads();
        if (kt + 2 < 32) issue(kt + 2, kt & 1);
        CP_COMMIT();
    }

#pragma unroll
    for (int mt = 0; mt < 2; mt++) {
#pragma unroll
        for (int nt = 0; nt < 8; nt++) {
            const int n  = n0 + wn + nt * 8 + 2 * qd;
            const int h  = n >> 6;
            const int dp = (n & 63) >> 1;
            const int mA = blockIdx.y * 128 + wm + mt * 16 + grp;
            const int mB = mA + 8;
            uint32_t hi, lo;
            pack2(acc[mt][nt][0], acc[mt][nt][1], hi, lo);
            Oh[((size_t)h * S_LEN + mA) * 32 + dp] = hi;
            Ol[((size_t)h * S_LEN + mA) * 32 + dp] = lo;
            pack2(acc[mt][nt][2], acc[mt][nt][3], hi, lo);
            Oh[((size_t)h * S_LEN + mB) * 32 + dp] = hi;
            Ol[((size_t)h * S_LEN + mB) * 32 + dp] = lo;
        }
    }
}

// =================================================================
// fp16 GEMM: operands pre-packed u32 half2 along k.
// =================================================================
#define FP  20
#define FSTG (128 * FP)

template<bool BIAS, bool RELU, bool RESID, bool OUTF32, bool OUTPACK, bool OUTPACKHEAD>
__global__ __launch_bounds__(256, 2) void gemm_f16(
    const uint32_t* __restrict__ A2, const uint32_t* __restrict__ B2,
    const float* __restrict__ bias, const float* __restrict__ resid,
    float* __restrict__ Cf, uint32_t* __restrict__ Cp,
    int M, int N, int K)
{
    extern __shared__ float sm[];
    uint32_t* smu = (uint32_t*)sm;

    const int t    = threadIdx.x;
    const int lane = t & 31;
    const int w    = t >> 5;
    const int grp  = lane >> 2;
    const int qd   = lane & 3;
    const int wm   = (w & 3) * 32;
    const int wn   = (w >> 2) * 64;
    const int m0   = blockIdx.y * 128;
    const int n0   = blockIdx.x * 128;
    const int K2   = K >> 1;
    const int KT   = K >> 5;

    float acc[2][8][4];
#pragma unroll
    for (int i = 0; i < 2; i++)
#pragma unroll
        for (int j = 0; j < 8; j++)
#pragma unroll
            for (int k = 0; k < 4; k++) acc[i][j][k] = 0.0f;

    const uint32_t sb = (uint32_t)__cvta_generic_to_shared(smu);

    auto issue = [&](int kt, int s) {
        const int kb = kt * 16;
        const uint32_t base = sb + (uint32_t)s * 2 * FSTG * 4;
#pragma unroll
        for (int i = t; i < 512; i += 256) {
            const int r = i >> 2, c = (i & 3) * 4;
            const uint32_t d = base + (r * FP + c) * 4;
            cp16(d,            A2 + (size_t)(m0 + r) * K2 + kb + c);
            cp16(d + FSTG * 4, B2 + (size_t)(n0 + r) * K2 + kb + c);
        }
    };

    issue(0, 0); CP_COMMIT();
    issue(1, 1); CP_COMMIT();
    issue(2, 2); CP_COMMIT();

    for (int kt = 0; kt < KT; kt++) {
        const int s = kt % 3;
        CP_WAIT2();
        __syncthreads();
        const uint32_t* Ab = smu + s * 2 * FSTG;
        const uint32_t* Bb = Ab + FSTG;

#pragma unroll
        for (int ks2 = 0; ks2 < 16; ks2 += 8) {
            uint32_t af[2][4];
#pragma unroll
            for (int mt = 0; mt < 2; mt++) {
                const int r = (wm + mt * 16 + grp) * FP;
                af[mt][0] = Ab[r + ks2 + qd];
                af[mt][1] = Ab[r + 8 * FP + ks2 + qd];
                af[mt][2] = Ab[r + ks2 + qd + 4];
                af[mt][3] = Ab[r + 8 * FP + ks2 + qd + 4];
            }
#pragma unroll
            for (int nt = 0; nt < 8; nt++) {
                const int rb = (wn + nt * 8 + grp) * FP;
                uint32_t b0 = Bb[rb + ks2 + qd];
                uint32_t b1 = Bb[rb + ks2 + qd + 4];
#pragma unroll
                for (int mt = 0; mt < 2; mt++)
                    mma16h(acc[mt][nt], af[mt][0], af[mt][1], af[mt][2], af[mt][3], b0, b1);
            }
        }
        __syncthreads();
        if (kt + 3 < KT) issue(kt + 3, s);
        CP_COMMIT();
    }

#pragma unroll
    for (int mt = 0; mt < 2; mt++) {
#pragma unroll
        for (int nt = 0; nt < 8; nt++) {
            const int n  = n0 + wn + nt * 8 + 2 * qd;
            float2 v0 = make_float2(acc[mt][nt][0], acc[mt][nt][1]);
            float2 v1 = make_float2(acc[mt][nt][2], acc[mt][nt][3]);
            if (BIAS) {
                float2 bb = *(const float2*)&bias[n];
                v0.x += bb.x; v0.y += bb.y;
                v1.x += bb.x; v1.y += bb.y;
            }
            if (RELU) {
                v0.x = fmaxf(v0.x, 0.f); v0.y = fmaxf(v0.y, 0.f);
                v1.x = fmaxf(v1.x, 0.f); v1.y = fmaxf(v1.y, 0.f);
            }
            const int mA = m0 + wm + mt * 16 + grp;
            const int mB = mA + 8;
            if (RESID) {
                float2 r0 = *(const float2*)&resid[(size_t)mA * N + n];
                float2 r1 = *(const float2*)&resid[(size_t)mB * N + n];
                v0.x += r0.x; v0.y += r0.y;
                v1.x += r1.x; v1.y += r1.y;
            }
            if (OUTF32) {
                *(float2*)&Cf[(size_t)mA * N + n] = v0;
                *(float2*)&Cf[(size_t)mB * N + n] = v1;
            }
            if (OUTPACK) {
                Cp[(size_t)mA * (N >> 1) + (n >> 1)] = packh2(v0.x, v0.y);
                Cp[(size_t)mB * (N >> 1) + (n >> 1)] = packh2(v1.x, v1.y);
            }
            if (OUTPACKHEAD) {
                const int h  = n >> 6;
                const int dp = (n & 63) >> 1;
                Cp[((size_t)h * M + mA) * 32 + dp] = packh2(v0.x, v0.y);
                Cp[((size_t)h * M + mB) * 32 + dp] = packh2(v1.x, v1.y);
            }
        }
    }
}

// =================================================================
// Attention: split-bf16 scores + fp16 z (ldmatrix.trans V),
// 2-stage cp.async K/V pipeline.
// smem layout (u32): Qh[64*36] Ql[64*36] | stage{0,1}: Kh[64*36] Kl[64*36] Vf[64*36] | Ps2[64*36]
// =================================================================
#define KP2 36
#define ATILE (64 * KP2)     // 2304 u32
#define ASTAGE (3 * ATILE)   // per pipeline stage
#define ATTN_SMEM_U32 (2 * ATILE + 2 * ASTAGE + ATILE)   // 20736

__global__ __launch_bounds__(256, 2) void attn_tc(
    const uint32_t* __restrict__ Qh2, const uint32_t* __restrict__ Ql2,
    const uint32_t* __restrict__ Kh2, const uint32_t* __restrict__ Kl2,
    const uint32_t* __restrict__ Vf2g, float* __restrict__ SA,
    uint32_t* __restrict__ Zf2, float* __restrict__ Lsum)
{
    extern __shared__ float sm[];
    uint32_t* smu  = (uint32_t*)sm;
    uint32_t* Qh_s = smu;
    uint32_t* Ql_s = smu + ATILE;
    uint32_t* Ps2  = smu + 2 * ATILE + 2 * ASTAGE;

    const int t    = threadIdx.x;
    const int lane = t & 31;
    const int w    = t >> 5;
    const int grp  = lane >> 2;
    const int qd   = lane & 3;
    const int wm   = (w >> 1) * 16;
    const int wn   = (w & 1) * 32;
    const int qt   = (int)gridDim.x - 1 - (int)blockIdx.x;   // heavy first
    const int h    = blockIdx.y;
    const int q0   = qt * 64;

    const float slope = exp2f(-0.5f * (float)(h + 1));
    const uint32_t* Qhg = Qh2 + (size_t)h * S_LEN * 32;
    const uint32_t* Qlg = Ql2 + (size_t)h * S_LEN * 32;
    const uint32_t* Khg = Kh2 + (size_t)h * S_LEN * 32;
    const uint32_t* Klg = Kl2 + (size_t)h * S_LEN * 32;
    const uint32_t* Vfg = Vf2g + (size_t)h * S_LEN * 32;

    const uint32_t sb = (uint32_t)__cvta_generic_to_shared(smu);

    auto issueif = [&](int kt) {
        if (kt <= qt) {
            const int s = kt & 1;
            const uint32_t base = sb + (uint32_t)(2 * ATILE + s * ASTAGE) * 4;
            const int k0 = kt * 64;
#pragma unroll
            for (int i = t; i < 512; i += 256) {
                const int r = i >> 3, c = (i & 7) * 4;
                const uint32_t d = base + (r * KP2 + c) * 4;
                cp16(d,                 Khg + (size_t)(k0 + r) * 32 + c);
                cp16(d + ATILE * 4,     Klg + (size_t)(k0 + r) * 32 + c);
                cp16(d + 2 * ATILE * 4, Vfg + (size_t)(k0 + r) * 32 + c);
            }
        }
        CP_COMMIT();
    };

    // load Q tile (plain vector loads, once)
    {
        const int r  = t >> 2;
        const int c8 = (t & 3) * 8;
        *(uint4*)&Qh_s[r * KP2 + c8]     = *(const uint4*)(Qhg + (size_t)(q0 + r) * 32 + c8);
        *(uint4*)&Qh_s[r * KP2 + c8 + 4] = *(const uint4*)(Qhg + (size_t)(q0 + r) * 32 + c8 + 4);
        *(uint4*)&Ql_s[r * KP2 + c8]     = *(const uint4*)(Qlg + (size_t)(q0 + r) * 32 + c8);
        *(uint4*)&Ql_s[r * KP2 + c8 + 4] = *(const uint4*)(Qlg + (size_t)(q0 + r) * 32 + c8 + 4);
    }

    issueif(0);
    issueif(1);

    float zacc[4][4];
#pragma unroll
    for (int i = 0; i < 4; i++)
#pragma unroll
        for (int j = 0; j < 4; j++) zacc[i][j] = 0.0f;
    float la = 0.0f, lb = 0.0f;

    const int iA = q0 + wm + grp;
    const int iB = iA + 8;

    // ldmatrix lane geometry (fixed per thread)
    const int lrow = (lane & 7) + ((lane >> 3) & 1) * 8;
    const int lcol = wn + ((lane >> 4) & 1) * 8;     // halfs within row

    for (int kt = 0; kt <= qt; kt++) {
        const int s = kt & 1;
        const uint32_t* Kh_s = smu + 2 * ATILE + s * ASTAGE;
        const uint32_t* Kl_s = Kh_s + ATILE;
        const uint32_t  vbase = sb + (uint32_t)(2 * ATILE + s * ASTAGE + 2 * ATILE) * 4;
        const int k0 = kt * 64;

        CP_WAIT1();
        __syncthreads();      // stage s data visible to all

        // ---- scores: split-bf16, 3 mma per k16 ----
        float sacc[4][4];
#pragma unroll
        for (int i = 0; i < 4; i++)
#pragma unroll
            for (int j = 0; j < 4; j++) sacc[i][j] = 0.0f;

#pragma unroll
        for (int kp8 = 0; kp8 < 32; kp8 += 8) {
            const int rA = (wm + grp) * KP2;
            uint32_t ah0 = Qh_s[rA + kp8 + qd];
            uint32_t ah1 = Qh_s[rA + 8 * KP2 + kp8 + qd];
            uint32_t ah2 = Qh_s[rA + kp8 + qd + 4];
            uint32_t ah3 = Qh_s[rA + 8 * KP2 + kp8 + qd + 4];
            uint32_t al0 = Ql_s[rA + kp8 + qd];
            uint32_t al1 = Ql_s[rA + 8 * KP2 + kp8 + qd];
            uint32_t al2 = Ql_s[rA + kp8 + qd + 4];
            uint32_t al3 = Ql_s[rA + 8 * KP2 + kp8 + qd + 4];
#pragma unroll
            for (int nt = 0; nt < 4; nt++) {
                const int rb = (wn + nt * 8 + grp) * KP2;
                uint32_t bh0 = Kh_s[rb + kp8 + qd];
                uint32_t bh1 = Kh_s[rb + kp8 + qd + 4];
                uint32_t bl0 = Kl_s[rb + kp8 + qd];
                uint32_t bl1 = Kl_s[rb + kp8 + qd + 4];
                mma16(sacc[nt], ah0, ah1, ah2, ah3, bh0, bh1);
                mma16(sacc[nt], ah0, ah1, ah2, ah3, bl0, bl1);
                mma16(sacc[nt], al0, al1, al2, al3, bh0, bh1);
            }
        }

        // ---- epilogue: exp, SA store, l-sums, packed P to smem ----
        const bool diag = (kt == qt);
#pragma unroll
        for (int nt = 0; nt < 4; nt++) {
            const int j0 = k0 + wn + nt * 8 + 2 * qd;
            float p0 = __expf(sacc[nt][0] * 0.125f - (float)(iA - j0) * slope);
            float p1 = __expf(sacc[nt][1] * 0.125f - (float)(iA - j0 - 1) * slope);
            float p2 = __expf(sacc[nt][2] * 0.125f - (float)(iB - j0) * slope);
            float p3 = __expf(sacc[nt][3] * 0.125f - (float)(iB - j0 - 1) * slope);
            if (diag) {
                if (j0     > iA) p0 = 0.0f;
                if (j0 + 1 > iA) p1 = 0.0f;
                if (j0     > iB) p2 = 0.0f;
                if (j0 + 1 > iB) p3 = 0.0f;
            }
            la += p0 + p1;
            lb += p2 + p3;
            if (SA) {
                *(float2*)&SA[((size_t)h * S_LEN + iA) * S_LEN + j0] = make_float2(p0, p1);
                *(float2*)&SA[((size_t)h * S_LEN + iB) * S_LEN + j0] = make_float2(p2, p3);
            }
            const int pcol = (wn >> 1) + nt * 4 + qd;
            Ps2[(wm + grp)     * KP2 + pcol] = packh2(p0, p1);
            Ps2[(wm + grp + 8) * KP2 + pcol] = packh2(p2, p3);
        }
        __syncthreads();      // Ps2 visible; K reads done

        // ---- z += P V  (fp16; V via ldmatrix.trans) ----
#pragma unroll
        for (int ks2 = 0; ks2 < 4; ks2++) {
            const int rA = (wm + grp) * KP2 + ks2 * 8;
            uint32_t a0 = Ps2[rA + qd];
            uint32_t a1 = Ps2[rA + 8 * KP2 + qd];
            uint32_t a2 = Ps2[rA + qd + 4];
            uint32_t a3 = Ps2[rA + 8 * KP2 + qd + 4];
#pragma unroll
            for (int ntp = 0; ntp < 2; ntp++) {
                uint32_t addr = vbase + (uint32_t)((ks2 * 16 + lrow) * KP2) * 4
                              + (uint32_t)(lcol + ntp * 16) * 2;
                uint32_t b0, b1, b2, b3;
                ldsm_x4_t(b0, b1, b2, b3, addr);
                mma16h(zacc[2 * ntp],     a0, a1, a2, a3, b0, b1);
                mma16h(zacc[2 * ntp + 1], a0, a1, a2, a3, b2, b3);
            }
        }
        __syncthreads();      // V[s]/Ps2 reads done -> stage s reusable
        issueif(kt + 2);
    }

    // ---- row-sum reduction across quad + the two n-half warps ----
    la += __shfl_xor_sync(0xffffffffu, la, 1);
    la += __shfl_xor_sync(0xffffffffu, la, 2);
    lb += __shfl_xor_sync(0xffffffffu, lb, 1);
    lb += __shfl_xor_sync(0xffffffffu, lb, 2);
    __syncthreads();
    float* red = (float*)(smu + 2 * ATILE);   // reuse stage memory
    if (qd == 0) {
        red[(w & 1) * 64 + wm + grp]     = la;
        red[(w & 1) * 64 + wm + grp + 8] = lb;
    }
    __syncthreads();
    const float lA = red[wm + grp]     + red[64 + wm + grp];
    const float lB = red[wm + grp + 8] + red[64 + wm + grp + 8];
    if ((w & 1) == 0 && qd == 0) {
        Lsum[h * S_LEN + iA] = lA;
        Lsum[h * S_LEN + iB] = lB;
    }
    const float liA = 1.0f / lA;
    const float liB = 1.0f / lB;

#pragma unroll
    for (int nt = 0; nt < 4; nt++) {
        const int v0 = h * D_HEAD + wn + nt * 8 + 2 * qd;
        Zf2[(size_t)iA * (D_MODEL / 2) + (v0 >> 1)] =
            packh2(zacc[nt][0] * liA, zacc[nt][1] * liA);
        Zf2[(size_t)iB * (D_MODEL / 2) + (v0 >> 1)] =
            packh2(zacc[nt][2] * liB, zacc[nt][3] * liB);
    }
}

// ---- SA upper-triangle zero-fill (tile granularity) ----
__global__ __launch_bounds__(256) void sa_zero(float* __restrict__ SA)
{
    const int row   = blockIdx.x;
    const int i     = row & (S_LEN - 1);
    const int start = (((i >> 6) + 1) << 6) >> 2;
    float4* p = (float4*)(SA + (size_t)row * S_LEN);
    const float4 z4 = make_float4(0.f, 0.f, 0.f, 0.f);
    for (int v = start + threadIdx.x; v < S_LEN / 4; v += 256)
        p[v] = z4;
}

// ---- SA rescale: lower tiles only ----
__global__ __launch_bounds__(256) void sa_rescale(
    float* __restrict__ SA, const float* __restrict__ Lsum)
{
    const int row = blockIdx.x;
    const int i   = row & (S_LEN - 1);
    const int end = (((i >> 6) + 1) << 6) >> 2;
    const float linv = 1.0f / Lsum[row];
    float4* p = (float4*)(SA + (size_t)row * S_LEN);
    for (int v = threadIdx.x; v < end; v += 256) {
        float4 x = p[v];
        x.x *= linv; x.y *= linv; x.z *= linv; x.w *= linv;
        p[v] = x;
    }
}

// =================================================================
extern "C" void kernel_launch(void* const* d_in, const int* in_sizes, int n_in,
                              void* d_out, int out_size)
{
    const float* X   = (const float*)d_in[0];
    const float* WQ  = (const float*)d_in[1];
    const float* WK  = (const float*)d_in[2];
    const float* WV  = (const float*)d_in[3];
    const float* WOw = (const float*)d_in[4];
    const float* WOb = (const float*)d_in[5];
    const float* F1w = (const float*)d_in[6];
    const float* F1b = (const float*)d_in[7];
    const float* F2w = (const float*)d_in[8];
    const float* F2b = (const float*)d_in[9];

    float *Ap, *Lp, *Dp;
    uint32_t *Xh2, *Xl2, *WQh2, *WQl2, *WKh2, *WKl2, *Qh2, *Ql2, *Kh2, *Kl2;
    uint32_t *Xf2, *WVf2, *WOf2, *F1f2, *F2f2, *Vf2, *Zf2, *ATTf2, *HIDf2;
    cudaGetSymbolAddress((void**)&Ap, g_ATT);
    cudaGetSymbolAddress((void**)&Lp, g_L);
    cudaGetSymbolAddress((void**)&Dp, g_DUMMY);
    cudaGetSymbolAddress((void**)&Xh2, g_Xh2);
    cudaGetSymbolAddress((void**)&Xl2, g_Xl2);
    cudaGetSymbolAddress((void**)&WQh2, g_WQh2);
    cudaGetSymbolAddress((void**)&WQl2, g_WQl2);
    cudaGetSymbolAddress((void**)&WKh2, g_WKh2);
    cudaGetSymbolAddress((void**)&WKl2, g_WKl2);
    cudaGetSymbolAddress((void**)&Qh2, g_Qh2);
    cudaGetSymbolAddress((void**)&Ql2, g_Ql2);
    cudaGetSymbolAddress((void**)&Kh2, g_Kh2);
    cudaGetSymbolAddress((void**)&Kl2, g_Kl2);
    cudaGetSymbolAddress((void**)&Xf2, g_Xf2);
    cudaGetSymbolAddress((void**)&WVf2, g_WVf2);
    cudaGetSymbolAddress((void**)&WOf2, g_WOf2);
    cudaGetSymbolAddress((void**)&F1f2, g_F1f2);
    cudaGetSymbolAddress((void**)&F2f2, g_F2f2);
    cudaGetSymbolAddress((void**)&Vf2, g_Vf2);
    cudaGetSymbolAddress((void**)&Zf2, g_Zf2);
    cudaGetSymbolAddress((void**)&ATTf2, g_ATTf2);
    cudaGetSymbolAddress((void**)&HIDf2, g_HIDf2);

    const size_t SA_EL = (size_t)N_HEADS * S_LEN * S_LEN;
    const size_t OV_EL = (size_t)S_LEN * D_MODEL;
    float* out = (float*)d_out;
    float* sa;
    float* ov;
    if ((size_t)out_size >= SA_EL + OV_EL)      { sa = out;     ov = out + SA_EL; }
    else if ((size_t)out_size >= SA_EL)         { sa = out;     ov = Dp; }
    else                                        { sa = nullptr; ov = out; }

    const int attn_smem = ATTN_SMEM_U32 * 4;   // 82944
    const int qk_smem   = 8 * QSTG * 4;        // 81920
    const int f16_smem  = 6 * FSTG * 4;        // 61440
    cudaFuncSetAttribute(attn_tc, cudaFuncAttributeMaxDynamicSharedMemorySize, attn_smem);
    cudaFuncSetAttribute(gemm_qk, cudaFuncAttributeMaxDynamicSharedMemorySize, qk_smem);
    cudaFuncSetAttribute(gemm_f16<false,false,false,false,false,true >,
                         cudaFuncAttributeMaxDynamicSharedMemorySize, f16_smem);
    cudaFuncSetAttribute(gemm_f16<true ,false,true ,true ,true ,false>,
                         cudaFuncAttributeMaxDynamicSharedMemorySize, f16_smem);
    cudaFuncSetAttribute(gemm_f16<true ,true ,false,false,true ,false>,
                         cudaFuncAttributeMaxDynamicSharedMemorySize, f16_smem);
    cudaFuncSetAttribute(gemm_f16<true ,false,true ,true ,false,false>,
                         cudaFuncAttributeMaxDynamicSharedMemorySize, f16_smem);

    static cudaStream_t s2 = nullptr;
    static cudaEvent_t evStart = nullptr, evAttn = nullptr, evSide = nullptr, evPack = nullptr;
    if (!s2) {
        cudaStreamCreateWithFlags(&s2, cudaStreamNonBlocking);
        cudaEventCreateWithFlags(&evStart, cudaEventDisableTiming);
        cudaEventCreateWithFlags(&evAttn,  cudaEventDisableTiming);
        cudaEventCreateWithFlags(&evSide,  cudaEventDisableTiming);
        cudaEventCreateWithFlags(&evPack,  cudaEventDisableTiming);
    }

    dim3 blk(256);

    // ---- side stream: SA zero + weight packs for the late GEMMs ----
    cudaEventRecord(evStart, 0);
    cudaStreamWaitEvent(s2, evStart, 0);
    if (sa)
        sa_zero<<<dim3(N_HEADS * S_LEN), blk, 0, s2>>>(sa);
    pack_wf_row<<<dim3(2048), blk, 0, s2>>>(WOw, WOf2, D_MODEL * D_MODEL / 2);
    pack_wf_row<<<dim3(8192), blk, 0, s2>>>(F1w, F1f2, D_FF * D_MODEL / 2);
    pack_wf_row<<<dim3(8192), blk, 0, s2>>>(F2w, F2f2, D_MODEL * D_FF / 2);
    cudaEventRecord(evPack, s2);

    // ---- main stream ----
    pack_x<<<dim3(2048), blk>>>(X, Xh2, Xl2, Xf2, S_LEN * D_MODEL / 4);
    pack_w<<<dim3(2048), blk>>>(WQ, WQh2, WQl2);
    pack_w<<<dim3(2048), blk>>>(WK, WKh2, WKl2);
    pack_wf_head<<<dim3(2048), blk>>>(WV, WVf2);

    gemm_qk<<<dim3(8, 16, 2), blk, qk_smem>>>(Xh2, Xl2,
        WQh2, WQl2, WKh2, WKl2, Qh2, Ql2, Kh2, Kl2);
    // V = X @ WV (fp16), packed fp16 head layout out
    gemm_f16<false,false,false,false,false,true ><<<dim3(8, 16), blk, f16_smem>>>(
        Xf2, WVf2, nullptr, nullptr, nullptr, Vf2, S_LEN, D_MODEL, D_MODEL);

    attn_tc<<<dim3(S_LEN / 64, N_HEADS), blk, attn_smem>>>(
        Qh2, Ql2, Kh2, Kl2, Vf2, sa, Zf2, Lp);

    // ---- fork: rescale SA overlapping WO/FF ----
    cudaEventRecord(evAttn, 0);
    if (sa) {
        cudaStreamWaitEvent(s2, evAttn, 0);
        sa_rescale<<<dim3(N_HEADS * S_LEN), blk, 0, s2>>>(sa, Lp);
        cudaEventRecord(evSide, s2);
    }

    cudaStreamWaitEvent(0, evPack, 0);

    // ATT = X + Z @ WO^T + b  (fp32 + packed fp16 out)
    gemm_f16<true ,false,true ,true ,true ,false><<<dim3(8, 16), blk, f16_smem>>>(
        Zf2, WOf2, WOb, X, Ap, ATTf2, S_LEN, D_MODEL, D_MODEL);
    // HID = relu(ATT @ FF1^T + b1)  (packed fp16 only)
    gemm_f16<true ,true ,false,false,true ,false><<<dim3(32, 16), blk, f16_smem>>>(
        ATTf2, F1f2, F1b, nullptr, nullptr, HIDf2, S_LEN, D_FF, D_MODEL);
    // out = ATT + HID @ FF2^T + b2  (fp32 out)
    gemm_f16<true ,false,true ,true ,false,false><<<dim3(8, 16), blk, f16_smem>>>(
        HIDf2, F2f2, F2b, Ap, ov, nullptr, S_LEN, D_MODEL, D_FF);

    if (sa)
        cudaStreamWaitEvent(0, evSide, 0);
}

// round 12
// speedup vs baseline: 4.6065x; 1.0101x over previous
#include <cuda_runtime.h>
#include <cstdint>

#define S_LEN   2048
#define D_MODEL 1024
#define N_HEADS 16
#define D_HEAD  64
#define D_FF    4096

// ---------------- scratch (no allocation allowed) ----------------
__device__ float    g_ATT[S_LEN * D_MODEL];
__device__ float    g_L[N_HEADS * S_LEN];
__device__ float    g_DUMMY[S_LEN * D_MODEL];
// bf16x2 (hi/lo) packed operands for Q/K path
__device__ uint32_t g_Xh2[S_LEN * (D_MODEL / 2)];
__device__ uint32_t g_Xl2[S_LEN * (D_MODEL / 2)];
__device__ uint32_t g_WQh2[N_HEADS * D_HEAD * (D_MODEL / 2)];
__device__ uint32_t g_WQl2[N_HEADS * D_HEAD * (D_MODEL / 2)];
__device__ uint32_t g_WKh2[N_HEADS * D_HEAD * (D_MODEL / 2)];
__device__ uint32_t g_WKl2[N_HEADS * D_HEAD * (D_MODEL / 2)];
__device__ uint32_t g_Qh2[N_HEADS * S_LEN * (D_HEAD / 2)];
__device__ uint32_t g_Ql2[N_HEADS * S_LEN * (D_HEAD / 2)];
__device__ uint32_t g_Kh2[N_HEADS * S_LEN * (D_HEAD / 2)];
__device__ uint32_t g_Kl2[N_HEADS * S_LEN * (D_HEAD / 2)];
// fp16x2 packed operands
__device__ uint32_t g_Xf2[S_LEN * (D_MODEL / 2)];
__device__ uint32_t g_WVf2[D_MODEL * (D_MODEL / 2)];
__device__ uint32_t g_WOf2[D_MODEL * (D_MODEL / 2)];
__device__ uint32_t g_F1f2[D_FF * (D_MODEL / 2)];
__device__ uint32_t g_F2f2[D_MODEL * (D_FF / 2)];
__device__ uint32_t g_Vf2[N_HEADS * S_LEN * (D_HEAD / 2)];
__device__ uint32_t g_Zf2[S_LEN * (D_MODEL / 2)];
__device__ uint32_t g_ATTf2[S_LEN * (D_MODEL / 2)];
__device__ uint32_t g_HIDf2[S_LEN * (D_FF / 2)];

// =================================================================
// helpers
// =================================================================
__device__ __forceinline__ void mma16(float* c,
    uint32_t a0, uint32_t a1, uint32_t a2, uint32_t a3,
    uint32_t b0, uint32_t b1)
{
    asm volatile(
        "mma.sync.aligned.m16n8k16.row.col.f32.bf16.bf16.f32 "
        "{%0,%1,%2,%3},{%4,%5,%6,%7},{%8,%9},{%0,%1,%2,%3};"
        : "+f"(c[0]), "+f"(c[1]), "+f"(c[2]), "+f"(c[3])
        : "r"(a0), "r"(a1), "r"(a2), "r"(a3), "r"(b0), "r"(b1));
}

__device__ __forceinline__ void mma16h(float* c,
    uint32_t a0, uint32_t a1, uint32_t a2, uint32_t a3,
    uint32_t b0, uint32_t b1)
{
    asm volatile(
        "mma.sync.aligned.m16n8k16.row.col.f32.f16.f16.f32 "
        "{%0,%1,%2,%3},{%4,%5,%6,%7},{%8,%9},{%0,%1,%2,%3};"
        : "+f"(c[0]), "+f"(c[1]), "+f"(c[2]), "+f"(c[3])
        : "r"(a0), "r"(a1), "r"(a2), "r"(a3), "r"(b0), "r"(b1));
}

__device__ __forceinline__ void ldsm_x4_t(
    uint32_t& r0, uint32_t& r1, uint32_t& r2, uint32_t& r3, uint32_t addr)
{
    asm volatile(
        "ldmatrix.sync.aligned.m8n8.x4.trans.shared.b16 {%0,%1,%2,%3}, [%4];"
        : "=r"(r0), "=r"(r1), "=r"(r2), "=r"(r3) : "r"(addr));
}

__device__ __forceinline__ void pack2(float x0, float x1, uint32_t& hi, uint32_t& lo) {
    asm("cvt.rn.bf16x2.f32 %0, %1, %2;" : "=r"(hi) : "f"(x1), "f"(x0));
    float f0 = __uint_as_float(hi << 16);
    float f1 = __uint_as_float(hi & 0xffff0000u);
    asm("cvt.rn.bf16x2.f32 %0, %1, %2;" : "=r"(lo) : "f"(x1 - f1), "f"(x0 - f0));
}

__device__ __forceinline__ uint32_t packh2(float x0, float x1) {
    uint32_t r;
    asm("cvt.rn.f16x2.f32 %0, %1, %2;" : "=r"(r) : "f"(x1), "f"(x0));
    return r;
}

__device__ __forceinline__ void cp16(uint32_t dst_smem, const void* src) {
    asm volatile("cp.async.cg.shared.global [%0], [%1], 16;"
                 :: "r"(dst_smem), "l"(src));
}
#define CP_COMMIT() asm volatile("cp.async.commit_group;")
#define CP_WAIT1()  asm volatile("cp.async.wait_group 1;")
#define CP_WAIT2()  asm volatile("cp.async.wait_group 2;")

// =================================================================
// pack kernels
// =================================================================
__global__ __launch_bounds__(256) void pack_x(
    const float* __restrict__ in, uint32_t* __restrict__ oh,
    uint32_t* __restrict__ ol, uint32_t* __restrict__ of, int n4)
{
    int i = blockIdx.x * 256 + threadIdx.x;
    if (i < n4) {
        float4 v = ((const float4*)in)[i];
        uint32_t h0, l0, h1, l1;
        pack2(v.x, v.y, h0, l0);
        pack2(v.z, v.w, h1, l1);
        ((uint2*)oh)[i] = make_uint2(h0, h1);
        ((uint2*)ol)[i] = make_uint2(l0, l1);
        ((uint2*)of)[i] = make_uint2(packh2(v.x, v.y), packh2(v.z, v.w));
    }
}

__global__ __launch_bounds__(256) void pack_w(
    const float* __restrict__ in, uint32_t* __restrict__ oh,
    uint32_t* __restrict__ ol)
{
    int i  = blockIdx.x * 256 + threadIdx.x;
    int e  = i & 63;
    int kp = (i >> 6) & 511;
    int h  = i >> 15;
    float x0 = in[((size_t)h * 1024 + 2 * kp)     * 64 + e];
    float x1 = in[((size_t)h * 1024 + 2 * kp + 1) * 64 + e];
    uint32_t hi, lo;
    pack2(x0, x1, hi, lo);
    oh[((size_t)h * 64 + e) * 512 + kp] = hi;
    ol[((size_t)h * 64 + e) * 512 + kp] = lo;
}

__global__ __launch_bounds__(256) void pack_wf_head(
    const float* __restrict__ in, uint32_t* __restrict__ of)
{
    int i  = blockIdx.x * 256 + threadIdx.x;
    int e  = i & 63;
    int kp = (i >> 6) & 511;
    int h  = i >> 15;
    float x0 = in[((size_t)h * 1024 + 2 * kp)     * 64 + e];
    float x1 = in[((size_t)h * 1024 + 2 * kp + 1) * 64 + e];
    of[((size_t)h * 64 + e) * 512 + kp] = packh2(x0, x1);
}

__global__ __launch_bounds__(256) void pack_wf_row(
    const float* __restrict__ in, uint32_t* __restrict__ of, int npair)
{
    int i = blockIdx.x * 256 + threadIdx.x;
    if (i < npair) {
        float2 v = ((const float2*)in)[i];
        of[i] = packh2(v.x, v.y);
    }
}

// =================================================================
// Q+K projection (split-bf16, merged via blockIdx.z)
// =================================================================
#define QKP 20
#define QSTG (128 * QKP)

__global__ __launch_bounds__(256, 2) void gemm_qk(
    const uint32_t* __restrict__ Ah2g, const uint32_t* __restrict__ Al2g,
    const uint32_t* __restrict__ BQh, const uint32_t* __restrict__ BQl,
    const uint32_t* __restrict__ BKh, const uint32_t* __restrict__ BKl,
    uint32_t* __restrict__ OQh, uint32_t* __restrict__ OQl,
    uint32_t* __restrict__ OKh, uint32_t* __restrict__ OKl)
{
    extern __shared__ float sm[];
    uint32_t* smu = (uint32_t*)sm;

    const int t    = threadIdx.x;
    const int lane = t & 31;
    const int w    = t >> 5;
    const int grp  = lane >> 2;
    const int qd   = lane & 3;
    const int wm   = (w & 3) * 32;
    const int wn   = (w >> 2) * 64;
    const int m0   = blockIdx.y * 128;
    const int n0   = blockIdx.x * 128;

    const uint32_t* Bh2g = blockIdx.z ? BKh : BQh;
    const uint32_t* Bl2g = blockIdx.z ? BKl : BQl;
    uint32_t* Oh = blockIdx.z ? OKh : OQh;
    uint32_t* Ol = blockIdx.z ? OKl : OQl;

    float acc[2][8][4];
#pragma unroll
    for (int i = 0; i < 2; i++)
#pragma unroll
        for (int j = 0; j < 8; j++)
#pragma unroll
            for (int k = 0; k < 4; k++) acc[i][j][k] = 0.0f;

    const uint32_t sb = (uint32_t)__cvta_generic_to_shared(smu);

    auto issue = [&](int kt, int s) {
        const int kb = kt * 16;
        const uint32_t base = sb + (uint32_t)s * 4 * QSTG * 4;
#pragma unroll
        for (int i = t; i < 512; i += 256) {
            const int r = i >> 2, c = (i & 3) * 4;
            const uint32_t d = base + (r * QKP + c) * 4;
            cp16(d,                Ah2g + (size_t)(m0 + r) * 512 + kb + c);
            cp16(d + QSTG * 4,     Al2g + (size_t)(m0 + r) * 512 + kb + c);
            const size_t wo = (size_t)(n0 + r) * 512 + kb + c;
            cp16(d + 2 * QSTG * 4, Bh2g + wo);
            cp16(d + 3 * QSTG * 4, Bl2g + wo);
        }
    };

    issue(0, 0); CP_COMMIT();
    issue(1, 1); CP_COMMIT();

    for (int kt = 0; kt < 32; kt++) {
        CP_WAIT1();
        __syncthreads();
        const uint32_t* Ah = smu + (kt & 1) * 4 * QSTG;
        const uint32_t* Al = Ah + QSTG;
        const uint32_t* Bh = Ah + 2 * QSTG;
        const uint32_t* Bl = Ah + 3 * QSTG;

#pragma unroll
        for (int ks2 = 0; ks2 < 16; ks2 += 8) {
            uint32_t ah[2][4], al[2][4];
#pragma unroll
            for (int mt = 0; mt < 2; mt++) {
                const int r = (wm + mt * 16 + grp) * QKP;
                ah[mt][0] = Ah[r + ks2 + qd];
                ah[mt][1] = Ah[r + 8 * QKP + ks2 + qd];
                ah[mt][2] = Ah[r + ks2 + qd + 4];
                ah[mt][3] = Ah[r + 8 * QKP + ks2 + qd + 4];
                al[mt][0] = Al[r + ks2 + qd];
                al[mt][1] = Al[r + 8 * QKP + ks2 + qd];
                al[mt][2] = Al[r + ks2 + qd + 4];
                al[mt][3] = Al[r + 8 * QKP + ks2 + qd + 4];
            }
#pragma unroll
            for (int nt = 0; nt < 8; nt++) {
                const int rb = (wn + nt * 8 + grp) * QKP;
                uint32_t bh0 = Bh[rb + ks2 + qd];
                uint32_t bh1 = Bh[rb + ks2 + qd + 4];
                uint32_t bl0 = Bl[rb + ks2 + qd];
                uint32_t bl1 = Bl[rb + ks2 + qd + 4];
#pragma unroll
                for (int mt = 0; mt < 2; mt++) {
                    mma16(acc[mt][nt], ah[mt][0], ah[mt][1], ah[mt][2], ah[mt][3], bh0, bh1);
                    mma16(acc[mt][nt], ah[mt][0], ah[mt][1], ah[mt][2], ah[mt][3], bl0, bl1);
                    mma16(acc[mt][nt], al[mt][0], al[mt][1], al[mt][2], al[mt][3], bh0, bh1);
                }
            }
        }
        __syncthreads();
        if (kt + 2 < 32) issue(kt + 2, kt & 1);
        CP_COMMIT();
    }

#pragma unroll
    for (int mt = 0; mt < 2; mt++) {
#pragma unroll
        for (int nt = 0; nt < 8; nt++) {
            const int n  = n0 + wn + nt * 8 + 2 * qd;
            const int h  = n >> 6;
            const int dp = (n & 63) >> 1;
            const int mA = blockIdx.y * 128 + wm + mt * 16 + grp;
            const int mB = mA + 8;
            uint32_t hi, lo;
            pack2(acc[mt][nt][0], acc[mt][nt][1], hi, lo);
            Oh[((size_t)h * S_LEN + mA) * 32 + dp] = hi;
            Ol[((size_t)h * S_LEN + mA) * 32 + dp] = lo;
            pack2(acc[mt][nt][2], acc[mt][nt][3], hi, lo);
            Oh[((size_t)h * S_LEN + mB) * 32 + dp] = hi;
            Ol[((size_t)h * S_LEN + mB) * 32 + dp] = lo;
        }
    }
}

// =================================================================
// fp16 GEMM: operands pre-packed u32 half2 along k.
// =================================================================
#define FP  20
#define FSTG (128 * FP)

template<bool BIAS, bool RELU, bool RESID, bool OUTF32, bool OUTPACK, bool OUTPACKHEAD>
__global__ __launch_bounds__(256, 2) void gemm_f16(
    const uint32_t* __restrict__ A2, const uint32_t* __restrict__ B2,
    const float* __restrict__ bias, const float* __restrict__ resid,
    float* __restrict__ Cf, uint32_t* __restrict__ Cp,
    int M, int N, int K)
{
    extern __shared__ float sm[];
    uint32_t* smu = (uint32_t*)sm;

    const int t    = threadIdx.x;
    const int lane = t & 31;
    const int w    = t >> 5;
    const int grp  = lane >> 2;
    const int qd   = lane & 3;
    const int wm   = (w & 3) * 32;
    const int wn   = (w >> 2) * 64;
    const int m0   = blockIdx.y * 128;
    const int n0   = blockIdx.x * 128;
    const int K2   = K >> 1;
    const int KT   = K >> 5;

    float acc[2][8][4];
#pragma unroll
    for (int i = 0; i < 2; i++)
#pragma unroll
        for (int j = 0; j < 8; j++)
#pragma unroll
            for (int k = 0; k < 4; k++) acc[i][j][k] = 0.0f;

    const uint32_t sb = (uint32_t)__cvta_generic_to_shared(smu);

    auto issue = [&](int kt, int s) {
        const int kb = kt * 16;
        const uint32_t base = sb + (uint32_t)s * 2 * FSTG * 4;
#pragma unroll
        for (int i = t; i < 512; i += 256) {
            const int r = i >> 2, c = (i & 3) * 4;
            const uint32_t d = base + (r * FP + c) * 4;
            cp16(d,            A2 + (size_t)(m0 + r) * K2 + kb + c);
            cp16(d + FSTG * 4, B2 + (size_t)(n0 + r) * K2 + kb + c);
        }
    };

    issue(0, 0); CP_COMMIT();
    issue(1, 1); CP_COMMIT();
    issue(2, 2); CP_COMMIT();

    for (int kt = 0; kt < KT; kt++) {
        const int s = kt % 3;
        CP_WAIT2();
        __syncthreads();
        const uint32_t* Ab = smu + s * 2 * FSTG;
        const uint32_t* Bb = Ab + FSTG;

#pragma unroll
        for (int ks2 = 0; ks2 < 16; ks2 += 8) {
            uint32_t af[2][4];
#pragma unroll
            for (int mt = 0; mt < 2; mt++) {
                const int r = (wm + mt * 16 + grp) * FP;
                af[mt][0] = Ab[r + ks2 + qd];
                af[mt][1] = Ab[r + 8 * FP + ks2 + qd];
                af[mt][2] = Ab[r + ks2 + qd + 4];
                af[mt][3] = Ab[r + 8 * FP + ks2 + qd + 4];
            }
#pragma unroll
            for (int nt = 0; nt < 8; nt++) {
                const int rb = (wn + nt * 8 + grp) * FP;
                uint32_t b0 = Bb[rb + ks2 + qd];
                uint32_t b1 = Bb[rb + ks2 + qd + 4];
#pragma unroll
                for (int mt = 0; mt < 2; mt++)
                    mma16h(acc[mt][nt], af[mt][0], af[mt][1], af[mt][2], af[mt][3], b0, b1);
            }
        }
        __syncthreads();
        if (kt + 3 < KT) issue(kt + 3, s);
        CP_COMMIT();
    }

#pragma unroll
    for (int mt = 0; mt < 2; mt++) {
#pragma unroll
        for (int nt = 0; nt < 8; nt++) {
            const int n  = n0 + wn + nt * 8 + 2 * qd;
            float2 v0 = make_float2(acc[mt][nt][0], acc[mt][nt][1]);
            float2 v1 = make_float2(acc[mt][nt][2], acc[mt][nt][3]);
            if (BIAS) {
                float2 bb = *(const float2*)&bias[n];
                v0.x += bb.x; v0.y += bb.y;
                v1.x += bb.x; v1.y += bb.y;
            }
            if (RELU) {
                v0.x = fmaxf(v0.x, 0.f); v0.y = fmaxf(v0.y, 0.f);
                v1.x = fmaxf(v1.x, 0.f); v1.y = fmaxf(v1.y, 0.f);
            }
            const int mA = m0 + wm + mt * 16 + grp;
            const int mB = mA + 8;
            if (RESID) {
                float2 r0 = *(const float2*)&resid[(size_t)mA * N + n];
                float2 r1 = *(const float2*)&resid[(size_t)mB * N + n];
                v0.x += r0.x; v0.y += r0.y;
                v1.x += r1.x; v1.y += r1.y;
            }
            if (OUTF32) {
                *(float2*)&Cf[(size_t)mA * N + n] = v0;
                *(float2*)&Cf[(size_t)mB * N + n] = v1;
            }
            if (OUTPACK) {
                Cp[(size_t)mA * (N >> 1) + (n >> 1)] = packh2(v0.x, v0.y);
                Cp[(size_t)mB * (N >> 1) + (n >> 1)] = packh2(v1.x, v1.y);
            }
            if (OUTPACKHEAD) {
                const int h  = n >> 6;
                const int dp = (n & 63) >> 1;
                Cp[((size_t)h * M + mA) * 32 + dp] = packh2(v0.x, v0.y);
                Cp[((size_t)h * M + mB) * 32 + dp] = packh2(v1.x, v1.y);
            }
        }
    }
}

// =================================================================
// Attention v3: split-bf16 scores; z in fp16 with REGISTER A-fragments
// (each warp reduces its own 32-key half over all 64 dims; one final
// cross-warp merge). 2-stage cp.async K/V pipeline, 2 syncs per tile.
// smem (u32): Qh[2304] Ql[2304] | stage{0,1}: Kh Kl Vf (3*2304 each)
// =================================================================
#define KP2 36
#define ATILE (64 * KP2)
#define ASTAGE (3 * ATILE)
#define ATTN_SMEM_U32 (2 * ATILE + 2 * ASTAGE)   // 18432 u32 = 73728 B

__global__ __launch_bounds__(256, 2) void attn_tc(
    const uint32_t* __restrict__ Qh2, const uint32_t* __restrict__ Ql2,
    const uint32_t* __restrict__ Kh2, const uint32_t* __restrict__ Kl2,
    const uint32_t* __restrict__ Vf2g, float* __restrict__ SA,
    uint32_t* __restrict__ Zf2, float* __restrict__ Lsum)
{
    extern __shared__ float sm[];
    uint32_t* smu  = (uint32_t*)sm;
    uint32_t* Qh_s = smu;
    uint32_t* Ql_s = smu + ATILE;

    const int t    = threadIdx.x;
    const int lane = t & 31;
    const int w    = t >> 5;
    const int grp  = lane >> 2;
    const int qd   = lane & 3;
    const int wm   = (w >> 1) * 16;
    const int wn   = (w & 1) * 32;       // this warp's key half
    const int qt   = (int)gridDim.x - 1 - (int)blockIdx.x;   // heavy first
    const int h    = blockIdx.y;
    const int q0   = qt * 64;

    const float slope = exp2f(-0.5f * (float)(h + 1));
    const uint32_t* Qhg = Qh2 + (size_t)h * S_LEN * 32;
    const uint32_t* Qlg = Ql2 + (size_t)h * S_LEN * 32;
    const uint32_t* Khg = Kh2 + (size_t)h * S_LEN * 32;
    const uint32_t* Klg = Kl2 + (size_t)h * S_LEN * 32;
    const uint32_t* Vfg = Vf2g + (size_t)h * S_LEN * 32;

    const uint32_t sb = (uint32_t)__cvta_generic_to_shared(smu);

    auto issueif = [&](int kt) {
        if (kt <= qt) {
            const int s = kt & 1;
            const uint32_t base = sb + (uint32_t)(2 * ATILE + s * ASTAGE) * 4;
            const int k0 = kt * 64;
#pragma unroll
            for (int i = t; i < 512; i += 256) {
                const int r = i >> 3, c = (i & 7) * 4;
                const uint32_t d = base + (r * KP2 + c) * 4;
                cp16(d,                 Khg + (size_t)(k0 + r) * 32 + c);
                cp16(d + ATILE * 4,     Klg + (size_t)(k0 + r) * 32 + c);
                cp16(d + 2 * ATILE * 4, Vfg + (size_t)(k0 + r) * 32 + c);
            }
        }
        CP_COMMIT();
    };

    // load Q tile (once)
    {
        const int r  = t >> 2;
        const int c8 = (t & 3) * 8;
        *(uint4*)&Qh_s[r * KP2 + c8]     = *(const uint4*)(Qhg + (size_t)(q0 + r) * 32 + c8);
        *(uint4*)&Qh_s[r * KP2 + c8 + 4] = *(const uint4*)(Qhg + (size_t)(q0 + r) * 32 + c8 + 4);
        *(uint4*)&Ql_s[r * KP2 + c8]     = *(const uint4*)(Qlg + (size_t)(q0 + r) * 32 + c8);
        *(uint4*)&Ql_s[r * KP2 + c8 + 4] = *(const uint4*)(Qlg + (size_t)(q0 + r) * 32 + c8 + 4);
    }

    issueif(0);
    issueif(1);

    float zacc[8][4];
#pragma unroll
    for (int i = 0; i < 8; i++)
#pragma unroll
        for (int j = 0; j < 4; j++) zacc[i][j] = 0.0f;
    float la = 0.0f, lb = 0.0f;

    const int iA = q0 + wm + grp;
    const int iB = iA + 8;

    // ldmatrix lane geometry
    const int lrow = (lane & 7) + ((lane >> 3) & 1) * 8;
    const int lcsh = ((lane >> 4) & 1) * 8;

    for (int kt = 0; kt <= qt; kt++) {
        const int s = kt & 1;
        const uint32_t* Kh_s = smu + 2 * ATILE + s * ASTAGE;
        const uint32_t* Kl_s = Kh_s + ATILE;
        const uint32_t  vbase = sb + (uint32_t)(2 * ATILE + s * ASTAGE + 2 * ATILE) * 4;
        const int k0 = kt * 64;

        CP_WAIT1();
        __syncthreads();

        // ---- scores: split-bf16, keys [wn, wn+32) ----
        float sacc[4][4];
#pragma unroll
        for (int i = 0; i < 4; i++)
#pragma unroll
            for (int j = 0; j < 4; j++) sacc[i][j] = 0.0f;

#pragma unroll
        for (int kp8 = 0; kp8 < 32; kp8 += 8) {
            const int rA = (wm + grp) * KP2;
            uint32_t ah0 = Qh_s[rA + kp8 + qd];
            uint32_t ah1 = Qh_s[rA + 8 * KP2 + kp8 + qd];
            uint32_t ah2 = Qh_s[rA + kp8 + qd + 4];
            uint32_t ah3 = Qh_s[rA + 8 * KP2 + kp8 + qd + 4];
            uint32_t al0 = Ql_s[rA + kp8 + qd];
            uint32_t al1 = Ql_s[rA + 8 * KP2 + kp8 + qd];
            uint32_t al2 = Ql_s[rA + kp8 + qd + 4];
            uint32_t al3 = Ql_s[rA + 8 * KP2 + kp8 + qd + 4];
#pragma unroll
            for (int nt = 0; nt < 4; nt++) {
                const int rb = (wn + nt * 8 + grp) * KP2;
                uint32_t bh0 = Kh_s[rb + kp8 + qd];
                uint32_t bh1 = Kh_s[rb + kp8 + qd + 4];
                uint32_t bl0 = Kl_s[rb + kp8 + qd];
                uint32_t bl1 = Kl_s[rb + kp8 + qd + 4];
                mma16(sacc[nt], ah0, ah1, ah2, ah3, bh0, bh1);
                mma16(sacc[nt], ah0, ah1, ah2, ah3, bl0, bl1);
                mma16(sacc[nt], al0, al1, al2, al3, bh0, bh1);
            }
        }

        // ---- epilogue: exp, SA store, l-sums, P packed in registers ----
        const bool diag = (kt == qt);
        uint32_t pp[4], qq[4];
#pragma unroll
        for (int nt = 0; nt < 4; nt++) {
            const int j0 = k0 + wn + nt * 8 + 2 * qd;
            float p0 = __expf(sacc[nt][0] * 0.125f - (float)(iA - j0) * slope);
            float p1 = __expf(sacc[nt][1] * 0.125f - (float)(iA - j0 - 1) * slope);
            float p2 = __expf(sacc[nt][2] * 0.125f - (float)(iB - j0) * slope);
            float p3 = __expf(sacc[nt][3] * 0.125f - (float)(iB - j0 - 1) * slope);
            if (diag) {
                if (j0     > iA) p0 = 0.0f;
                if (j0 + 1 > iA) p1 = 0.0f;
                if (j0     > iB) p2 = 0.0f;
                if (j0 + 1 > iB) p3 = 0.0f;
            }
            la += p0 + p1;
            lb += p2 + p3;
            if (SA) {
                *(float2*)&SA[((size_t)h * S_LEN + iA) * S_LEN + j0] = make_float2(p0, p1);
                *(float2*)&SA[((size_t)h * S_LEN + iB) * S_LEN + j0] = make_float2(p2, p3);
            }
            pp[nt] = packh2(p0, p1);
            qq[nt] = packh2(p2, p3);
        }

        // ---- z += P V over this warp's 32 keys, all 64 dims ----
#pragma unroll
        for (int ks2 = 0; ks2 < 2; ks2++) {
            uint32_t a0 = pp[2 * ks2];
            uint32_t a1 = qq[2 * ks2];
            uint32_t a2 = pp[2 * ks2 + 1];
            uint32_t a3 = qq[2 * ks2 + 1];
            const uint32_t rbase = vbase
                + (uint32_t)((wn + ks2 * 16 + lrow) * KP2) * 4;
#pragma unroll
            for (int ntp = 0; ntp < 4; ntp++) {
                uint32_t addr = rbase + (uint32_t)(ntp * 16 + lcsh) * 2;
                uint32_t b0, b1, b2, b3;
                ldsm_x4_t(b0, b1, b2, b3, addr);
                mma16h(zacc[2 * ntp],     a0, a1, a2, a3, b0, b1);
                mma16h(zacc[2 * ntp + 1], a0, a1, a2, a3, b2, b3);
            }
        }
        __syncthreads();      // K/V reads done -> stage s reusable
        issueif(kt + 2);
    }

    // ---- cross-warp z merge (odd key-half -> even) ----
    __syncthreads();
    float* zred = (float*)(smu + 2 * ATILE);        // [64][66]
    if (w & 1) {
#pragma unroll
        for (int nb = 0; nb < 8; nb++) {
            const int c = nb * 8 + 2 * qd;
            *(float2*)&zred[(wm + grp)     * 66 + c] = make_float2(zacc[nb][0], zacc[nb][1]);
            *(float2*)&zred[(wm + grp + 8) * 66 + c] = make_float2(zacc[nb][2], zacc[nb][3]);
        }
    }
    __syncthreads();
    if (!(w & 1)) {
#pragma unroll
        for (int nb = 0; nb < 8; nb++) {
            const int c = nb * 8 + 2 * qd;
            float2 r0 = *(const float2*)&zred[(wm + grp)     * 66 + c];
            float2 r1 = *(const float2*)&zred[(wm + grp + 8) * 66 + c];
            zacc[nb][0] += r0.x; zacc[nb][1] += r0.y;
            zacc[nb][2] += r1.x; zacc[nb][3] += r1.y;
        }
    }

    // ---- row-sum reduction across quad + the two key-half warps ----
    la += __shfl_xor_sync(0xffffffffu, la, 1);
    la += __shfl_xor_sync(0xffffffffu, la, 2);
    lb += __shfl_xor_sync(0xffffffffu, lb, 1);
    lb += __shfl_xor_sync(0xffffffffu, lb, 2);
    __syncthreads();
    float* red = (float*)(smu + 2 * ATILE) + 64 * 66;
    if (qd == 0) {
        red[(w & 1) * 64 + wm + grp]     = la;
        red[(w & 1) * 64 + wm + grp + 8] = lb;
    }
    __syncthreads();
    if (!(w & 1)) {
        const float lA = red[wm + grp]     + red[64 + wm + grp];
        const float lB = red[wm + grp + 8] + red[64 + wm + grp + 8];
        if (qd == 0) {
            Lsum[h * S_LEN + iA] = lA;
            Lsum[h * S_LEN + iB] = lB;
        }
        const float liA = 1.0f / lA;
        const float liB = 1.0f / lB;
#pragma unroll
        for (int nb = 0; nb < 8; nb++) {
            const int v0 = h * D_HEAD + nb * 8 + 2 * qd;
            Zf2[(size_t)iA * (D_MODEL / 2) + (v0 >> 1)] =
                packh2(zacc[nb][0] * liA, zacc[nb][1] * liA);
            Zf2[(size_t)iB * (D_MODEL / 2) + (v0 >> 1)] =
                packh2(zacc[nb][2] * liB, zacc[nb][3] * liB);
        }
    }
}

// ---- SA upper-triangle zero-fill ----
__global__ __launch_bounds__(256) void sa_zero(float* __restrict__ SA)
{
    const int row   = blockIdx.x;
    const int i     = row & (S_LEN - 1);
    const int start = (((i >> 6) + 1) << 6) >> 2;
    float4* p = (float4*)(SA + (size_t)row * S_LEN);
    const float4 z4 = make_float4(0.f, 0.f, 0.f, 0.f);
    for (int v = start + threadIdx.x; v < S_LEN / 4; v += 256)
        p[v] = z4;
}

// ---- SA rescale: lower tiles only ----
__global__ __launch_bounds__(256) void sa_rescale(
    float* __restrict__ SA, const float* __restrict__ Lsum)
{
    const int row = blockIdx.x;
    const int i   = row & (S_LEN - 1);
    const int end = (((i >> 6) + 1) << 6) >> 2;
    const float linv = 1.0f / Lsum[row];
    float4* p = (float4*)(SA + (size_t)row * S_LEN);
    for (int v = threadIdx.x; v < end; v += 256) {
        float4 x = p[v];
        x.x *= linv; x.y *= linv; x.z *= linv; x.w *= linv;
        p[v] = x;
    }
}

// =================================================================
extern "C" void kernel_launch(void* const* d_in, const int* in_sizes, int n_in,
                              void* d_out, int out_size)
{
    const float* X   = (const float*)d_in[0];
    const float* WQ  = (const float*)d_in[1];
    const float* WK  = (const float*)d_in[2];
    const float* WV  = (const float*)d_in[3];
    const float* WOw = (const float*)d_in[4];
    const float* WOb = (const float*)d_in[5];
    const float* F1w = (const float*)d_in[6];
    const float* F1b = (const float*)d_in[7];
    const float* F2w = (const float*)d_in[8];
    const float* F2b = (const float*)d_in[9];

    float *Ap, *Lp, *Dp;
    uint32_t *Xh2, *Xl2, *WQh2, *WQl2, *WKh2, *WKl2, *Qh2, *Ql2, *Kh2, *Kl2;
    uint32_t *Xf2, *WVf2, *WOf2, *F1f2, *F2f2, *Vf2, *Zf2, *ATTf2, *HIDf2;
    cudaGetSymbolAddress((void**)&Ap, g_ATT);
    cudaGetSymbolAddress((void**)&Lp, g_L);
    cudaGetSymbolAddress((void**)&Dp, g_DUMMY);
    cudaGetSymbolAddress((void**)&Xh2, g_Xh2);
    cudaGetSymbolAddress((void**)&Xl2, g_Xl2);
    cudaGetSymbolAddress((void**)&WQh2, g_WQh2);
    cudaGetSymbolAddress((void**)&WQl2, g_WQl2);
    cudaGetSymbolAddress((void**)&WKh2, g_WKh2);
    cudaGetSymbolAddress((void**)&WKl2, g_WKl2);
    cudaGetSymbolAddress((void**)&Qh2, g_Qh2);
    cudaGetSymbolAddress((void**)&Ql2, g_Ql2);
    cudaGetSymbolAddress((void**)&Kh2, g_Kh2);
    cudaGetSymbolAddress((void**)&Kl2, g_Kl2);
    cudaGetSymbolAddress((void**)&Xf2, g_Xf2);
    cudaGetSymbolAddress((void**)&WVf2, g_WVf2);
    cudaGetSymbolAddress((void**)&WOf2, g_WOf2);
    cudaGetSymbolAddress((void**)&F1f2, g_F1f2);
    cudaGetSymbolAddress((void**)&F2f2, g_F2f2);
    cudaGetSymbolAddress((void**)&Vf2, g_Vf2);
    cudaGetSymbolAddress((void**)&Zf2, g_Zf2);
    cudaGetSymbolAddress((void**)&ATTf2, g_ATTf2);
    cudaGetSymbolAddress((void**)&HIDf2, g_HIDf2);

    const size_t SA_EL = (size_t)N_HEADS * S_LEN * S_LEN;
    const size_t OV_EL = (size_t)S_LEN * D_MODEL;
    float* out = (float*)d_out;
    float* sa;
    float* ov;
    if ((size_t)out_size >= SA_EL + OV_EL)      { sa = out;     ov = out + SA_EL; }
    else if ((size_t)out_size >= SA_EL)         { sa = out;     ov = Dp; }
    else                                        { sa = nullptr; ov = out; }

    const int attn_smem = ATTN_SMEM_U32 * 4;   // 73728
    const int qk_smem   = 8 * QSTG * 4;        // 81920
    const int f16_smem  = 6 * FSTG * 4;        // 61440
    cudaFuncSetAttribute(attn_tc, cudaFuncAttributeMaxDynamicSharedMemorySize, attn_smem);
    cudaFuncSetAttribute(gemm_qk, cudaFuncAttributeMaxDynamicSharedMemorySize, qk_smem);
    cudaFuncSetAttribute(gemm_f16<false,false,false,false,false,true >,
                         cudaFuncAttributeMaxDynamicSharedMemorySize, f16_smem);
    cudaFuncSetAttribute(gemm_f16<true ,false,true ,true ,true ,false>,
                         cudaFuncAttributeMaxDynamicSharedMemorySize, f16_smem);
    cudaFuncSetAttribute(gemm_f16<true ,true ,false,false,true ,false>,
                         cudaFuncAttributeMaxDynamicSharedMemorySize, f16_smem);
    cudaFuncSetAttribute(gemm_f16<true ,false,true ,true ,false,false>,
                         cudaFuncAttributeMaxDynamicSharedMemorySize, f16_smem);

    static cudaStream_t s2 = nullptr;
    static cudaEvent_t evStart = nullptr, evX = nullptr, evV = nullptr,
                       evAttn = nullptr, evSide = nullptr, evPack = nullptr;
    if (!s2) {
        cudaStreamCreateWithFlags(&s2, cudaStreamNonBlocking);
        cudaEventCreateWithFlags(&evStart, cudaEventDisableTiming);
        cudaEventCreateWithFlags(&evX,     cudaEventDisableTiming);
        cudaEventCreateWithFlags(&evV,     cudaEventDisableTiming);
        cudaEventCreateWithFlags(&evAttn,  cudaEventDisableTiming);
        cudaEventCreateWithFlags(&evSide,  cudaEventDisableTiming);
        cudaEventCreateWithFlags(&evPack,  cudaEventDisableTiming);
    }

    dim3 blk(256);

    // ---- fork side stream ----
    cudaEventRecord(evStart, 0);
    cudaStreamWaitEvent(s2, evStart, 0);

    // ---- main: pack X (needed by both streams) ----
    pack_x<<<dim3(2048), blk>>>(X, Xh2, Xl2, Xf2, S_LEN * D_MODEL / 4);
    cudaEventRecord(evX, 0);

    // ---- side: WV pack -> V-GEMM (overlaps gemm_qk), then SA zero + packs
    pack_wf_head<<<dim3(2048), blk, 0, s2>>>(WV, WVf2);
    cudaStreamWaitEvent(s2, evX, 0);
    gemm_f16<false,false,false,false,false,true ><<<dim3(8, 16), blk, f16_smem, s2>>>(
        Xf2, WVf2, nullptr, nullptr, nullptr, Vf2, S_LEN, D_MODEL, D_MODEL);
    cudaEventRecord(evV, s2);
    if (sa)
        sa_zero<<<dim3(N_HEADS * S_LEN), blk, 0, s2>>>(sa);
    pack_wf_row<<<dim3(2048), blk, 0, s2>>>(WOw, WOf2, D_MODEL * D_MODEL / 2);
    pack_wf_row<<<dim3(8192), blk, 0, s2>>>(F1w, F1f2, D_FF * D_MODEL / 2);
    pack_wf_row<<<dim3(8192), blk, 0, s2>>>(F2w, F2f2, D_MODEL * D_FF / 2);
    cudaEventRecord(evPack, s2);

    // ---- main: QK packs + QK projection ----
    pack_w<<<dim3(2048), blk>>>(WQ, WQh2, WQl2);
    pack_w<<<dim3(2048), blk>>>(WK, WKh2, WKl2);
    gemm_qk<<<dim3(8, 16, 2), blk, qk_smem>>>(Xh2, Xl2,
        WQh2, WQl2, WKh2, WKl2, Qh2, Ql2, Kh2, Kl2);

    // attention needs V from the side stream
    cudaStreamWaitEvent(0, evV, 0);
    attn_tc<<<dim3(S_LEN / 64, N_HEADS), blk, attn_smem>>>(
        Qh2, Ql2, Kh2, Kl2, Vf2, sa, Zf2, Lp);

    // ---- fork: rescale SA overlapping WO/FF ----
    cudaEventRecord(evAttn, 0);
    if (sa) {
        cudaStreamWaitEvent(s2, evAttn, 0);
        sa_rescale<<<dim3(N_HEADS * S_LEN), blk, 0, s2>>>(sa, Lp);
        cudaEventRecord(evSide, s2);
    }

    cudaStreamWaitEvent(0, evPack, 0);

    // ATT = X + Z @ WO^T + b  (fp32 + packed fp16 out)
    gemm_f16<true ,false,true ,true ,true ,false><<<dim3(8, 16), blk, f16_smem>>>(
        Zf2, WOf2, WOb, X, Ap, ATTf2, S_LEN, D_MODEL, D_MODEL);
    // HID = relu(ATT @ FF1^T + b1)  (packed fp16 only)
    gemm_f16<true ,true ,false,false,true ,false><<<dim3(32, 16), blk, f16_smem>>>(
        ATTf2, F1f2, F1b, nullptr, nullptr, HIDf2, S_LEN, D_FF, D_MODEL);
    // out = ATT + HID @ FF2^T + b2  (fp32 out)
    gemm_f16<true ,false,true ,true ,false,false><<<dim3(8, 16), blk, f16_smem>>>(
        HIDf2, F2f2, F2b, Ap, ov, nullptr, S_LEN, D_MODEL, D_FF);

    if (sa)
        cudaStreamWaitEvent(0, evSide, 0);
}

// round 13
// speedup vs baseline: 4.6259x; 1.0042x over previous
#include <cuda_runtime.h>
#include <cstdint>

#define S_LEN   2048
#define D_MODEL 1024
#define N_HEADS 16
#define D_HEAD  64
#define D_FF    4096

// ---------------- scratch (no allocation allowed) ----------------
__device__ float    g_ATT[S_LEN * D_MODEL];
__device__ float    g_L[N_HEADS * S_LEN];
__device__ float    g_DUMMY[S_LEN * D_MODEL];
// bf16x2 (hi/lo) packed operands for Q/K path
__device__ uint32_t g_Xh2[S_LEN * (D_MODEL / 2)];
__device__ uint32_t g_Xl2[S_LEN * (D_MODEL / 2)];
__device__ uint32_t g_WQh2[N_HEADS * D_HEAD * (D_MODEL / 2)];
__device__ uint32_t g_WQl2[N_HEADS * D_HEAD * (D_MODEL / 2)];
__device__ uint32_t g_WKh2[N_HEADS * D_HEAD * (D_MODEL / 2)];
__device__ uint32_t g_WKl2[N_HEADS * D_HEAD * (D_MODEL / 2)];
__device__ uint32_t g_Qh2[N_HEADS * S_LEN * (D_HEAD / 2)];
__device__ uint32_t g_Ql2[N_HEADS * S_LEN * (D_HEAD / 2)];
__device__ uint32_t g_Kh2[N_HEADS * S_LEN * (D_HEAD / 2)];
__device__ uint32_t g_Kl2[N_HEADS * S_LEN * (D_HEAD / 2)];
// fp16x2 packed operands
__device__ uint32_t g_Xf2[S_LEN * (D_MODEL / 2)];
__device__ uint32_t g_WVf2[D_MODEL * (D_MODEL / 2)];
__device__ uint32_t g_WOf2[D_MODEL * (D_MODEL / 2)];
__device__ uint32_t g_F1f2[D_FF * (D_MODEL / 2)];
__device__ uint32_t g_F2f2[D_MODEL * (D_FF / 2)];
__device__ uint32_t g_Vf2[N_HEADS * S_LEN * (D_HEAD / 2)];
__device__ uint32_t g_Zf2[S_LEN * (D_MODEL / 2)];
__device__ uint32_t g_ATTf2[S_LEN * (D_MODEL / 2)];
__device__ uint32_t g_HIDf2[S_LEN * (D_FF / 2)];

// =================================================================
// helpers
// =================================================================
__device__ __forceinline__ void mma16(float* c,
    uint32_t a0, uint32_t a1, uint32_t a2, uint32_t a3,
    uint32_t b0, uint32_t b1)
{
    asm volatile(
        "mma.sync.aligned.m16n8k16.row.col.f32.bf16.bf16.f32 "
        "{%0,%1,%2,%3},{%4,%5,%6,%7},{%8,%9},{%0,%1,%2,%3};"
        : "+f"(c[0]), "+f"(c[1]), "+f"(c[2]), "+f"(c[3])
        : "r"(a0), "r"(a1), "r"(a2), "r"(a3), "r"(b0), "r"(b1));
}

__device__ __forceinline__ void mma16h(float* c,
    uint32_t a0, uint32_t a1, uint32_t a2, uint32_t a3,
    uint32_t b0, uint32_t b1)
{
    asm volatile(
        "mma.sync.aligned.m16n8k16.row.col.f32.f16.f16.f32 "
        "{%0,%1,%2,%3},{%4,%5,%6,%7},{%8,%9},{%0,%1,%2,%3};"
        : "+f"(c[0]), "+f"(c[1]), "+f"(c[2]), "+f"(c[3])
        : "r"(a0), "r"(a1), "r"(a2), "r"(a3), "r"(b0), "r"(b1));
}

__device__ __forceinline__ void ldsm_x4_t(
    uint32_t& r0, uint32_t& r1, uint32_t& r2, uint32_t& r3, uint32_t addr)
{
    asm volatile(
        "ldmatrix.sync.aligned.m8n8.x4.trans.shared.b16 {%0,%1,%2,%3}, [%4];"
        : "=r"(r0), "=r"(r1), "=r"(r2), "=r"(r3) : "r"(addr));
}

__device__ __forceinline__ void pack2(float x0, float x1, uint32_t& hi, uint32_t& lo) {
    asm("cvt.rn.bf16x2.f32 %0, %1, %2;" : "=r"(hi) : "f"(x1), "f"(x0));
    float f0 = __uint_as_float(hi << 16);
    float f1 = __uint_as_float(hi & 0xffff0000u);
    asm("cvt.rn.bf16x2.f32 %0, %1, %2;" : "=r"(lo) : "f"(x1 - f1), "f"(x0 - f0));
}

__device__ __forceinline__ uint32_t packh2(float x0, float x1) {
    uint32_t r;
    asm("cvt.rn.f16x2.f32 %0, %1, %2;" : "=r"(r) : "f"(x1), "f"(x0));
    return r;
}

__device__ __forceinline__ void cp16(uint32_t dst_smem, const void* src) {
    asm volatile("cp.async.cg.shared.global [%0], [%1], 16;"
                 :: "r"(dst_smem), "l"(src));
}
#define CP_COMMIT() asm volatile("cp.async.commit_group;")
#define CP_WAIT1()  asm volatile("cp.async.wait_group 1;")
#define CP_WAIT2()  asm volatile("cp.async.wait_group 2;")

// =================================================================
// pack kernels
// =================================================================
__global__ __launch_bounds__(256) void pack_x(
    const float* __restrict__ in, uint32_t* __restrict__ oh,
    uint32_t* __restrict__ ol, uint32_t* __restrict__ of, int n4)
{
    int i = blockIdx.x * 256 + threadIdx.x;
    if (i < n4) {
        float4 v = ((const float4*)in)[i];
        uint32_t h0, l0, h1, l1;
        pack2(v.x, v.y, h0, l0);
        pack2(v.z, v.w, h1, l1);
        ((uint2*)oh)[i] = make_uint2(h0, h1);
        ((uint2*)ol)[i] = make_uint2(l0, l1);
        ((uint2*)of)[i] = make_uint2(packh2(v.x, v.y), packh2(v.z, v.w));
    }
}

// merged Q+K per-head weight pack (blockIdx.y selects)
__global__ __launch_bounds__(256) void pack_w2(
    const float* __restrict__ inQ, const float* __restrict__ inK,
    uint32_t* __restrict__ oQh, uint32_t* __restrict__ oQl,
    uint32_t* __restrict__ oKh, uint32_t* __restrict__ oKl)
{
    const float* in = blockIdx.y ? inK : inQ;
    uint32_t* oh = blockIdx.y ? oKh : oQh;
    uint32_t* ol = blockIdx.y ? oKl : oQl;
    int i  = blockIdx.x * 256 + threadIdx.x;
    int e  = i & 63;
    int kp = (i >> 6) & 511;
    int h  = i >> 15;
    float x0 = in[((size_t)h * 1024 + 2 * kp)     * 64 + e];
    float x1 = in[((size_t)h * 1024 + 2 * kp + 1) * 64 + e];
    uint32_t hi, lo;
    pack2(x0, x1, hi, lo);
    oh[((size_t)h * 64 + e) * 512 + kp] = hi;
    ol[((size_t)h * 64 + e) * 512 + kp] = lo;
}

__global__ __launch_bounds__(256) void pack_wf_head(
    const float* __restrict__ in, uint32_t* __restrict__ of)
{
    int i  = blockIdx.x * 256 + threadIdx.x;
    int e  = i & 63;
    int kp = (i >> 6) & 511;
    int h  = i >> 15;
    float x0 = in[((size_t)h * 1024 + 2 * kp)     * 64 + e];
    float x1 = in[((size_t)h * 1024 + 2 * kp + 1) * 64 + e];
    of[((size_t)h * 64 + e) * 512 + kp] = packh2(x0, x1);
}

__global__ __launch_bounds__(256) void pack_wf_row(
    const float* __restrict__ in, uint32_t* __restrict__ of, int npair)
{
    int i = blockIdx.x * 256 + threadIdx.x;
    if (i < npair) {
        float2 v = ((const float2*)in)[i];
        of[i] = packh2(v.x, v.y);
    }
}

// =================================================================
// Q+K projection (split-bf16, merged via blockIdx.z)
// =================================================================
#define QKP 20
#define QSTG (128 * QKP)

__global__ __launch_bounds__(256, 2) void gemm_qk(
    const uint32_t* __restrict__ Ah2g, const uint32_t* __restrict__ Al2g,
    const uint32_t* __restrict__ BQh, const uint32_t* __restrict__ BQl,
    const uint32_t* __restrict__ BKh, const uint32_t* __restrict__ BKl,
    uint32_t* __restrict__ OQh, uint32_t* __restrict__ OQl,
    uint32_t* __restrict__ OKh, uint32_t* __restrict__ OKl)
{
    extern __shared__ float sm[];
    uint32_t* smu = (uint32_t*)sm;

    const int t    = threadIdx.x;
    const int lane = t & 31;
    const int w    = t >> 5;
    const int grp  = lane >> 2;
    const int qd   = lane & 3;
    const int wm   = (w & 3) * 32;
    const int wn   = (w >> 2) * 64;
    const int m0   = blockIdx.y * 128;
    const int n0   = blockIdx.x * 128;

    const uint32_t* Bh2g = blockIdx.z ? BKh : BQh;
    const uint32_t* Bl2g = blockIdx.z ? BKl : BQl;
    uint32_t* Oh = blockIdx.z ? OKh : OQh;
    uint32_t* Ol = blockIdx.z ? OKl : OQl;

    float acc[2][8][4];
#pragma unroll
    for (int i = 0; i < 2; i++)
#pragma unroll
        for (int j = 0; j < 8; j++)
#pragma unroll
            for (int k = 0; k < 4; k++) acc[i][j][k] = 0.0f;

    const uint32_t sb = (uint32_t)__cvta_generic_to_shared(smu);

    auto issue = [&](int kt, int s) {
        const int kb = kt * 16;
        const uint32_t base = sb + (uint32_t)s * 4 * QSTG * 4;
#pragma unroll
        for (int i = t; i < 512; i += 256) {
            const int r = i >> 2, c = (i & 3) * 4;
            const uint32_t d = base + (r * QKP + c) * 4;
            cp16(d,                Ah2g + (size_t)(m0 + r) * 512 + kb + c);
            cp16(d + QSTG * 4,     Al2g + (size_t)(m0 + r) * 512 + kb + c);
            const size_t wo = (size_t)(n0 + r) * 512 + kb + c;
            cp16(d + 2 * QSTG * 4, Bh2g + wo);
            cp16(d + 3 * QSTG * 4, Bl2g + wo);
        }
    };

    issue(0, 0); CP_COMMIT();
    issue(1, 1); CP_COMMIT();

    for (int kt = 0; kt < 32; kt++) {
        CP_WAIT1();
        __syncthreads();
        const uint32_t* Ah = smu + (kt & 1) * 4 * QSTG;
        const uint32_t* Al = Ah + QSTG;
        const uint32_t* Bh = Ah + 2 * QSTG;
        const uint32_t* Bl = Ah + 3 * QSTG;

#pragma unroll
        for (int ks2 = 0; ks2 < 16; ks2 += 8) {
            uint32_t ah[2][4], al[2][4];
#pragma unroll
            for (int mt = 0; mt < 2; mt++) {
                const int r = (wm + mt * 16 + grp) * QKP;
                ah[mt][0] = Ah[r + ks2 + qd];
                ah[mt][1] = Ah[r + 8 * QKP + ks2 + qd];
                ah[mt][2] = Ah[r + ks2 + qd + 4];
                ah[mt][3] = Ah[r + 8 * QKP + ks2 + qd + 4];
                al[mt][0] = Al[r + ks2 + qd];
                al[mt][1] = Al[r + 8 * QKP + ks2 + qd];
                al[mt][2] = Al[r + ks2 + qd + 4];
                al[mt][3] = Al[r + 8 * QKP + ks2 + qd + 4];
            }
#pragma unroll
            for (int nt = 0; nt < 8; nt++) {
                const int rb = (wn + nt * 8 + grp) * QKP;
                uint32_t bh0 = Bh[rb + ks2 + qd];
                uint32_t bh1 = Bh[rb + ks2 + qd + 4];
                uint32_t bl0 = Bl[rb + ks2 + qd];
                uint32_t bl1 = Bl[rb + ks2 + qd + 4];
#pragma unroll
                for (int mt = 0; mt < 2; mt++) {
                    mma16(acc[mt][nt], ah[mt][0], ah[mt][1], ah[mt][2], ah[mt][3], bh0, bh1);
                    mma16(acc[mt][nt], ah[mt][0], ah[mt][1], ah[mt][2], ah[mt][3], bl0, bl1);
                    mma16(acc[mt][nt], al[mt][0], al[mt][1], al[mt][2], al[mt][3], bh0, bh1);
                }
            }
        }
        __syncthreads();
        if (kt + 2 < 32) issue(kt + 2, kt & 1);
        CP_COMMIT();
    }

#pragma unroll
    for (int mt = 0; mt < 2; mt++) {
#pragma unroll
        for (int nt = 0; nt < 8; nt++) {
            const int n  = n0 + wn + nt * 8 + 2 * qd;
            const int h  = n >> 6;
            const int dp = (n & 63) >> 1;
            const int mA = blockIdx.y * 128 + wm + mt * 16 + grp;
            const int mB = mA + 8;
            uint32_t hi, lo;
            pack2(acc[mt][nt][0], acc[mt][nt][1], hi, lo);
            Oh[((size_t)h * S_LEN + mA) * 32 + dp] = hi;
            Ol[((size_t)h * S_LEN + mA) * 32 + dp] = lo;
            pack2(acc[mt][nt][2], acc[mt][nt][3], hi, lo);
            Oh[((size_t)h * S_LEN + mB) * 32 + dp] = hi;
            Ol[((size_t)h * S_LEN + mB) * 32 + dp] = lo;
        }
    }
}

// =================================================================
// fp16 GEMM: operands pre-packed u32 half2 along k.
// MT = 128 (8 warps 4Mx2N, warp 32x64) or 64 (8 warps 2Mx4N, warp 32x32).
// =================================================================
#define FP  20

template<int MT, bool BIAS, bool RELU, bool RESID, bool OUTF32, bool OUTPACK, bool OUTPACKHEAD>
__global__ __launch_bounds__(256, 2) void gemm_f16(
    const uint32_t* __restrict__ A2, const uint32_t* __restrict__ B2,
    const float* __restrict__ bias, const float* __restrict__ resid,
    float* __restrict__ Cf, uint32_t* __restrict__ Cp,
    int M, int N, int K)
{
    constexpr int ASTG = MT * FP;
    constexpr int BSTG = 128 * FP;
    constexpr int SSTG = ASTG + BSTG;
    constexpr int NTI  = (MT == 128) ? 8 : 4;

    extern __shared__ float sm[];
    uint32_t* smu = (uint32_t*)sm;

    const int t    = threadIdx.x;
    const int lane = t & 31;
    const int w    = t >> 5;
    const int grp  = lane >> 2;
    const int qd   = lane & 3;
    const int wm   = (MT == 128) ? (w & 3) * 32 : (w & 1) * 32;
    const int wn   = (MT == 128) ? (w >> 2) * 64 : (w >> 1) * 32;
    const int m0   = blockIdx.y * MT;
    const int n0   = blockIdx.x * 128;
    const int K2   = K >> 1;
    const int KT   = K >> 5;

    float acc[2][NTI][4];
#pragma unroll
    for (int i = 0; i < 2; i++)
#pragma unroll
        for (int j = 0; j < NTI; j++)
#pragma unroll
            for (int k = 0; k < 4; k++) acc[i][j][k] = 0.0f;

    const uint32_t sb = (uint32_t)__cvta_generic_to_shared(smu);

    auto issue = [&](int kt, int s) {
        const int kb = kt * 16;
        const uint32_t base = sb + (uint32_t)s * SSTG * 4;
#pragma unroll
        for (int i = t; i < MT * 4; i += 256) {
            const int r = i >> 2, c = (i & 3) * 4;
            cp16(base + (r * FP + c) * 4, A2 + (size_t)(m0 + r) * K2 + kb + c);
        }
#pragma unroll
        for (int i = t; i < 512; i += 256) {
            const int r = i >> 2, c = (i & 3) * 4;
            cp16(base + (ASTG + r * FP + c) * 4, B2 + (size_t)(n0 + r) * K2 + kb + c);
        }
    };

    issue(0, 0); CP_COMMIT();
    issue(1, 1); CP_COMMIT();
    issue(2, 2); CP_COMMIT();

    for (int kt = 0; kt < KT; kt++) {
        const int s = kt % 3;
        CP_WAIT2();
        __syncthreads();
        const uint32_t* Ab = smu + s * SSTG;
        const uint32_t* Bb = Ab + ASTG;

#pragma unroll
        for (int ks2 = 0; ks2 < 16; ks2 += 8) {
            uint32_t af[2][4];
#pragma unroll
            for (int mt = 0; mt < 2; mt++) {
                const int r = (wm + mt * 16 + grp) * FP;
                af[mt][0] = Ab[r + ks2 + qd];
                af[mt][1] = Ab[r + 8 * FP + ks2 + qd];
                af[mt][2] = Ab[r + ks2 + qd + 4];
                af[mt][3] = Ab[r + 8 * FP + ks2 + qd + 4];
            }
#pragma unroll
            for (int nt = 0; nt < NTI; nt++) {
                const int rb = (wn + nt * 8 + grp) * FP;
                uint32_t b0 = Bb[rb + ks2 + qd];
                uint32_t b1 = Bb[rb + ks2 + qd + 4];
#pragma unroll
                for (int mt = 0; mt < 2; mt++)
                    mma16h(acc[mt][nt], af[mt][0], af[mt][1], af[mt][2], af[mt][3], b0, b1);
            }
        }
        __syncthreads();
        if (kt + 3 < KT) issue(kt + 3, s);
        CP_COMMIT();
    }

#pragma unroll
    for (int mt = 0; mt < 2; mt++) {
#pragma unroll
        for (int nt = 0; nt < NTI; nt++) {
            const int n  = n0 + wn + nt * 8 + 2 * qd;
            float2 v0 = make_float2(acc[mt][nt][0], acc[mt][nt][1]);
            float2 v1 = make_float2(acc[mt][nt][2], acc[mt][nt][3]);
            if (BIAS) {
                float2 bb = *(const float2*)&bias[n];
                v0.x += bb.x; v0.y += bb.y;
                v1.x += bb.x; v1.y += bb.y;
            }
            if (RELU) {
                v0.x = fmaxf(v0.x, 0.f); v0.y = fmaxf(v0.y, 0.f);
                v1.x = fmaxf(v1.x, 0.f); v1.y = fmaxf(v1.y, 0.f);
            }
            const int mA = m0 + wm + mt * 16 + grp;
            const int mB = mA + 8;
            if (RESID) {
                float2 r0 = *(const float2*)&resid[(size_t)mA * N + n];
                float2 r1 = *(const float2*)&resid[(size_t)mB * N + n];
                v0.x += r0.x; v0.y += r0.y;
                v1.x += r1.x; v1.y += r1.y;
            }
            if (OUTF32) {
                *(float2*)&Cf[(size_t)mA * N + n] = v0;
                *(float2*)&Cf[(size_t)mB * N + n] = v1;
            }
            if (OUTPACK) {
                Cp[(size_t)mA * (N >> 1) + (n >> 1)] = packh2(v0.x, v0.y);
                Cp[(size_t)mB * (N >> 1) + (n >> 1)] = packh2(v1.x, v1.y);
            }
            if (OUTPACKHEAD) {
                const int h  = n >> 6;
                const int dp = (n & 63) >> 1;
                Cp[((size_t)h * M + mA) * 32 + dp] = packh2(v0.x, v0.y);
                Cp[((size_t)h * M + mB) * 32 + dp] = packh2(v1.x, v1.y);
            }
        }
    }
}

// =================================================================
// Attention v3 (R12): split-bf16 scores; fp16 z with register A-frags.
// =================================================================
#define KP2 36
#define ATILE (64 * KP2)
#define ASTAGE (3 * ATILE)
#define ATTN_SMEM_U32 (2 * ATILE + 2 * ASTAGE)

__global__ __launch_bounds__(256, 2) void attn_tc(
    const uint32_t* __restrict__ Qh2, const uint32_t* __restrict__ Ql2,
    const uint32_t* __restrict__ Kh2, const uint32_t* __restrict__ Kl2,
    const uint32_t* __restrict__ Vf2g, float* __restrict__ SA,
    uint32_t* __restrict__ Zf2, float* __restrict__ Lsum)
{
    extern __shared__ float sm[];
    uint32_t* smu  = (uint32_t*)sm;
    uint32_t* Qh_s = smu;
    uint32_t* Ql_s = smu + ATILE;

    const int t    = threadIdx.x;
    const int lane = t & 31;
    const int w    = t >> 5;
    const int grp  = lane >> 2;
    const int qd   = lane & 3;
    const int wm   = (w >> 1) * 16;
    const int wn   = (w & 1) * 32;
    const int qt   = (int)gridDim.x - 1 - (int)blockIdx.x;
    const int h    = blockIdx.y;
    const int q0   = qt * 64;

    const float slope = exp2f(-0.5f * (float)(h + 1));
    const uint32_t* Qhg = Qh2 + (size_t)h * S_LEN * 32;
    const uint32_t* Qlg = Ql2 + (size_t)h * S_LEN * 32;
    const uint32_t* Khg = Kh2 + (size_t)h * S_LEN * 32;
    const uint32_t* Klg = Kl2 + (size_t)h * S_LEN * 32;
    const uint32_t* Vfg = Vf2g + (size_t)h * S_LEN * 32;

    const uint32_t sb = (uint32_t)__cvta_generic_to_shared(smu);

    auto issueif = [&](int kt) {
        if (kt <= qt) {
            const int s = kt & 1;
            const uint32_t base = sb + (uint32_t)(2 * ATILE + s * ASTAGE) * 4;
            const int k0 = kt * 64;
#pragma unroll
            for (int i = t; i < 512; i += 256) {
                const int r = i >> 3, c = (i & 7) * 4;
                const uint32_t d = base + (r * KP2 + c) * 4;
                cp16(d,                 Khg + (size_t)(k0 + r) * 32 + c);
                cp16(d + ATILE * 4,     Klg + (size_t)(k0 + r) * 32 + c);
                cp16(d + 2 * ATILE * 4, Vfg + (size_t)(k0 + r) * 32 + c);
            }
        }
        CP_COMMIT();
    };

    {
        const int r  = t >> 2;
        const int c8 = (t & 3) * 8;
        *(uint4*)&Qh_s[r * KP2 + c8]     = *(const uint4*)(Qhg + (size_t)(q0 + r) * 32 + c8);
        *(uint4*)&Qh_s[r * KP2 + c8 + 4] = *(const uint4*)(Qhg + (size_t)(q0 + r) * 32 + c8 + 4);
        *(uint4*)&Ql_s[r * KP2 + c8]     = *(const uint4*)(Qlg + (size_t)(q0 + r) * 32 + c8);
        *(uint4*)&Ql_s[r * KP2 + c8 + 4] = *(const uint4*)(Qlg + (size_t)(q0 + r) * 32 + c8 + 4);
    }

    issueif(0);
    issueif(1);

    float zacc[8][4];
#pragma unroll
    for (int i = 0; i < 8; i++)
#pragma unroll
        for (int j = 0; j < 4; j++) zacc[i][j] = 0.0f;
    float la = 0.0f, lb = 0.0f;

    const int iA = q0 + wm + grp;
    const int iB = iA + 8;

    const int lrow = (lane & 7) + ((lane >> 3) & 1) * 8;
    const int lcsh = ((lane >> 4) & 1) * 8;

    for (int kt = 0; kt <= qt; kt++) {
        const int s = kt & 1;
        const uint32_t* Kh_s = smu + 2 * ATILE + s * ASTAGE;
        const uint32_t* Kl_s = Kh_s + ATILE;
        const uint32_t  vbase = sb + (uint32_t)(2 * ATILE + s * ASTAGE + 2 * ATILE) * 4;
        const int k0 = kt * 64;

        CP_WAIT1();
        __syncthreads();

        float sacc[4][4];
#pragma unroll
        for (int i = 0; i < 4; i++)
#pragma unroll
            for (int j = 0; j < 4; j++) sacc[i][j] = 0.0f;

#pragma unroll
        for (int kp8 = 0; kp8 < 32; kp8 += 8) {
            const int rA = (wm + grp) * KP2;
            uint32_t ah0 = Qh_s[rA + kp8 + qd];
            uint32_t ah1 = Qh_s[rA + 8 * KP2 + kp8 + qd];
            uint32_t ah2 = Qh_s[rA + kp8 + qd + 4];
            uint32_t ah3 = Qh_s[rA + 8 * KP2 + kp8 + qd + 4];
            uint32_t al0 = Ql_s[rA + kp8 + qd];
            uint32_t al1 = Ql_s[rA + 8 * KP2 + kp8 + qd];
            uint32_t al2 = Ql_s[rA + kp8 + qd + 4];
            uint32_t al3 = Ql_s[rA + 8 * KP2 + kp8 + qd + 4];
#pragma unroll
            for (int nt = 0; nt < 4; nt++) {
                const int rb = (wn + nt * 8 + grp) * KP2;
                uint32_t bh0 = Kh_s[rb + kp8 + qd];
                uint32_t bh1 = Kh_s[rb + kp8 + qd + 4];
                uint32_t bl0 = Kl_s[rb + kp8 + qd];
                uint32_t bl1 = Kl_s[rb + kp8 + qd + 4];
                mma16(sacc[nt], ah0, ah1, ah2, ah3, bh0, bh1);
                mma16(sacc[nt], ah0, ah1, ah2, ah3, bl0, bl1);
                mma16(sacc[nt], al0, al1, al2, al3, bh0, bh1);
            }
        }

        const bool diag = (kt == qt);
        uint32_t pp[4], qq[4];
#pragma unroll
        for (int nt = 0; nt < 4; nt++) {
            const int j0 = k0 + wn + nt * 8 + 2 * qd;
            float p0 = __expf(sacc[nt][0] * 0.125f - (float)(iA - j0) * slope);
            float p1 = __expf(sacc[nt][1] * 0.125f - (float)(iA - j0 - 1) * slope);
            float p2 = __expf(sacc[nt][2] * 0.125f - (float)(iB - j0) * slope);
            float p3 = __expf(sacc[nt][3] * 0.125f - (float)(iB - j0 - 1) * slope);
            if (diag) {
                if (j0     > iA) p0 = 0.0f;
                if (j0 + 1 > iA) p1 = 0.0f;
                if (j0     > iB) p2 = 0.0f;
                if (j0 + 1 > iB) p3 = 0.0f;
            }
            la += p0 + p1;
            lb += p2 + p3;
            if (SA) {
                *(float2*)&SA[((size_t)h * S_LEN + iA) * S_LEN + j0] = make_float2(p0, p1);
                *(float2*)&SA[((size_t)h * S_LEN + iB) * S_LEN + j0] = make_float2(p2, p3);
            }
            pp[nt] = packh2(p0, p1);
            qq[nt] = packh2(p2, p3);
        }

#pragma unroll
        for (int ks2 = 0; ks2 < 2; ks2++) {
            uint32_t a0 = pp[2 * ks2];
            uint32_t a1 = qq[2 * ks2];
            uint32_t a2 = pp[2 * ks2 + 1];
            uint32_t a3 = qq[2 * ks2 + 1];
            const uint32_t rbase = vbase
                + (uint32_t)((wn + ks2 * 16 + lrow) * KP2) * 4;
#pragma unroll
            for (int ntp = 0; ntp < 4; ntp++) {
                uint32_t addr = rbase + (uint32_t)(ntp * 16 + lcsh) * 2;
                uint32_t b0, b1, b2, b3;
                ldsm_x4_t(b0, b1, b2, b3, addr);
                mma16h(zacc[2 * ntp],     a0, a1, a2, a3, b0, b1);
                mma16h(zacc[2 * ntp + 1], a0, a1, a2, a3, b2, b3);
            }
        }
        __syncthreads();
        issueif(kt + 2);
    }

    __syncthreads();
    float* zred = (float*)(smu + 2 * ATILE);
    if (w & 1) {
#pragma unroll
        for (int nb = 0; nb < 8; nb++) {
            const int c = nb * 8 + 2 * qd;
            *(float2*)&zred[(wm + grp)     * 66 + c] = make_float2(zacc[nb][0], zacc[nb][1]);
            *(float2*)&zred[(wm + grp + 8) * 66 + c] = make_float2(zacc[nb][2], zacc[nb][3]);
        }
    }
    __syncthreads();
    if (!(w & 1)) {
#pragma unroll
        for (int nb = 0; nb < 8; nb++) {
            const int c = nb * 8 + 2 * qd;
            float2 r0 = *(const float2*)&zred[(wm + grp)     * 66 + c];
            float2 r1 = *(const float2*)&zred[(wm + grp + 8) * 66 + c];
            zacc[nb][0] += r0.x; zacc[nb][1] += r0.y;
            zacc[nb][2] += r1.x; zacc[nb][3] += r1.y;
        }
    }

    la += __shfl_xor_sync(0xffffffffu, la, 1);
    la += __shfl_xor_sync(0xffffffffu, la, 2);
    lb += __shfl_xor_sync(0xffffffffu, lb, 1);
    lb += __shfl_xor_sync(0xffffffffu, lb, 2);
    __syncthreads();
    float* red = (float*)(smu + 2 * ATILE) + 64 * 66;
    if (qd == 0) {
        red[(w & 1) * 64 + wm + grp]     = la;
        red[(w & 1) * 64 + wm + grp + 8] = lb;
    }
    __syncthreads();
    if (!(w & 1)) {
        const float lA = red[wm + grp]     + red[64 + wm + grp];
        const float lB = red[wm + grp + 8] + red[64 + wm + grp + 8];
        if (qd == 0) {
            Lsum[h * S_LEN + iA] = lA;
            Lsum[h * S_LEN + iB] = lB;
        }
        const float liA = 1.0f / lA;
        const float liB = 1.0f / lB;
#pragma unroll
        for (int nb = 0; nb < 8; nb++) {
            const int v0 = h * D_HEAD + nb * 8 + 2 * qd;
            Zf2[(size_t)iA * (D_MODEL / 2) + (v0 >> 1)] =
                packh2(zacc[nb][0] * liA, zacc[nb][1] * liA);
            Zf2[(size_t)iB * (D_MODEL / 2) + (v0 >> 1)] =
                packh2(zacc[nb][2] * liB, zacc[nb][3] * liB);
        }
    }
}

// ---- SA upper-triangle zero-fill ----
__global__ __launch_bounds__(256) void sa_zero(float* __restrict__ SA)
{
    const int row   = blockIdx.x;
    const int i     = row & (S_LEN - 1);
    const int start = (((i >> 6) + 1) << 6) >> 2;
    float4* p = (float4*)(SA + (size_t)row * S_LEN);
    const float4 z4 = make_float4(0.f, 0.f, 0.f, 0.f);
    for (int v = start + threadIdx.x; v < S_LEN / 4; v += 256)
        p[v] = z4;
}

// ---- SA rescale: lower tiles only ----
__global__ __launch_bounds__(256) void sa_rescale(
    float* __restrict__ SA, const float* __restrict__ Lsum)
{
    const int row = blockIdx.x;
    const int i   = row & (S_LEN - 1);
    const int end = (((i >> 6) + 1) << 6) >> 2;
    const float linv = 1.0f / Lsum[row];
    float4* p = (float4*)(SA + (size_t)row * S_LEN);
    for (int v = threadIdx.x; v < end; v += 256) {
        float4 x = p[v];
        x.x *= linv; x.y *= linv; x.z *= linv; x.w *= linv;
        p[v] = x;
    }
}

// =================================================================
extern "C" void kernel_launch(void* const* d_in, const int* in_sizes, int n_in,
                              void* d_out, int out_size)
{
    const float* X   = (const float*)d_in[0];
    const float* WQ  = (const float*)d_in[1];
    const float* WK  = (const float*)d_in[2];
    const float* WV  = (const float*)d_in[3];
    const float* WOw = (const float*)d_in[4];
    const float* WOb = (const float*)d_in[5];
    const float* F1w = (const float*)d_in[6];
    const float* F1b = (const float*)d_in[7];
    const float* F2w = (const float*)d_in[8];
    const float* F2b = (const float*)d_in[9];

    float *Ap, *Lp, *Dp;
    uint32_t *Xh2, *Xl2, *WQh2, *WQl2, *WKh2, *WKl2, *Qh2, *Ql2, *Kh2, *Kl2;
    uint32_t *Xf2, *WVf2, *WOf2, *F1f2, *F2f2, *Vf2, *Zf2, *ATTf2, *HIDf2;
    cudaGetSymbolAddress((void**)&Ap, g_ATT);
    cudaGetSymbolAddress((void**)&Lp, g_L);
    cudaGetSymbolAddress((void**)&Dp, g_DUMMY);
    cudaGetSymbolAddress((void**)&Xh2, g_Xh2);
    cudaGetSymbolAddress((void**)&Xl2, g_Xl2);
    cudaGetSymbolAddress((void**)&WQh2, g_WQh2);
    cudaGetSymbolAddress((void**)&WQl2, g_WQl2);
    cudaGetSymbolAddress((void**)&WKh2, g_WKh2);
    cudaGetSymbolAddress((void**)&WKl2, g_WKl2);
    cudaGetSymbolAddress((void**)&Qh2, g_Qh2);
    cudaGetSymbolAddress((void**)&Ql2, g_Ql2);
    cudaGetSymbolAddress((void**)&Kh2, g_Kh2);
    cudaGetSymbolAddress((void**)&Kl2, g_Kl2);
    cudaGetSymbolAddress((void**)&Xf2, g_Xf2);
    cudaGetSymbolAddress((void**)&WVf2, g_WVf2);
    cudaGetSymbolAddress((void**)&WOf2, g_WOf2);
    cudaGetSymbolAddress((void**)&F1f2, g_F1f2);
    cudaGetSymbolAddress((void**)&F2f2, g_F2f2);
    cudaGetSymbolAddress((void**)&Vf2, g_Vf2);
    cudaGetSymbolAddress((void**)&Zf2, g_Zf2);
    cudaGetSymbolAddress((void**)&ATTf2, g_ATTf2);
    cudaGetSymbolAddress((void**)&HIDf2, g_HIDf2);

    const size_t SA_EL = (size_t)N_HEADS * S_LEN * S_LEN;
    const size_t OV_EL = (size_t)S_LEN * D_MODEL;
    float* out = (float*)d_out;
    float* sa;
    float* ov;
    if ((size_t)out_size >= SA_EL + OV_EL)      { sa = out;     ov = out + SA_EL; }
    else if ((size_t)out_size >= SA_EL)         { sa = out;     ov = Dp; }
    else                                        { sa = nullptr; ov = out; }

    const int attn_smem  = ATTN_SMEM_U32 * 4;             // 73728
    const int qk_smem    = 8 * QSTG * 4;                  // 81920
    const int f16_smem   = 3 * (128 * FP + 128 * FP) * 4; // 61440 (MT=128)
    const int f16_smem64 = 3 * (64 * FP + 128 * FP) * 4;  // 46080 (MT=64)
    cudaFuncSetAttribute(attn_tc, cudaFuncAttributeMaxDynamicSharedMemorySize, attn_smem);
    cudaFuncSetAttribute(gemm_qk, cudaFuncAttributeMaxDynamicSharedMemorySize, qk_smem);
    cudaFuncSetAttribute(gemm_f16<128,false,false,false,false,false,true >,
                         cudaFuncAttributeMaxDynamicSharedMemorySize, f16_smem);
    cudaFuncSetAttribute(gemm_f16<64 ,true ,false,true ,true ,true ,false>,
                         cudaFuncAttributeMaxDynamicSharedMemorySize, f16_smem64);
    cudaFuncSetAttribute(gemm_f16<128,true ,true ,false,false,true ,false>,
                         cudaFuncAttributeMaxDynamicSharedMemorySize, f16_smem);
    cudaFuncSetAttribute(gemm_f16<64 ,true ,false,true ,true ,false,false>,
                         cudaFuncAttributeMaxDynamicSharedMemorySize, f16_smem64);

    static cudaStream_t s2 = nullptr;
    static cudaEvent_t evStart = nullptr, evX = nullptr, evV = nullptr,
                       evAttn = nullptr, evSide = nullptr, evPack = nullptr;
    if (!s2) {
        cudaStreamCreateWithFlags(&s2, cudaStreamNonBlocking);
        cudaEventCreateWithFlags(&evStart, cudaEventDisableTiming);
        cudaEventCreateWithFlags(&evX,     cudaEventDisableTiming);
        cudaEventCreateWithFlags(&evV,     cudaEventDisableTiming);
        cudaEventCreateWithFlags(&evAttn,  cudaEventDisableTiming);
        cudaEventCreateWithFlags(&evSide,  cudaEventDisableTiming);
        cudaEventCreateWithFlags(&evPack,  cudaEventDisableTiming);
    }

    dim3 blk(256);

    // ---- fork side stream ----
    cudaEventRecord(evStart, 0);
    cudaStreamWaitEvent(s2, evStart, 0);

    // ---- main: pack X ----
    pack_x<<<dim3(2048), blk>>>(X, Xh2, Xl2, Xf2, S_LEN * D_MODEL / 4);
    cudaEventRecord(evX, 0);

    // ---- side: WV pack -> V-GEMM, then SA zero + late-weight packs ----
    pack_wf_head<<<dim3(2048), blk, 0, s2>>>(WV, WVf2);
    cudaStreamWaitEvent(s2, evX, 0);
    gemm_f16<128,false,false,false,false,false,true ><<<dim3(8, 16), blk, f16_smem, s2>>>(
        Xf2, WVf2, nullptr, nullptr, nullptr, Vf2, S_LEN, D_MODEL, D_MODEL);
    cudaEventRecord(evV, s2);
    if (sa)
        sa_zero<<<dim3(N_HEADS * S_LEN), blk, 0, s2>>>(sa);
    pack_wf_row<<<dim3(2048), blk, 0, s2>>>(WOw, WOf2, D_MODEL * D_MODEL / 2);
    pack_wf_row<<<dim3(8192), blk, 0, s2>>>(F1w, F1f2, D_FF * D_MODEL / 2);
    pack_wf_row<<<dim3(8192), blk, 0, s2>>>(F2w, F2f2, D_MODEL * D_FF / 2);
    cudaEventRecord(evPack, s2);

    // ---- main: merged QK pack + QK projection ----
    pack_w2<<<dim3(2048, 2), blk>>>(WQ, WK, WQh2, WQl2, WKh2, WKl2);
    gemm_qk<<<dim3(8, 16, 2), blk, qk_smem>>>(Xh2, Xl2,
        WQh2, WQl2, WKh2, WKl2, Qh2, Ql2, Kh2, Kl2);

    cudaStreamWaitEvent(0, evV, 0);
    attn_tc<<<dim3(S_LEN / 64, N_HEADS), blk, attn_smem>>>(
        Qh2, Ql2, Kh2, Kl2, Vf2, sa, Zf2, Lp);

    // ---- fork: rescale SA overlapping WO/FF ----
    cudaEventRecord(evAttn, 0);
    if (sa) {
        cudaStreamWaitEvent(s2, evAttn, 0);
        sa_rescale<<<dim3(N_HEADS * S_LEN), blk, 0, s2>>>(sa, Lp);
        cudaEventRecord(evSide, s2);
    }

    cudaStreamWaitEvent(0, evPack, 0);

    // ATT = X + Z @ WO^T + b   (MT=64, grid 256)
    gemm_f16<64 ,true ,false,true ,true ,true ,false><<<dim3(8, 32), blk, f16_smem64>>>(
        Zf2, WOf2, WOb, X, Ap, ATTf2, S_LEN, D_MODEL, D_MODEL);
    // HID = relu(ATT @ FF1^T + b1)   (MT=128, grid 512)
    gemm_f16<128,true ,true ,false,false,true ,false><<<dim3(32, 16), blk, f16_smem>>>(
        ATTf2, F1f2, F1b, nullptr, nullptr, HIDf2, S_LEN, D_FF, D_MODEL);
    // out = ATT + HID @ FF2^T + b2   (MT=64, grid 256)
    gemm_f16<64 ,true ,false,true ,true ,false,false><<<dim3(8, 32), blk, f16_smem64>>>(
        HIDf2, F2f2, F2b, Ap, ov, nullptr, S_LEN, D_MODEL, D_FF);

    if (sa)
        cudaStreamWaitEvent(0, evSide, 0);
}